// round 4
// baseline (speedup 1.0000x reference)
#include <cuda_runtime.h>
#include <cuda_bf16.h>

// ---------------------------------------------------------------------------
// AFNO2D: rfft2(128x128, ortho) -> blockwise complex MLP (8 blocks x 96ch,
// relu, softshrink 0.01) -> irfft2 -> + x.
// K1 rfftW x->A ; K2 fftH A->B (*1/128) ; K3 MLP (bf16 tensor cores) B->A ;
// K4 ifftH A->B ; K5 irfftW B (+x, *1/128) -> out
// ---------------------------------------------------------------------------

#define BB 4
#define HH 128
#define WW 128
#define CH 768
#define NB 8
#define BS 96
#define WF 65
#define MPTS (BB*HH*WF)   /* 33280 frequency points */

__device__ float2 g_A[(size_t)MPTS * CH];
__device__ float2 g_B[(size_t)MPTS * CH];

__device__ __forceinline__ int brev7(int j) { return (int)(__brev((unsigned)j) >> 25); }

// ---------------------------------------------------------------------------
// 128-pt FFT on a thread-private smem row of float2. Input bit-reversed,
// output natural order. Stage 1 radix-2 (tw=1) + 3 fused radix-4 stages.
// tw[k] = (cos(2pi k/128), sin(2pi k/128)); dir=-1 fwd, +1 inv.
// ---------------------------------------------------------------------------
__device__ __forceinline__ void fft128_f2(float2* d, const float2* tw, float dir)
{
    // stage 1: half=1, twiddle = 1
    for (int j0 = 0; j0 < 128; j0 += 2) {
        float2 a = d[j0], b = d[j0 + 1];
        d[j0]     = make_float2(a.x + b.x, a.y + b.y);
        d[j0 + 1] = make_float2(a.x - b.x, a.y - b.y);
    }
    // fused radix-4 stages: h = 2, 8, 32 (covers radix-2 halves (2,4),(8,16),(32,64))
    #pragma unroll
    for (int s = 0; s < 3; s++) {
        const int h  = 2 << (2 * s);
        const int M1 = 64 / h;     // stage-s twiddle step
        const int M2 = 32 / h;     // stage-(s+1) twiddle step
        for (int j = 0; j < h; j++) {
            float2 t1 = tw[j * M1];
            float2 t2 = tw[j * M2];
            float w1r = t1.x, w1i = dir * t1.y;
            float w2r = t2.x, w2i = dir * t2.y;
            float w3r = -t2.y, w3i = dir * t2.x;   // w2 * (dir * i) => W^(jM2+32)
            for (int g4 = j; g4 < 128; g4 += 4 * h) {
                int i0 = g4, i1 = g4 + h, i2 = g4 + 2 * h, i3 = g4 + 3 * h;
                float2 x0 = d[i0], x1 = d[i1], x2 = d[i2], x3 = d[i3];
                float t1r = x1.x * w1r - x1.y * w1i, t1i = x1.x * w1i + x1.y * w1r;
                float t3r = x3.x * w1r - x3.y * w1i, t3i = x3.x * w1i + x3.y * w1r;
                float u0r = x0.x + t1r, u0i = x0.y + t1i;
                float u1r = x0.x - t1r, u1i = x0.y - t1i;
                float u2r = x2.x + t3r, u2i = x2.y + t3i;
                float u3r = x2.x - t3r, u3i = x2.y - t3i;
                float a2r = u2r * w2r - u2i * w2i, a2i = u2r * w2i + u2i * w2r;
                float a3r = u3r * w3r - u3i * w3i, a3i = u3r * w3i + u3i * w3r;
                d[i0] = make_float2(u0r + a2r, u0i + a2i);
                d[i2] = make_float2(u0r - a2r, u0i - a2i);
                d[i1] = make_float2(u1r + a3r, u1i + a3i);
                d[i3] = make_float2(u1r - a3r, u1i - a3i);
            }
        }
    }
}

#define FP2 129   /* float2 pitch per line: 2 lanes 16 apart land on distinct banks */

__device__ __forceinline__ void build_tw(float2* tw, int t)
{
    for (int j = t; j < 64; j += 32) {
        float s, c; sincospif(j * (1.0f / 64.0f), &s, &c);
        tw[j] = make_float2(c, s);
    }
}

// ---------------- K1: rfft along W: x -> g_A[b,h,wf,c] ---------------------
__global__ void k1_rfft_w(const float* __restrict__ x)
{
    __shared__ float2 sd[32 * FP2];
    __shared__ float2 tw[64];
    int t = threadIdx.x;
    build_tw(tw, t);
    int bh = blockIdx.y;
    int c0 = blockIdx.x * 32 + t;
    float2* d = &sd[t * FP2];

    const float* px = x + (size_t)bh * WW * CH + c0;
    for (int w = 0; w < 128; w++) d[brev7(w)] = make_float2(px[(size_t)w * CH], 0.0f);
    __syncthreads();

    fft128_f2(d, tw, -1.0f);

    float2* pa = g_A + (size_t)bh * WF * CH + c0;
    for (int k = 0; k <= 64; k++) pa[(size_t)k * CH] = d[k];
}

// ---------------- K2: fft along H: g_A -> g_B, scale 1/128 -----------------
__global__ void k2_fft_h()
{
    __shared__ float2 sd[32 * FP2];
    __shared__ float2 tw[64];
    int t = threadIdx.x;
    build_tw(tw, t);
    int bwf = blockIdx.y;
    int b = bwf / WF, wf = bwf - b * WF;
    int c0 = blockIdx.x * 32 + t;
    float2* d = &sd[t * FP2];

    const float2* pa = g_A + ((size_t)b * HH * WF + wf) * CH + c0;
    for (int h = 0; h < 128; h++) d[brev7(h)] = pa[(size_t)h * WF * CH];
    __syncthreads();

    fft128_f2(d, tw, -1.0f);

    float2* pb = g_B + ((size_t)b * HH * WF + wf) * CH + c0;
    const float sc = 1.0f / 128.0f;
    for (int h = 0; h < 128; h++)
        pb[(size_t)h * WF * CH] = make_float2(d[h].x * sc, d[h].y * sc);
}

// ---------------------------------------------------------------------------
// K3: blockwise complex MLP on tensor cores (bf16 mma.sync, fp32 accum).
// Per CTA: channel block n, 128 points. X~=[xr|xi] (128x192 bf16), layers as
// 4 sign-combined K=96 GEMMs. 8 warps = 4(M) x 2(N-half: re/im outputs).
// ---------------------------------------------------------------------------
#define XP 200    /* sX pitch in bf16  */
#define WP 104    /* sW pitch in bf16  */
#define SP 200    /* stage pitch fp32  */
#define SM_X   0
#define SM_WR  51200
#define SM_WI  71168
#define SM_B1  102400
#define SM_B2  103168
#define SM_K3  103936

__device__ __forceinline__ void mma_bf16(float* d, const unsigned* a, unsigned b0, unsigned b1)
{
    asm volatile(
        "mma.sync.aligned.m16n8k16.row.col.f32.bf16.bf16.f32 "
        "{%0,%1,%2,%3},{%4,%5,%6,%7},{%8,%9},{%0,%1,%2,%3};"
        : "+f"(d[0]), "+f"(d[1]), "+f"(d[2]), "+f"(d[3])
        : "r"(a[0]), "r"(a[1]), "r"(a[2]), "r"(a[3]), "r"(b0), "r"(b1));
}

__global__ void __launch_bounds__(256) k3_mlp(const float* __restrict__ w1,
                                              const float* __restrict__ b1,
                                              const float* __restrict__ w2,
                                              const float* __restrict__ b2)
{
    extern __shared__ char sm[];
    __nv_bfloat16* sX  = (__nv_bfloat16*)(sm + SM_X);
    __nv_bfloat16* sWr = (__nv_bfloat16*)(sm + SM_WR);
    __nv_bfloat16* sWi = (__nv_bfloat16*)(sm + SM_WI);
    float* stage = (float*)(sm + SM_X);
    float* sB1   = (float*)(sm + SM_B1);
    float* sB2   = (float*)(sm + SM_B2);

    const int tid = threadIdx.x;
    const int n   = blockIdx.x;
    const int m0  = blockIdx.y * 128;
    const int lane = tid & 31, warp = tid >> 5;
    const int g = lane >> 2, tig = lane & 3;
    const int wm = warp & 3, wn = warp >> 2;

    // load X tile: [m][0:96)=re, [96:192)=im
    for (int idx = tid; idx < 128 * 96; idx += 256) {
        int m = idx / 96, i = idx - (idx / 96) * 96;
        float2 v = g_B[(size_t)(m0 + m) * CH + n * BS + i];
        sX[m * XP + i]      = __float2bfloat16_rn(v.x);
        sX[m * XP + 96 + i] = __float2bfloat16_rn(v.y);
    }
    // load W1 (transposed to [o][i]) and biases
    {
        const float* wr = w1 + (size_t)n * BS * BS;
        const float* wi = w1 + (size_t)(NB + n) * BS * BS;
        for (int idx = tid; idx < BS * BS; idx += 256) {
            int i = idx / 96, o = idx - (idx / 96) * 96;
            sWr[o * WP + i] = __float2bfloat16_rn(wr[idx]);
            sWi[o * WP + i] = __float2bfloat16_rn(wi[idx]);
        }
        if (tid < 192) {
            int half = tid / 96, j = tid - half * 96;
            sB1[tid] = b1[half * (NB * BS) + n * BS + j];
            sB2[tid] = b2[half * (NB * BS) + n * BS + j];
        }
    }
    __syncthreads();

    float acc[2][12][4];

    // ======================= layer 1 =======================
    #pragma unroll
    for (int mt = 0; mt < 2; mt++)
        #pragma unroll
        for (int nt = 0; nt < 12; nt++)
            #pragma unroll
            for (int r = 0; r < 4; r++) acc[mt][nt][r] = 0.0f;

    for (int ks = 0; ks < 12; ks++) {
        int khalf = (ks >= 6);
        int k0 = ks * 16, kk = k0 - khalf * 96;
        const __nv_bfloat16* sW = (wn == 0) ? (khalf ? sWi : sWr)
                                            : (khalf ? sWr : sWi);
        bool negA = (wn == 0) && khalf;

        unsigned a[2][4];
        #pragma unroll
        for (int mt = 0; mt < 2; mt++) {
            const __nv_bfloat16* ap = sX + (wm * 32 + mt * 16 + g) * XP + k0 + 2 * tig;
            a[mt][0] = *(const unsigned*)(ap);
            a[mt][1] = *(const unsigned*)(ap + 8 * XP);
            a[mt][2] = *(const unsigned*)(ap + 8);
            a[mt][3] = *(const unsigned*)(ap + 8 * XP + 8);
        }
        if (negA) {
            #pragma unroll
            for (int mt = 0; mt < 2; mt++)
                #pragma unroll
                for (int r = 0; r < 4; r++) a[mt][r] ^= 0x80008000u;
        }
        #pragma unroll
        for (int nt = 0; nt < 12; nt++) {
            const __nv_bfloat16* bp = sW + (nt * 8 + g) * WP + kk + 2 * tig;
            unsigned b0 = *(const unsigned*)(bp);
            unsigned b1v = *(const unsigned*)(bp + 8);
            mma_bf16(acc[0][nt], a[0], b0, b1v);
            mma_bf16(acc[1][nt], a[1], b0, b1v);
        }
    }
    __syncthreads();   // all reads of sX / sW done

    // epilogue L1: +bias, relu, bf16 -> sX (Y1); load W2 into sW
    #pragma unroll
    for (int mt = 0; mt < 2; mt++) {
        #pragma unroll
        for (int nt = 0; nt < 12; nt++) {
            int row0 = wm * 32 + mt * 16 + g;
            int j = wn * 96 + nt * 8 + 2 * tig;
            float bb0 = sB1[j], bb1 = sB1[j + 1];
            __nv_bfloat162 p0 = __floats2bfloat162_rn(
                fmaxf(acc[mt][nt][0] + bb0, 0.0f), fmaxf(acc[mt][nt][1] + bb1, 0.0f));
            __nv_bfloat162 p1 = __floats2bfloat162_rn(
                fmaxf(acc[mt][nt][2] + bb0, 0.0f), fmaxf(acc[mt][nt][3] + bb1, 0.0f));
            *(__nv_bfloat162*)(sX + row0 * XP + j)       = p0;
            *(__nv_bfloat162*)(sX + (row0 + 8) * XP + j) = p1;
        }
    }
    {
        const float* wr = w2 + (size_t)n * BS * BS;
        const float* wi = w2 + (size_t)(NB + n) * BS * BS;
        for (int idx = tid; idx < BS * BS; idx += 256) {
            int i = idx / 96, o = idx - (idx / 96) * 96;
            sWr[o * WP + i] = __float2bfloat16_rn(wr[idx]);
            sWi[o * WP + i] = __float2bfloat16_rn(wi[idx]);
        }
    }
    __syncthreads();

    // ======================= layer 2 =======================
    #pragma unroll
    for (int mt = 0; mt < 2; mt++)
        #pragma unroll
        for (int nt = 0; nt < 12; nt++)
            #pragma unroll
            for (int r = 0; r < 4; r++) acc[mt][nt][r] = 0.0f;

    for (int ks = 0; ks < 12; ks++) {
        int khalf = (ks >= 6);
        int k0 = ks * 16, kk = k0 - khalf * 96;
        const __nv_bfloat16* sW = (wn == 0) ? (khalf ? sWi : sWr)
                                            : (khalf ? sWr : sWi);
        bool negA = (wn == 0) && khalf;

        unsigned a[2][4];
        #pragma unroll
        for (int mt = 0; mt < 2; mt++) {
            const __nv_bfloat16* ap = sX + (wm * 32 + mt * 16 + g) * XP + k0 + 2 * tig;
            a[mt][0] = *(const unsigned*)(ap);
            a[mt][1] = *(const unsigned*)(ap + 8 * XP);
            a[mt][2] = *(const unsigned*)(ap + 8);
            a[mt][3] = *(const unsigned*)(ap + 8 * XP + 8);
        }
        if (negA) {
            #pragma unroll
            for (int mt = 0; mt < 2; mt++)
                #pragma unroll
                for (int r = 0; r < 4; r++) a[mt][r] ^= 0x80008000u;
        }
        #pragma unroll
        for (int nt = 0; nt < 12; nt++) {
            const __nv_bfloat16* bp = sW + (nt * 8 + g) * WP + kk + 2 * tig;
            unsigned b0 = *(const unsigned*)(bp);
            unsigned b1v = *(const unsigned*)(bp + 8);
            mma_bf16(acc[0][nt], a[0], b0, b1v);
            mma_bf16(acc[1][nt], a[1], b0, b1v);
        }
    }
    __syncthreads();   // sX/sW reads done; stage aliases them

    // epilogue L2: +bias -> fp32 stage
    #pragma unroll
    for (int mt = 0; mt < 2; mt++) {
        #pragma unroll
        for (int nt = 0; nt < 12; nt++) {
            int row0 = wm * 32 + mt * 16 + g;
            int j = wn * 96 + nt * 8 + 2 * tig;
            float bb0 = sB2[j], bb1 = sB2[j + 1];
            *(float2*)&stage[row0 * SP + j] =
                make_float2(acc[mt][nt][0] + bb0, acc[mt][nt][1] + bb1);
            *(float2*)&stage[(row0 + 8) * SP + j] =
                make_float2(acc[mt][nt][2] + bb0, acc[mt][nt][3] + bb1);
        }
    }
    __syncthreads();

    // softshrink + interleaved write to g_A
    const float lam = 0.01f;
    for (int idx = tid; idx < 128 * 96; idx += 256) {
        int m = idx / 96, o = idx - (idx / 96) * 96;
        float r  = stage[m * SP + o];
        float ii = stage[m * SP + 96 + o];
        r  = copysignf(fmaxf(fabsf(r)  - lam, 0.0f), r);
        ii = copysignf(fmaxf(fabsf(ii) - lam, 0.0f), ii);
        g_A[(size_t)(m0 + m) * CH + n * BS + o] = make_float2(r, ii);
    }
}

// ---------------- K4: inverse fft along H: g_A -> g_B ----------------------
__global__ void k4_ifft_h()
{
    __shared__ float2 sd[32 * FP2];
    __shared__ float2 tw[64];
    int t = threadIdx.x;
    build_tw(tw, t);
    int bwf = blockIdx.y;
    int b = bwf / WF, wf = bwf - b * WF;
    int c0 = blockIdx.x * 32 + t;
    float2* d = &sd[t * FP2];

    const float2* pa = g_A + ((size_t)b * HH * WF + wf) * CH + c0;
    for (int h = 0; h < 128; h++) d[brev7(h)] = pa[(size_t)h * WF * CH];
    __syncthreads();

    fft128_f2(d, tw, +1.0f);

    float2* pb = g_B + ((size_t)b * HH * WF + wf) * CH + c0;
    for (int h = 0; h < 128; h++) pb[(size_t)h * WF * CH] = d[h];
}

// ---------- K5: inverse rfft along W (+ residual, *1/128): g_B,x -> out ----
__global__ void k5_irfft_w(const float* __restrict__ x, float* __restrict__ out)
{
    __shared__ float2 sd[32 * FP2];
    __shared__ float2 tw[64];
    int t = threadIdx.x;
    build_tw(tw, t);
    int bh = blockIdx.y;
    int c0 = blockIdx.x * 32 + t;
    float2* d = &sd[t * FP2];

    const float2* pb = g_B + (size_t)bh * WF * CH + c0;
    for (int k = 0; k <= 64; k++) {
        float2 v = pb[(size_t)k * CH];
        d[brev7(k)] = v;
        if (k >= 1 && k <= 63)
            d[brev7(128 - k)] = make_float2(v.x, -v.y);   // Hermitian completion
    }
    __syncthreads();

    fft128_f2(d, tw, +1.0f);

    const float* px = x   + (size_t)bh * WW * CH + c0;
    float*       po = out + (size_t)bh * WW * CH + c0;
    const float sc = 1.0f / 128.0f;
    for (int w = 0; w < 128; w++)
        po[(size_t)w * CH] = fmaf(d[w].x, sc, px[(size_t)w * CH]);
}

// ---------------------------------------------------------------------------
extern "C" void kernel_launch(void* const* d_in, const int* in_sizes, int n_in,
                              void* d_out, int out_size)
{
    (void)in_sizes; (void)n_in; (void)out_size;
    const float* x  = (const float*)d_in[0];
    const float* w1 = (const float*)d_in[1];
    const float* b1 = (const float*)d_in[2];
    const float* w2 = (const float*)d_in[3];
    const float* b2 = (const float*)d_in[4];
    float* out = (float*)d_out;

    cudaFuncSetAttribute(k3_mlp, cudaFuncAttributeMaxDynamicSharedMemorySize, SM_K3);

    k1_rfft_w <<<dim3(CH / 32, BB * HH), 32>>>(x);
    k2_fft_h  <<<dim3(CH / 32, BB * WF), 32>>>();
    k3_mlp    <<<dim3(NB, MPTS / 128), 256, SM_K3>>>(w1, b1, w2, b2);
    k4_ifft_h <<<dim3(CH / 32, BB * WF), 32>>>();
    k5_irfft_w<<<dim3(CH / 32, BB * HH), 32>>>(x, out);
}

// round 5
// speedup vs baseline: 1.1153x; 1.1153x over previous
#include <cuda_runtime.h>
#include <cuda_bf16.h>

// ---------------------------------------------------------------------------
// AFNO2D: rfft2(128x128, ortho) -> blockwise complex MLP (8 blocks x 96ch,
// relu, softshrink 0.01) -> irfft2 -> + x.
// K1 rfftW x -> g_A (bf16x2)
// KMID (per b,wf,n): H-DFT (bf16 GEMM) -> MLP (bf16 GEMM) -> inv H-DFT (GEMM)
//      g_A -> g_B, all intermediate data stays in SMEM
// K5 irfftW g_B (+x, *1/128) -> out
// ---------------------------------------------------------------------------

#define BB 4
#define HH 128
#define WW 128
#define CH 768
#define NB 8
#define BS 96
#define WF 65
#define MPTS (BB*HH*WF)   /* 33280 frequency points */

__device__ __nv_bfloat162 g_A2[(size_t)MPTS * CH];
__device__ __nv_bfloat162 g_B2[(size_t)MPTS * CH];
__device__ __nv_bfloat16  g_G[128 * 256];   // [h'][k]: k<128 -> cos, k>=128 -> sin

__device__ __forceinline__ int brev7(int j) { return (int)(__brev((unsigned)j) >> 25); }

// ---------------- K0: build DFT matrix G = [C | S] -------------------------
__global__ void k0_build_G()
{
    int tid = threadIdx.x;
    for (int idx = tid; idx < 128 * 256; idx += 256) {
        int hp = idx >> 8, k = idx & 255, kk = k & 127;
        int m = (hp * kk) & 127;
        float s, c; sincospif(m * (1.0f / 64.0f), &s, &c);
        g_G[idx] = __float2bfloat16_rn((k < 128) ? c : s);
    }
}

// ---------------------------------------------------------------------------
// 128-pt FFT on a thread-private smem row of float2 (radix-2 + fused radix-4)
// ---------------------------------------------------------------------------
__device__ __forceinline__ void fft128_f2(float2* d, const float2* tw, float dir)
{
    for (int j0 = 0; j0 < 128; j0 += 2) {
        float2 a = d[j0], b = d[j0 + 1];
        d[j0]     = make_float2(a.x + b.x, a.y + b.y);
        d[j0 + 1] = make_float2(a.x - b.x, a.y - b.y);
    }
    #pragma unroll
    for (int s = 0; s < 3; s++) {
        const int h  = 2 << (2 * s);
        const int M1 = 64 / h;
        const int M2 = 32 / h;
        for (int j = 0; j < h; j++) {
            float2 t1 = tw[j * M1];
            float2 t2 = tw[j * M2];
            float w1r = t1.x, w1i = dir * t1.y;
            float w2r = t2.x, w2i = dir * t2.y;
            float w3r = -t2.y, w3i = dir * t2.x;
            for (int g4 = j; g4 < 128; g4 += 4 * h) {
                int i0 = g4, i1 = g4 + h, i2 = g4 + 2 * h, i3 = g4 + 3 * h;
                float2 x0 = d[i0], x1 = d[i1], x2 = d[i2], x3 = d[i3];
                float t1r = x1.x * w1r - x1.y * w1i, t1i = x1.x * w1i + x1.y * w1r;
                float t3r = x3.x * w1r - x3.y * w1i, t3i = x3.x * w1i + x3.y * w1r;
                float u0r = x0.x + t1r, u0i = x0.y + t1i;
                float u1r = x0.x - t1r, u1i = x0.y - t1i;
                float u2r = x2.x + t3r, u2i = x2.y + t3i;
                float u3r = x2.x - t3r, u3i = x2.y - t3i;
                float a2r = u2r * w2r - u2i * w2i, a2i = u2r * w2i + u2i * w2r;
                float a3r = u3r * w3r - u3i * w3i, a3i = u3r * w3i + u3i * w3r;
                d[i0] = make_float2(u0r + a2r, u0i + a2i);
                d[i2] = make_float2(u0r - a2r, u0i - a2i);
                d[i1] = make_float2(u1r + a3r, u1i + a3i);
                d[i3] = make_float2(u1r - a3r, u1i - a3i);
            }
        }
    }
}

#define FP2 129

__device__ __forceinline__ void build_tw(float2* tw, int t)
{
    for (int j = t; j < 64; j += 32) {
        float s, c; sincospif(j * (1.0f / 64.0f), &s, &c);
        tw[j] = make_float2(c, s);
    }
}

// ---------------- K1: rfft along W: x -> g_A2[b,h,wf,c] (bf16x2) -----------
__global__ void k1_rfft_w(const float* __restrict__ x)
{
    __shared__ float2 sd[32 * FP2];
    __shared__ float2 tw[64];
    int t = threadIdx.x;
    build_tw(tw, t);
    int bh = blockIdx.y;
    int c0 = blockIdx.x * 32 + t;
    float2* d = &sd[t * FP2];

    const float* px = x + (size_t)bh * WW * CH + c0;
    for (int w = 0; w < 128; w++) d[brev7(w)] = make_float2(px[(size_t)w * CH], 0.0f);
    __syncthreads();

    fft128_f2(d, tw, -1.0f);

    __nv_bfloat162* pa = g_A2 + (size_t)bh * WF * CH + c0;
    for (int k = 0; k <= 64; k++)
        pa[(size_t)k * CH] = __floats2bfloat162_rn(d[k].x, d[k].y);
}

// ---------------------------------------------------------------------------
// KMID: per-(b,wf,n) fused H-DFT -> complex MLP -> inverse H-DFT.
// 8 warps: wm=warp&3 = 32-row M slab, wn=warp>>2 = re/im half.
// ---------------------------------------------------------------------------
#define GP  264   /* sG pitch (bf16) : 132 words == 4 mod 32 -> frag loads cf */
#define XT  264   /* sX / sOt pitch  */
#define XP  200   /* sXm pitch       */
#define WP  104   /* sW pitch        */
#define SM_G   0          /* 128*264*2 = 67584 */
#define SM_X   67584      /* max(96*264*2, 128*200*2) = 51200 */
#define SM_W   118784     /* 96*104*2 = 19968 */
#define SM_WI  138752     /* 19968 */
#define SM_B1  158720
#define SM_B2  159488
#define SM_TOT 160256

__device__ __forceinline__ void mma_bf16(float* d, const unsigned* a, unsigned b0, unsigned b1)
{
    asm volatile(
        "mma.sync.aligned.m16n8k16.row.col.f32.bf16.bf16.f32 "
        "{%0,%1,%2,%3},{%4,%5,%6,%7},{%8,%9},{%0,%1,%2,%3};"
        : "+f"(d[0]), "+f"(d[1]), "+f"(d[2]), "+f"(d[3])
        : "r"(a[0]), "r"(a[1]), "r"(a[2]), "r"(a[3]), "r"(b0), "r"(b1));
}

__global__ void __launch_bounds__(256) kmid(const float* __restrict__ w1,
                                            const float* __restrict__ b1,
                                            const float* __restrict__ w2,
                                            const float* __restrict__ b2)
{
    extern __shared__ char sm[];
    __nv_bfloat16* sG  = (__nv_bfloat16*)(sm + SM_G);
    __nv_bfloat16* sX  = (__nv_bfloat16*)(sm + SM_X);   // [c][256]  (DFT in)
    __nv_bfloat16* sXm = (__nv_bfloat16*)(sm + SM_X);   // [h'][192] (MLP)
    __nv_bfloat16* sOt = (__nv_bfloat16*)(sm + SM_X);   // [c][256]  (DFT out in)
    __nv_bfloat16* sWr = (__nv_bfloat16*)(sm + SM_W);
    __nv_bfloat16* sWi = (__nv_bfloat16*)(sm + SM_WI);
    __nv_bfloat16* stg = (__nv_bfloat16*)(sm + SM_G);   // final stage aliases sG
    float* sB1 = (float*)(sm + SM_B1);
    float* sB2 = (float*)(sm + SM_B2);

    const int tid = threadIdx.x;
    const int n   = blockIdx.x;
    const int b   = blockIdx.y / WF;
    const int wf  = blockIdx.y - b * WF;
    const int lane = tid & 31, warp = tid >> 5;
    const int g = lane >> 2, tig = lane & 3;
    const int wm = warp & 3, wn = warp >> 2;

    // ---- load G (pitched), W1, biases; ingest X (scaled 1/128, transposed)
    {
        const __nv_bfloat162* src = (const __nv_bfloat162*)g_G;
        for (int p = tid; p < 128 * 128; p += 256) {
            int hp = p >> 7, kp = p & 127;
            *(__nv_bfloat162*)(sG + hp * GP + 2 * kp) = src[p];
        }
    }
    {
        const float* wr = w1 + (size_t)n * BS * BS;
        const float* wi = w1 + (size_t)(NB + n) * BS * BS;
        for (int idx = tid; idx < BS * BS; idx += 256) {
            int i = idx / 96, o = idx - (idx / 96) * 96;
            sWr[o * WP + i] = __float2bfloat16_rn(wr[idx]);
            sWi[o * WP + i] = __float2bfloat16_rn(wi[idx]);
        }
        if (tid < 192) {
            int half = tid / 96, j = tid - half * 96;
            sB1[tid] = b1[half * (NB * BS) + n * BS + j];
            sB2[tid] = b2[half * (NB * BS) + n * BS + j];
        }
    }
    {
        const __nv_bfloat162* pa = g_A2 + ((size_t)(b * HH) * WF + wf) * CH + n * BS;
        const __nv_bfloat162 c128 = __float2bfloat162_rn(0.0078125f);  // exact
        for (int idx = tid; idx < HH * BS; idx += 256) {
            int h = idx / BS, c = idx - (idx / BS) * BS;
            __nv_bfloat162 v = __hmul2(pa[(size_t)h * WF * CH + c], c128);
            sX[c * XT + h]       = __low2bfloat16(v);
            sX[c * XT + 128 + h] = __high2bfloat16(v);
        }
    }
    __syncthreads();

    float acc[2][12][4];

    // =============== GEMM1: forward H-DFT: Y = G * [Xr;Xi] =================
    // wn=0: Yr = [C|S].[Xr;Xi] ; wn=1: Yi = [C|S].[Xi;-Xr]
    #pragma unroll
    for (int mt = 0; mt < 2; mt++)
        #pragma unroll
        for (int nt = 0; nt < 12; nt++)
            #pragma unroll
            for (int r = 0; r < 4; r++) acc[mt][nt][r] = 0.0f;

    for (int ks = 0; ks < 16; ks++) {
        const int k0 = ks * 16;
        unsigned a[2][4];
        #pragma unroll
        for (int mt = 0; mt < 2; mt++) {
            const __nv_bfloat16* ap = sG + (wm * 32 + mt * 16 + g) * GP + k0 + 2 * tig;
            a[mt][0] = *(const unsigned*)(ap);
            a[mt][1] = *(const unsigned*)(ap + 8 * GP);
            a[mt][2] = *(const unsigned*)(ap + 8);
            a[mt][3] = *(const unsigned*)(ap + 8 * GP + 8);
        }
        const int kk = wn ? (k0 ^ 128) : k0;
        const unsigned msk = (wn && k0 >= 128) ? 0x80008000u : 0u;
        #pragma unroll
        for (int nt = 0; nt < 12; nt++) {
            const __nv_bfloat16* bp = sX + (nt * 8 + g) * XT + kk + 2 * tig;
            unsigned b0 = *(const unsigned*)(bp) ^ msk;
            unsigned b1v = *(const unsigned*)(bp + 8) ^ msk;
            mma_bf16(acc[0][nt], a[0], b0, b1v);
            mma_bf16(acc[1][nt], a[1], b0, b1v);
        }
    }
    __syncthreads();

    // epilogue: Y -> sXm [h'][wn*96 + c] bf16
    #pragma unroll
    for (int mt = 0; mt < 2; mt++)
        #pragma unroll
        for (int nt = 0; nt < 12; nt++) {
            int row0 = wm * 32 + mt * 16 + g;
            int jj = wn * 96 + nt * 8 + 2 * tig;
            *(__nv_bfloat162*)(sXm + row0 * XP + jj) =
                __floats2bfloat162_rn(acc[mt][nt][0], acc[mt][nt][1]);
            *(__nv_bfloat162*)(sXm + (row0 + 8) * XP + jj) =
                __floats2bfloat162_rn(acc[mt][nt][2], acc[mt][nt][3]);
        }
    __syncthreads();

    // =============== MLP layer 1 ===========================================
    #pragma unroll
    for (int mt = 0; mt < 2; mt++)
        #pragma unroll
        for (int nt = 0; nt < 12; nt++)
            #pragma unroll
            for (int r = 0; r < 4; r++) acc[mt][nt][r] = 0.0f;

    for (int ks = 0; ks < 12; ks++) {
        const int khalf = (ks >= 6);
        const int k0 = ks * 16, kkm = k0 - khalf * 96;
        const __nv_bfloat16* sW = (wn == 0) ? (khalf ? sWi : sWr)
                                            : (khalf ? sWr : sWi);
        const bool negA = (wn == 0) && khalf;
        unsigned a[2][4];
        #pragma unroll
        for (int mt = 0; mt < 2; mt++) {
            const __nv_bfloat16* ap = sXm + (wm * 32 + mt * 16 + g) * XP + k0 + 2 * tig;
            a[mt][0] = *(const unsigned*)(ap);
            a[mt][1] = *(const unsigned*)(ap + 8 * XP);
            a[mt][2] = *(const unsigned*)(ap + 8);
            a[mt][3] = *(const unsigned*)(ap + 8 * XP + 8);
        }
        if (negA) {
            #pragma unroll
            for (int mt = 0; mt < 2; mt++)
                #pragma unroll
                for (int r = 0; r < 4; r++) a[mt][r] ^= 0x80008000u;
        }
        #pragma unroll
        for (int nt = 0; nt < 12; nt++) {
            const __nv_bfloat16* bp = sW + (nt * 8 + g) * WP + kkm + 2 * tig;
            unsigned b0 = *(const unsigned*)(bp);
            unsigned b1v = *(const unsigned*)(bp + 8);
            mma_bf16(acc[0][nt], a[0], b0, b1v);
            mma_bf16(acc[1][nt], a[1], b0, b1v);
        }
    }
    __syncthreads();

    // epilogue: relu(acc + b1) -> sXm ; reload W2
    #pragma unroll
    for (int mt = 0; mt < 2; mt++)
        #pragma unroll
        for (int nt = 0; nt < 12; nt++) {
            int row0 = wm * 32 + mt * 16 + g;
            int jj = wn * 96 + nt * 8 + 2 * tig;
            float bb0 = sB1[jj], bb1 = sB1[jj + 1];
            *(__nv_bfloat162*)(sXm + row0 * XP + jj) = __floats2bfloat162_rn(
                fmaxf(acc[mt][nt][0] + bb0, 0.0f), fmaxf(acc[mt][nt][1] + bb1, 0.0f));
            *(__nv_bfloat162*)(sXm + (row0 + 8) * XP + jj) = __floats2bfloat162_rn(
                fmaxf(acc[mt][nt][2] + bb0, 0.0f), fmaxf(acc[mt][nt][3] + bb1, 0.0f));
        }
    {
        const float* wr = w2 + (size_t)n * BS * BS;
        const float* wi = w2 + (size_t)(NB + n) * BS * BS;
        for (int idx = tid; idx < BS * BS; idx += 256) {
            int i = idx / 96, o = idx - (idx / 96) * 96;
            sWr[o * WP + i] = __float2bfloat16_rn(wr[idx]);
            sWi[o * WP + i] = __float2bfloat16_rn(wi[idx]);
        }
    }
    __syncthreads();

    // =============== MLP layer 2 ===========================================
    #pragma unroll
    for (int mt = 0; mt < 2; mt++)
        #pragma unroll
        for (int nt = 0; nt < 12; nt++)
            #pragma unroll
            for (int r = 0; r < 4; r++) acc[mt][nt][r] = 0.0f;

    for (int ks = 0; ks < 12; ks++) {
        const int khalf = (ks >= 6);
        const int k0 = ks * 16, kkm = k0 - khalf * 96;
        const __nv_bfloat16* sW = (wn == 0) ? (khalf ? sWi : sWr)
                                            : (khalf ? sWr : sWi);
        const bool negA = (wn == 0) && khalf;
        unsigned a[2][4];
        #pragma unroll
        for (int mt = 0; mt < 2; mt++) {
            const __nv_bfloat16* ap = sXm + (wm * 32 + mt * 16 + g) * XP + k0 + 2 * tig;
            a[mt][0] = *(const unsigned*)(ap);
            a[mt][1] = *(const unsigned*)(ap + 8 * XP);
            a[mt][2] = *(const unsigned*)(ap + 8);
            a[mt][3] = *(const unsigned*)(ap + 8 * XP + 8);
        }
        if (negA) {
            #pragma unroll
            for (int mt = 0; mt < 2; mt++)
                #pragma unroll
                for (int r = 0; r < 4; r++) a[mt][r] ^= 0x80008000u;
        }
        #pragma unroll
        for (int nt = 0; nt < 12; nt++) {
            const __nv_bfloat16* bp = sW + (nt * 8 + g) * WP + kkm + 2 * tig;
            unsigned b0 = *(const unsigned*)(bp);
            unsigned b1v = *(const unsigned*)(bp + 8);
            mma_bf16(acc[0][nt], a[0], b0, b1v);
            mma_bf16(acc[1][nt], a[1], b0, b1v);
        }
    }
    __syncthreads();

    // epilogue: softshrink(acc + b2) -> sOt [c][h'-stack] (transposed)
    {
        const float lam = 0.01f;
        #pragma unroll
        for (int mt = 0; mt < 2; mt++)
            #pragma unroll
            for (int nt = 0; nt < 12; nt++) {
                int row0 = wm * 32 + mt * 16 + g;
                int jj = wn * 96 + nt * 8 + 2 * tig;
                int c = jj - wn * 96;
                float bb0 = sB2[jj], bb1 = sB2[jj + 1];
                #pragma unroll
                for (int r = 0; r < 4; r++) {
                    float v = acc[mt][nt][r] + ((r & 1) ? bb1 : bb0);
                    v = copysignf(fmaxf(fabsf(v) - lam, 0.0f), v);
                    int cc = c + (r & 1);
                    int kb = wn * 128 + row0 + (r >> 1) * 8;
                    sOt[cc * XT + kb] = __float2bfloat16_rn(v);
                }
            }
    }
    __syncthreads();

    // =============== GEMM2: inverse H-DFT: Z = Ginv * [Or;Oi] ==============
    // wn=0: Zr = [C|S].[Or;-Oi] ; wn=1: Zi = [C|S].[Oi;Or]
    #pragma unroll
    for (int mt = 0; mt < 2; mt++)
        #pragma unroll
        for (int nt = 0; nt < 12; nt++)
            #pragma unroll
            for (int r = 0; r < 4; r++) acc[mt][nt][r] = 0.0f;

    for (int ks = 0; ks < 16; ks++) {
        const int k0 = ks * 16;
        unsigned a[2][4];
        #pragma unroll
        for (int mt = 0; mt < 2; mt++) {
            const __nv_bfloat16* ap = sG + (wm * 32 + mt * 16 + g) * GP + k0 + 2 * tig;
            a[mt][0] = *(const unsigned*)(ap);
            a[mt][1] = *(const unsigned*)(ap + 8 * GP);
            a[mt][2] = *(const unsigned*)(ap + 8);
            a[mt][3] = *(const unsigned*)(ap + 8 * GP + 8);
        }
        const int kk = wn ? (k0 ^ 128) : k0;
        const unsigned msk = (!wn && k0 >= 128) ? 0x80008000u : 0u;
        #pragma unroll
        for (int nt = 0; nt < 12; nt++) {
            const __nv_bfloat16* bp = sOt + (nt * 8 + g) * XT + kk + 2 * tig;
            unsigned b0 = *(const unsigned*)(bp) ^ msk;
            unsigned b1v = *(const unsigned*)(bp + 8) ^ msk;
            mma_bf16(acc[0][nt], a[0], b0, b1v);
            mma_bf16(acc[1][nt], a[1], b0, b1v);
        }
    }
    __syncthreads();    // all sG reads done -> stg may alias it

    // stage Z -> stg [h][wn*96+c] then coalesced interleaved write to g_B2
    #pragma unroll
    for (int mt = 0; mt < 2; mt++)
        #pragma unroll
        for (int nt = 0; nt < 12; nt++) {
            int row0 = wm * 32 + mt * 16 + g;
            int jj = wn * 96 + nt * 8 + 2 * tig;
            *(__nv_bfloat162*)(stg + row0 * XP + jj) =
                __floats2bfloat162_rn(acc[mt][nt][0], acc[mt][nt][1]);
            *(__nv_bfloat162*)(stg + (row0 + 8) * XP + jj) =
                __floats2bfloat162_rn(acc[mt][nt][2], acc[mt][nt][3]);
        }
    __syncthreads();

    {
        __nv_bfloat162* pb = g_B2 + ((size_t)(b * HH) * WF + wf) * CH + n * BS;
        for (int idx = tid; idx < HH * BS; idx += 256) {
            int h = idx / BS, c = idx - (idx / BS) * BS;
            pb[(size_t)h * WF * CH + c] =
                __halves2bfloat162(stg[h * XP + c], stg[h * XP + 96 + c]);
        }
    }
}

// ---------- K5: inverse rfft along W (+ residual, *1/128): g_B2,x -> out ---
__global__ void k5_irfft_w(const float* __restrict__ x, float* __restrict__ out)
{
    __shared__ float2 sd[32 * FP2];
    __shared__ float2 tw[64];
    int t = threadIdx.x;
    build_tw(tw, t);
    int bh = blockIdx.y;
    int c0 = blockIdx.x * 32 + t;
    float2* d = &sd[t * FP2];

    const __nv_bfloat162* pb = g_B2 + (size_t)bh * WF * CH + c0;
    for (int k = 0; k <= 64; k++) {
        float2 v = __bfloat1622float2(pb[(size_t)k * CH]);
        d[brev7(k)] = v;
        if (k >= 1 && k <= 63)
            d[brev7(128 - k)] = make_float2(v.x, -v.y);
    }
    __syncthreads();

    fft128_f2(d, tw, +1.0f);

    const float* px = x   + (size_t)bh * WW * CH + c0;
    float*       po = out + (size_t)bh * WW * CH + c0;
    const float sc = 1.0f / 128.0f;
    for (int w = 0; w < 128; w++)
        po[(size_t)w * CH] = fmaf(d[w].x, sc, px[(size_t)w * CH]);
}

// ---------------------------------------------------------------------------
extern "C" void kernel_launch(void* const* d_in, const int* in_sizes, int n_in,
                              void* d_out, int out_size)
{
    (void)in_sizes; (void)n_in; (void)out_size;
    const float* x  = (const float*)d_in[0];
    const float* w1 = (const float*)d_in[1];
    const float* b1 = (const float*)d_in[2];
    const float* w2 = (const float*)d_in[3];
    const float* b2 = (const float*)d_in[4];
    float* out = (float*)d_out;

    cudaFuncSetAttribute(kmid, cudaFuncAttributeMaxDynamicSharedMemorySize, SM_TOT);

    k0_build_G<<<1, 256>>>();
    k1_rfft_w <<<dim3(CH / 32, BB * HH), 32>>>(x);
    kmid      <<<dim3(NB, BB * WF), 256, SM_TOT>>>(w1, b1, w2, b2);
    k5_irfft_w<<<dim3(CH / 32, BB * HH), 32>>>(x, out);
}

// round 6
// speedup vs baseline: 1.3704x; 1.2287x over previous
#include <cuda_runtime.h>
#include <cuda_bf16.h>

// ---------------------------------------------------------------------------
// AFNO2D: rfft2(128x128, ortho) -> blockwise complex MLP (8 blocks x 96ch,
// relu, softshrink 0.01) -> irfft2 -> + x.   All three stages are tensor-core
// GEMMs now:
//   K1  W-rfft as GEMM:  Y = G1 . x          -> g_A2 (bf16x2)
//   KMID per (b,wf,n):   H-DFT -> MLP -> inv H-DFT (all in SMEM)  g_A2 -> g_B2
//   K5  W-irfft as GEMM: out = G5 . [Zr;Zi] + x
// ---------------------------------------------------------------------------

#define BB 4
#define HH 128
#define WW 128
#define CH 768
#define NB 8
#define BS 96
#define WF 65
#define MPTS (BB*HH*WF)

__device__ __nv_bfloat162 g_A2[(size_t)MPTS * CH];
__device__ __nv_bfloat162 g_B2[(size_t)MPTS * CH];
__device__ __nv_bfloat16  g_G [128 * 256];   // kmid H-DFT  [h'][k<128:cos | k>=128:sin]
__device__ __nv_bfloat16  g_G1[128 * 128];   // k1: rows 0..64 = cos(2pi m w/128), rows 65..127 = -sin(2pi (m-64) w/128)
__device__ __nv_bfloat16  g_G5[128 * 146];   // k5: [w][k<65: eps*cos/128 | 72..136: -eps*sin/128 | else 0]

// ---------------- K0: build DFT matrices -----------------------------------
__global__ void k0_build()
{
    int tid = threadIdx.x;
    for (int idx = tid; idx < 128 * 256; idx += 256) {
        int hp = idx >> 8, k = idx & 255, kk = k & 127;
        int m = (hp * kk) & 127;
        float s, c; sincospif(m * (1.0f / 64.0f), &s, &c);
        g_G[idx] = __float2bfloat16_rn((k < 128) ? c : s);
    }
    for (int idx = tid; idx < 128 * 128; idx += 256) {
        int m = idx >> 7, w = idx & 127;
        float val;
        if (m < 65) {
            int a = (m * w) & 127;
            float s, c; sincospif(a * (1.0f / 64.0f), &s, &c);
            val = c;
        } else {
            int a = ((m - 64) * w) & 127;
            float s, c; sincospif(a * (1.0f / 64.0f), &s, &c);
            val = -s;
        }
        g_G1[idx] = __float2bfloat16_rn(val);
    }
    for (int idx = tid; idx < 128 * 146; idx += 256) {
        int w = idx / 146, k = idx - (idx / 146) * 146;
        float val = 0.0f;
        if (k < 65) {
            float eps = (k == 0 || k == 64) ? 1.0f : 2.0f;
            int a = (w * k) & 127;
            float s, c; sincospif(a * (1.0f / 64.0f), &s, &c);
            val = eps * c * (1.0f / 128.0f);
        } else if (k >= 72 && k < 137) {
            int kk = k - 72;
            float eps = (kk == 0 || kk == 64) ? 1.0f : 2.0f;
            int a = (w * kk) & 127;
            float s, c; sincospif(a * (1.0f / 64.0f), &s, &c);
            val = -eps * s * (1.0f / 128.0f);
        }
        g_G5[idx] = __float2bfloat16_rn(val);
    }
}

__device__ __forceinline__ void mma_bf16(float* d, const unsigned* a, unsigned b0, unsigned b1)
{
    asm volatile(
        "mma.sync.aligned.m16n8k16.row.col.f32.bf16.bf16.f32 "
        "{%0,%1,%2,%3},{%4,%5,%6,%7},{%8,%9},{%0,%1,%2,%3};"
        : "+f"(d[0]), "+f"(d[1]), "+f"(d[2]), "+f"(d[3])
        : "r"(a[0]), "r"(a[1]), "r"(a[2]), "r"(a[3]), "r"(b0), "r"(b1));
}

// ---------------------------------------------------------------------------
// K1: W-rfft as GEMM. Per CTA: one bh row, one 96-channel tile.
//   Y(128 x 96) = G1(128 x 128) * x^T(128 x 96)  ->  g_A2[bh][k][c] bf16x2
// ---------------------------------------------------------------------------
#define P1 130                 /* bf16 pitch: 65 words -> conflict-free */
#define K1_SG 0                /* 128*130*2 = 33280 */
#define K1_SB 33280            /* 96*130*2  = 24960 */
#define K1_TOT 58240
#define STG_P 98

__global__ void __launch_bounds__(256) k1g(const float* __restrict__ x)
{
    extern __shared__ char sm[];
    __nv_bfloat16* sG = (__nv_bfloat16*)(sm + K1_SG);
    __nv_bfloat16* sB = (__nv_bfloat16*)(sm + K1_SB);
    __nv_bfloat16* stg = (__nv_bfloat16*)(sm + K1_SG);   // aliases sG after GEMM

    const int tid = threadIdx.x;
    const int bh = blockIdx.y;
    const int c0 = blockIdx.x * 96;
    const int lane = tid & 31, warp = tid >> 5;
    const int g = lane >> 2, tig = lane & 3;
    const int wm = warp & 3, wn = warp >> 2;

    // load G1 (pitched)
    {
        const unsigned* src = (const unsigned*)g_G1;
        unsigned* dst = (unsigned*)sG;
        for (int p = tid; p < 128 * 64; p += 256) {
            int row = p >> 6, kp = p & 63;
            dst[row * 65 + kp] = src[p];
        }
    }
    // ingest x transposed: sB[c][w]
    {
        const float* px = x + (size_t)bh * WW * CH + c0;
        for (int idx = tid; idx < 128 * 96; idx += 256) {
            int w = idx / 96, c = idx - (idx / 96) * 96;
            sB[c * P1 + w] = __float2bfloat16_rn(px[(size_t)w * CH + c]);
        }
    }
    __syncthreads();

    float acc[2][6][4];
    #pragma unroll
    for (int mt = 0; mt < 2; mt++)
        #pragma unroll
        for (int nt = 0; nt < 6; nt++)
            #pragma unroll
            for (int r = 0; r < 4; r++) acc[mt][nt][r] = 0.0f;

    for (int ks = 0; ks < 8; ks++) {
        const int k0 = ks * 16;
        unsigned a[2][4];
        #pragma unroll
        for (int mt = 0; mt < 2; mt++) {
            const __nv_bfloat16* ap = sG + (wm * 32 + mt * 16 + g) * P1 + k0 + 2 * tig;
            a[mt][0] = *(const unsigned*)(ap);
            a[mt][1] = *(const unsigned*)(ap + 8 * P1);
            a[mt][2] = *(const unsigned*)(ap + 8);
            a[mt][3] = *(const unsigned*)(ap + 8 * P1 + 8);
        }
        #pragma unroll
        for (int nt = 0; nt < 6; nt++) {
            const __nv_bfloat16* bp = sB + (wn * 48 + nt * 8 + g) * P1 + k0 + 2 * tig;
            unsigned b0 = *(const unsigned*)(bp);
            unsigned b1v = *(const unsigned*)(bp + 8);
            mma_bf16(acc[0][nt], a[0], b0, b1v);
            mma_bf16(acc[1][nt], a[1], b0, b1v);
        }
    }
    __syncthreads();

    // stage [row 0..127][c 0..95] bf16
    #pragma unroll
    for (int mt = 0; mt < 2; mt++)
        #pragma unroll
        for (int nt = 0; nt < 6; nt++) {
            int row0 = wm * 32 + mt * 16 + g;
            int jj = wn * 48 + nt * 8 + 2 * tig;
            *(__nv_bfloat162*)(stg + row0 * STG_P + jj) =
                __floats2bfloat162_rn(acc[mt][nt][0], acc[mt][nt][1]);
            *(__nv_bfloat162*)(stg + (row0 + 8) * STG_P + jj) =
                __floats2bfloat162_rn(acc[mt][nt][2], acc[mt][nt][3]);
        }
    __syncthreads();

    // pack (Yr, Yi) -> g_A2 ; Yi[0] = Yi[64] = 0
    {
        __nv_bfloat162* pa = g_A2 + (size_t)bh * WF * CH + c0;
        const __nv_bfloat16 z = __float2bfloat16_rn(0.0f);
        for (int idx = tid; idx < 65 * 96; idx += 256) {
            int k = idx / 96, c = idx - (idx / 96) * 96;
            __nv_bfloat16 re = stg[k * STG_P + c];
            __nv_bfloat16 im = (k >= 1 && k <= 63) ? stg[(64 + k) * STG_P + c] : z;
            pa[(size_t)k * CH + c] = __halves2bfloat162(re, im);
        }
    }
}

// ---------------------------------------------------------------------------
// KMID: per-(b,wf,n) fused H-DFT -> complex MLP -> inverse H-DFT. (unchanged)
// ---------------------------------------------------------------------------
#define GP  264
#define XT  264
#define XP  200
#define WP  104
#define SM_G   0
#define SM_X   67584
#define SM_W   118784
#define SM_WI  138752
#define SM_B1  158720
#define SM_B2  159488
#define SM_TOT 160256

__global__ void __launch_bounds__(256) kmid(const float* __restrict__ w1,
                                            const float* __restrict__ b1,
                                            const float* __restrict__ w2,
                                            const float* __restrict__ b2)
{
    extern __shared__ char sm[];
    __nv_bfloat16* sG  = (__nv_bfloat16*)(sm + SM_G);
    __nv_bfloat16* sX  = (__nv_bfloat16*)(sm + SM_X);
    __nv_bfloat16* sXm = (__nv_bfloat16*)(sm + SM_X);
    __nv_bfloat16* sOt = (__nv_bfloat16*)(sm + SM_X);
    __nv_bfloat16* sWr = (__nv_bfloat16*)(sm + SM_W);
    __nv_bfloat16* sWi = (__nv_bfloat16*)(sm + SM_WI);
    __nv_bfloat16* stg = (__nv_bfloat16*)(sm + SM_G);
    float* sB1 = (float*)(sm + SM_B1);
    float* sB2 = (float*)(sm + SM_B2);

    const int tid = threadIdx.x;
    const int n   = blockIdx.x;
    const int b   = blockIdx.y / WF;
    const int wf  = blockIdx.y - b * WF;
    const int lane = tid & 31, warp = tid >> 5;
    const int g = lane >> 2, tig = lane & 3;
    const int wm = warp & 3, wn = warp >> 2;

    {
        const __nv_bfloat162* src = (const __nv_bfloat162*)g_G;
        for (int p = tid; p < 128 * 128; p += 256) {
            int hp = p >> 7, kp = p & 127;
            *(__nv_bfloat162*)(sG + hp * GP + 2 * kp) = src[p];
        }
    }
    {
        const float* wr = w1 + (size_t)n * BS * BS;
        const float* wi = w1 + (size_t)(NB + n) * BS * BS;
        for (int idx = tid; idx < BS * BS; idx += 256) {
            int i = idx / 96, o = idx - (idx / 96) * 96;
            sWr[o * WP + i] = __float2bfloat16_rn(wr[idx]);
            sWi[o * WP + i] = __float2bfloat16_rn(wi[idx]);
        }
        if (tid < 192) {
            int half = tid / 96, j = tid - half * 96;
            sB1[tid] = b1[half * (NB * BS) + n * BS + j];
            sB2[tid] = b2[half * (NB * BS) + n * BS + j];
        }
    }
    {
        const __nv_bfloat162* pa = g_A2 + ((size_t)(b * HH) * WF + wf) * CH + n * BS;
        const __nv_bfloat162 c128 = __float2bfloat162_rn(0.0078125f);
        for (int idx = tid; idx < HH * BS; idx += 256) {
            int h = idx / BS, c = idx - (idx / BS) * BS;
            __nv_bfloat162 v = __hmul2(pa[(size_t)h * WF * CH + c], c128);
            sX[c * XT + h]       = __low2bfloat16(v);
            sX[c * XT + 128 + h] = __high2bfloat16(v);
        }
    }
    __syncthreads();

    float acc[2][12][4];

    // GEMM1: forward H-DFT
    #pragma unroll
    for (int mt = 0; mt < 2; mt++)
        #pragma unroll
        for (int nt = 0; nt < 12; nt++)
            #pragma unroll
            for (int r = 0; r < 4; r++) acc[mt][nt][r] = 0.0f;

    for (int ks = 0; ks < 16; ks++) {
        const int k0 = ks * 16;
        unsigned a[2][4];
        #pragma unroll
        for (int mt = 0; mt < 2; mt++) {
            const __nv_bfloat16* ap = sG + (wm * 32 + mt * 16 + g) * GP + k0 + 2 * tig;
            a[mt][0] = *(const unsigned*)(ap);
            a[mt][1] = *(const unsigned*)(ap + 8 * GP);
            a[mt][2] = *(const unsigned*)(ap + 8);
            a[mt][3] = *(const unsigned*)(ap + 8 * GP + 8);
        }
        const int kk = wn ? (k0 ^ 128) : k0;
        const unsigned msk = (wn && k0 >= 128) ? 0x80008000u : 0u;
        #pragma unroll
        for (int nt = 0; nt < 12; nt++) {
            const __nv_bfloat16* bp = sX + (nt * 8 + g) * XT + kk + 2 * tig;
            unsigned b0 = *(const unsigned*)(bp) ^ msk;
            unsigned b1v = *(const unsigned*)(bp + 8) ^ msk;
            mma_bf16(acc[0][nt], a[0], b0, b1v);
            mma_bf16(acc[1][nt], a[1], b0, b1v);
        }
    }
    __syncthreads();

    #pragma unroll
    for (int mt = 0; mt < 2; mt++)
        #pragma unroll
        for (int nt = 0; nt < 12; nt++) {
            int row0 = wm * 32 + mt * 16 + g;
            int jj = wn * 96 + nt * 8 + 2 * tig;
            *(__nv_bfloat162*)(sXm + row0 * XP + jj) =
                __floats2bfloat162_rn(acc[mt][nt][0], acc[mt][nt][1]);
            *(__nv_bfloat162*)(sXm + (row0 + 8) * XP + jj) =
                __floats2bfloat162_rn(acc[mt][nt][2], acc[mt][nt][3]);
        }
    __syncthreads();

    // MLP layer 1
    #pragma unroll
    for (int mt = 0; mt < 2; mt++)
        #pragma unroll
        for (int nt = 0; nt < 12; nt++)
            #pragma unroll
            for (int r = 0; r < 4; r++) acc[mt][nt][r] = 0.0f;

    for (int ks = 0; ks < 12; ks++) {
        const int khalf = (ks >= 6);
        const int k0 = ks * 16, kkm = k0 - khalf * 96;
        const __nv_bfloat16* sW = (wn == 0) ? (khalf ? sWi : sWr)
                                            : (khalf ? sWr : sWi);
        const bool negA = (wn == 0) && khalf;
        unsigned a[2][4];
        #pragma unroll
        for (int mt = 0; mt < 2; mt++) {
            const __nv_bfloat16* ap = sXm + (wm * 32 + mt * 16 + g) * XP + k0 + 2 * tig;
            a[mt][0] = *(const unsigned*)(ap);
            a[mt][1] = *(const unsigned*)(ap + 8 * XP);
            a[mt][2] = *(const unsigned*)(ap + 8);
            a[mt][3] = *(const unsigned*)(ap + 8 * XP + 8);
        }
        if (negA) {
            #pragma unroll
            for (int mt = 0; mt < 2; mt++)
                #pragma unroll
                for (int r = 0; r < 4; r++) a[mt][r] ^= 0x80008000u;
        }
        #pragma unroll
        for (int nt = 0; nt < 12; nt++) {
            const __nv_bfloat16* bp = sW + (nt * 8 + g) * WP + kkm + 2 * tig;
            unsigned b0 = *(const unsigned*)(bp);
            unsigned b1v = *(const unsigned*)(bp + 8);
            mma_bf16(acc[0][nt], a[0], b0, b1v);
            mma_bf16(acc[1][nt], a[1], b0, b1v);
        }
    }
    __syncthreads();

    #pragma unroll
    for (int mt = 0; mt < 2; mt++)
        #pragma unroll
        for (int nt = 0; nt < 12; nt++) {
            int row0 = wm * 32 + mt * 16 + g;
            int jj = wn * 96 + nt * 8 + 2 * tig;
            float bb0 = sB1[jj], bb1 = sB1[jj + 1];
            *(__nv_bfloat162*)(sXm + row0 * XP + jj) = __floats2bfloat162_rn(
                fmaxf(acc[mt][nt][0] + bb0, 0.0f), fmaxf(acc[mt][nt][1] + bb1, 0.0f));
            *(__nv_bfloat162*)(sXm + (row0 + 8) * XP + jj) = __floats2bfloat162_rn(
                fmaxf(acc[mt][nt][2] + bb0, 0.0f), fmaxf(acc[mt][nt][3] + bb1, 0.0f));
        }
    {
        const float* wr = w2 + (size_t)n * BS * BS;
        const float* wi = w2 + (size_t)(NB + n) * BS * BS;
        for (int idx = tid; idx < BS * BS; idx += 256) {
            int i = idx / 96, o = idx - (idx / 96) * 96;
            sWr[o * WP + i] = __float2bfloat16_rn(wr[idx]);
            sWi[o * WP + i] = __float2bfloat16_rn(wi[idx]);
        }
    }
    __syncthreads();

    // MLP layer 2
    #pragma unroll
    for (int mt = 0; mt < 2; mt++)
        #pragma unroll
        for (int nt = 0; nt < 12; nt++)
            #pragma unroll
            for (int r = 0; r < 4; r++) acc[mt][nt][r] = 0.0f;

    for (int ks = 0; ks < 12; ks++) {
        const int khalf = (ks >= 6);
        const int k0 = ks * 16, kkm = k0 - khalf * 96;
        const __nv_bfloat16* sW = (wn == 0) ? (khalf ? sWi : sWr)
                                            : (khalf ? sWr : sWi);
        const bool negA = (wn == 0) && khalf;
        unsigned a[2][4];
        #pragma unroll
        for (int mt = 0; mt < 2; mt++) {
            const __nv_bfloat16* ap = sXm + (wm * 32 + mt * 16 + g) * XP + k0 + 2 * tig;
            a[mt][0] = *(const unsigned*)(ap);
            a[mt][1] = *(const unsigned*)(ap + 8 * XP);
            a[mt][2] = *(const unsigned*)(ap + 8);
            a[mt][3] = *(const unsigned*)(ap + 8 * XP + 8);
        }
        if (negA) {
            #pragma unroll
            for (int mt = 0; mt < 2; mt++)
                #pragma unroll
                for (int r = 0; r < 4; r++) a[mt][r] ^= 0x80008000u;
        }
        #pragma unroll
        for (int nt = 0; nt < 12; nt++) {
            const __nv_bfloat16* bp = sW + (nt * 8 + g) * WP + kkm + 2 * tig;
            unsigned b0 = *(const unsigned*)(bp);
            unsigned b1v = *(const unsigned*)(bp + 8);
            mma_bf16(acc[0][nt], a[0], b0, b1v);
            mma_bf16(acc[1][nt], a[1], b0, b1v);
        }
    }
    __syncthreads();

    // softshrink -> sOt (transposed)
    {
        const float lam = 0.01f;
        #pragma unroll
        for (int mt = 0; mt < 2; mt++)
            #pragma unroll
            for (int nt = 0; nt < 12; nt++) {
                int row0 = wm * 32 + mt * 16 + g;
                int jj = wn * 96 + nt * 8 + 2 * tig;
                int c = jj - wn * 96;
                float bb0 = sB2[jj], bb1 = sB2[jj + 1];
                #pragma unroll
                for (int r = 0; r < 4; r++) {
                    float v = acc[mt][nt][r] + ((r & 1) ? bb1 : bb0);
                    v = copysignf(fmaxf(fabsf(v) - lam, 0.0f), v);
                    int cc = c + (r & 1);
                    int kb = wn * 128 + row0 + (r >> 1) * 8;
                    sOt[cc * XT + kb] = __float2bfloat16_rn(v);
                }
            }
    }
    __syncthreads();

    // GEMM2: inverse H-DFT
    #pragma unroll
    for (int mt = 0; mt < 2; mt++)
        #pragma unroll
        for (int nt = 0; nt < 12; nt++)
            #pragma unroll
            for (int r = 0; r < 4; r++) acc[mt][nt][r] = 0.0f;

    for (int ks = 0; ks < 16; ks++) {
        const int k0 = ks * 16;
        unsigned a[2][4];
        #pragma unroll
        for (int mt = 0; mt < 2; mt++) {
            const __nv_bfloat16* ap = sG + (wm * 32 + mt * 16 + g) * GP + k0 + 2 * tig;
            a[mt][0] = *(const unsigned*)(ap);
            a[mt][1] = *(const unsigned*)(ap + 8 * GP);
            a[mt][2] = *(const unsigned*)(ap + 8);
            a[mt][3] = *(const unsigned*)(ap + 8 * GP + 8);
        }
        const int kk = wn ? (k0 ^ 128) : k0;
        const unsigned msk = (!wn && k0 >= 128) ? 0x80008000u : 0u;
        #pragma unroll
        for (int nt = 0; nt < 12; nt++) {
            const __nv_bfloat16* bp = sOt + (nt * 8 + g) * XT + kk + 2 * tig;
            unsigned b0 = *(const unsigned*)(bp) ^ msk;
            unsigned b1v = *(const unsigned*)(bp + 8) ^ msk;
            mma_bf16(acc[0][nt], a[0], b0, b1v);
            mma_bf16(acc[1][nt], a[1], b0, b1v);
        }
    }
    __syncthreads();

    #pragma unroll
    for (int mt = 0; mt < 2; mt++)
        #pragma unroll
        for (int nt = 0; nt < 12; nt++) {
            int row0 = wm * 32 + mt * 16 + g;
            int jj = wn * 96 + nt * 8 + 2 * tig;
            *(__nv_bfloat162*)(stg + row0 * XP + jj) =
                __floats2bfloat162_rn(acc[mt][nt][0], acc[mt][nt][1]);
            *(__nv_bfloat162*)(stg + (row0 + 8) * XP + jj) =
                __floats2bfloat162_rn(acc[mt][nt][2], acc[mt][nt][3]);
        }
    __syncthreads();

    {
        __nv_bfloat162* pb = g_B2 + ((size_t)(b * HH) * WF + wf) * CH + n * BS;
        for (int idx = tid; idx < HH * BS; idx += 256) {
            int h = idx / BS, c = idx - (idx / BS) * BS;
            pb[(size_t)h * WF * CH + c] =
                __halves2bfloat162(stg[h * XP + c], stg[h * XP + 96 + c]);
        }
    }
}

// ---------------------------------------------------------------------------
// K5: W-irfft as GEMM + residual. Per CTA: one bh row, one 96-channel tile.
//   out(128 x 96) = G5(128 x 144) * [Zr;Zi](144 x 96) + x
// ---------------------------------------------------------------------------
#define P5 146                 /* bf16 pitch: 73 words -> conflict-free */
#define K5_SG 0                /* 128*146*2 = 37376 */
#define K5_SB 37376            /* 96*146*2  = 28032 */
#define K5_TOT 65408

__global__ void __launch_bounds__(256) k5g(const float* __restrict__ x,
                                           float* __restrict__ out)
{
    extern __shared__ char sm[];
    __nv_bfloat16* sG = (__nv_bfloat16*)(sm + K5_SG);
    __nv_bfloat16* sB = (__nv_bfloat16*)(sm + K5_SB);

    const int tid = threadIdx.x;
    const int bh = blockIdx.y;
    const int c0 = blockIdx.x * 96;
    const int lane = tid & 31, warp = tid >> 5;
    const int g = lane >> 2, tig = lane & 3;
    const int wm = warp & 3, wn = warp >> 2;

    // load G5 (pitch matches source: 146)
    {
        const unsigned* src = (const unsigned*)g_G5;
        unsigned* dst = (unsigned*)sG;
        for (int p = tid; p < 128 * 73; p += 256) dst[p] = src[p];
    }
    // zero sB, then fill Zr -> cols 0..64, Zi -> cols 72..136
    {
        unsigned* dz = (unsigned*)sB;
        for (int p = tid; p < 96 * 73; p += 256) dz[p] = 0u;
    }
    __syncthreads();
    {
        const __nv_bfloat162* pb = g_B2 + (size_t)bh * WF * CH + c0;
        for (int idx = tid; idx < 65 * 96; idx += 256) {
            int k = idx / 96, c = idx - (idx / 96) * 96;
            __nv_bfloat162 v = pb[(size_t)k * CH + c];
            sB[c * P5 + k]      = __low2bfloat16(v);
            sB[c * P5 + 72 + k] = __high2bfloat16(v);
        }
    }
    __syncthreads();

    float acc[2][6][4];
    #pragma unroll
    for (int mt = 0; mt < 2; mt++)
        #pragma unroll
        for (int nt = 0; nt < 6; nt++)
            #pragma unroll
            for (int r = 0; r < 4; r++) acc[mt][nt][r] = 0.0f;

    for (int ks = 0; ks < 9; ks++) {
        const int k0 = ks * 16;
        unsigned a[2][4];
        #pragma unroll
        for (int mt = 0; mt < 2; mt++) {
            const __nv_bfloat16* ap = sG + (wm * 32 + mt * 16 + g) * P5 + k0 + 2 * tig;
            a[mt][0] = *(const unsigned*)(ap);
            a[mt][1] = *(const unsigned*)(ap + 8 * P5);
            a[mt][2] = *(const unsigned*)(ap + 8);
            a[mt][3] = *(const unsigned*)(ap + 8 * P5 + 8);
        }
        #pragma unroll
        for (int nt = 0; nt < 6; nt++) {
            const __nv_bfloat16* bp = sB + (wn * 48 + nt * 8 + g) * P5 + k0 + 2 * tig;
            unsigned b0 = *(const unsigned*)(bp);
            unsigned b1v = *(const unsigned*)(bp + 8);
            mma_bf16(acc[0][nt], a[0], b0, b1v);
            mma_bf16(acc[1][nt], a[1], b0, b1v);
        }
    }

    // epilogue: + x residual, write out (fp32), directly from accumulators
    {
        const float* px = x   + (size_t)bh * WW * CH + c0;
        float*       po = out + (size_t)bh * WW * CH + c0;
        #pragma unroll
        for (int mt = 0; mt < 2; mt++)
            #pragma unroll
            for (int nt = 0; nt < 6; nt++) {
                int row0 = wm * 32 + mt * 16 + g;
                int jj = wn * 48 + nt * 8 + 2 * tig;
                float2 xv0 = *(const float2*)(px + (size_t)row0 * CH + jj);
                float2 xv1 = *(const float2*)(px + (size_t)(row0 + 8) * CH + jj);
                *(float2*)(po + (size_t)row0 * CH + jj) =
                    make_float2(acc[mt][nt][0] + xv0.x, acc[mt][nt][1] + xv0.y);
                *(float2*)(po + (size_t)(row0 + 8) * CH + jj) =
                    make_float2(acc[mt][nt][2] + xv1.x, acc[mt][nt][3] + xv1.y);
            }
    }
}

// ---------------------------------------------------------------------------
extern "C" void kernel_launch(void* const* d_in, const int* in_sizes, int n_in,
                              void* d_out, int out_size)
{
    (void)in_sizes; (void)n_in; (void)out_size;
    const float* x  = (const float*)d_in[0];
    const float* w1 = (const float*)d_in[1];
    const float* b1 = (const float*)d_in[2];
    const float* w2 = (const float*)d_in[3];
    const float* b2 = (const float*)d_in[4];
    float* out = (float*)d_out;

    cudaFuncSetAttribute(k1g,  cudaFuncAttributeMaxDynamicSharedMemorySize, K1_TOT);
    cudaFuncSetAttribute(kmid, cudaFuncAttributeMaxDynamicSharedMemorySize, SM_TOT);
    cudaFuncSetAttribute(k5g,  cudaFuncAttributeMaxDynamicSharedMemorySize, K5_TOT);

    k0_build<<<1, 256>>>();
    k1g <<<dim3(CH / 96, BB * HH), 256, K1_TOT>>>(x);
    kmid<<<dim3(NB, BB * WF), 256, SM_TOT>>>(w1, b1, w2, b2);
    k5g <<<dim3(CH / 96, BB * HH), 256, K5_TOT>>>(x, out);
}

// round 7
// speedup vs baseline: 1.3862x; 1.0116x over previous
#include <cuda_runtime.h>
#include <cuda_bf16.h>

// ---------------------------------------------------------------------------
// AFNO2D: rfft2(128x128, ortho) -> blockwise complex MLP (8 blocks x 96ch,
// relu, softshrink 0.01) -> irfft2 -> + x.   All three stages are tensor-core
// GEMMs now:
//   K1  W-rfft as GEMM:  Y = G1 . x          -> g_A2 (bf16x2)
//   KMID per (b,wf,n):   H-DFT -> MLP -> inv H-DFT (all in SMEM)  g_A2 -> g_B2
//   K5  W-irfft as GEMM: out = G5 . [Zr;Zi] + x
// ---------------------------------------------------------------------------

#define BB 4
#define HH 128
#define WW 128
#define CH 768
#define NB 8
#define BS 96
#define WF 65
#define MPTS (BB*HH*WF)

__device__ __nv_bfloat162 g_A2[(size_t)MPTS * CH];
__device__ __nv_bfloat162 g_B2[(size_t)MPTS * CH];
__device__ __nv_bfloat16  g_G [128 * 256];   // kmid H-DFT  [h'][k<128:cos | k>=128:sin]
__device__ __nv_bfloat16  g_G1[128 * 128];   // k1: rows 0..64 = cos(2pi m w/128), rows 65..127 = -sin(2pi (m-64) w/128)
__device__ __nv_bfloat16  g_G5[128 * 146];   // k5: [w][k<65: eps*cos/128 | 72..136: -eps*sin/128 | else 0]

// ---------------- K0: build DFT matrices -----------------------------------
__global__ void k0_build()
{
    int tid = threadIdx.x;
    for (int idx = tid; idx < 128 * 256; idx += 256) {
        int hp = idx >> 8, k = idx & 255, kk = k & 127;
        int m = (hp * kk) & 127;
        float s, c; sincospif(m * (1.0f / 64.0f), &s, &c);
        g_G[idx] = __float2bfloat16_rn((k < 128) ? c : s);
    }
    for (int idx = tid; idx < 128 * 128; idx += 256) {
        int m = idx >> 7, w = idx & 127;
        float val;
        if (m < 65) {
            int a = (m * w) & 127;
            float s, c; sincospif(a * (1.0f / 64.0f), &s, &c);
            val = c;
        } else {
            int a = ((m - 64) * w) & 127;
            float s, c; sincospif(a * (1.0f / 64.0f), &s, &c);
            val = -s;
        }
        g_G1[idx] = __float2bfloat16_rn(val);
    }
    for (int idx = tid; idx < 128 * 146; idx += 256) {
        int w = idx / 146, k = idx - (idx / 146) * 146;
        float val = 0.0f;
        if (k < 65) {
            float eps = (k == 0 || k == 64) ? 1.0f : 2.0f;
            int a = (w * k) & 127;
            float s, c; sincospif(a * (1.0f / 64.0f), &s, &c);
            val = eps * c * (1.0f / 128.0f);
        } else if (k >= 72 && k < 137) {
            int kk = k - 72;
            float eps = (kk == 0 || kk == 64) ? 1.0f : 2.0f;
            int a = (w * kk) & 127;
            float s, c; sincospif(a * (1.0f / 64.0f), &s, &c);
            val = -eps * s * (1.0f / 128.0f);
        }
        g_G5[idx] = __float2bfloat16_rn(val);
    }
}

__device__ __forceinline__ void mma_bf16(float* d, const unsigned* a, unsigned b0, unsigned b1)
{
    asm volatile(
        "mma.sync.aligned.m16n8k16.row.col.f32.bf16.bf16.f32 "
        "{%0,%1,%2,%3},{%4,%5,%6,%7},{%8,%9},{%0,%1,%2,%3};"
        : "+f"(d[0]), "+f"(d[1]), "+f"(d[2]), "+f"(d[3])
        : "r"(a[0]), "r"(a[1]), "r"(a[2]), "r"(a[3]), "r"(b0), "r"(b1));
}

// ---------------------------------------------------------------------------
// K1: W-rfft as GEMM. Per CTA: one bh row, one 96-channel tile.
//   Y(128 x 96) = G1(128 x 128) * x^T(128 x 96)  ->  g_A2[bh][k][c] bf16x2
// ---------------------------------------------------------------------------
#define P1 130                 /* bf16 pitch: 65 words -> conflict-free */
#define K1_SG 0                /* 128*130*2 = 33280 */
#define K1_SB 33280            /* 96*130*2  = 24960 */
#define K1_TOT 58240
#define STG_P 98

__global__ void __launch_bounds__(256) k1g(const float* __restrict__ x)
{
    extern __shared__ char sm[];
    __nv_bfloat16* sG = (__nv_bfloat16*)(sm + K1_SG);
    __nv_bfloat16* sB = (__nv_bfloat16*)(sm + K1_SB);
    __nv_bfloat16* stg = (__nv_bfloat16*)(sm + K1_SG);   // aliases sG after GEMM

    const int tid = threadIdx.x;
    const int bh = blockIdx.y;
    const int c0 = blockIdx.x * 96;
    const int lane = tid & 31, warp = tid >> 5;
    const int g = lane >> 2, tig = lane & 3;
    const int wm = warp & 3, wn = warp >> 2;

    // load G1 (pitched)
    {
        const unsigned* src = (const unsigned*)g_G1;
        unsigned* dst = (unsigned*)sG;
        for (int p = tid; p < 128 * 64; p += 256) {
            int row = p >> 6, kp = p & 63;
            dst[row * 65 + kp] = src[p];
        }
    }
    // ingest x transposed: sB[c][w]
    {
        const float* px = x + (size_t)bh * WW * CH + c0;
        for (int idx = tid; idx < 128 * 96; idx += 256) {
            int w = idx / 96, c = idx - (idx / 96) * 96;
            sB[c * P1 + w] = __float2bfloat16_rn(px[(size_t)w * CH + c]);
        }
    }
    __syncthreads();

    float acc[2][6][4];
    #pragma unroll
    for (int mt = 0; mt < 2; mt++)
        #pragma unroll
        for (int nt = 0; nt < 6; nt++)
            #pragma unroll
            for (int r = 0; r < 4; r++) acc[mt][nt][r] = 0.0f;

    for (int ks = 0; ks < 8; ks++) {
        const int k0 = ks * 16;
        unsigned a[2][4];
        #pragma unroll
        for (int mt = 0; mt < 2; mt++) {
            const __nv_bfloat16* ap = sG + (wm * 32 + mt * 16 + g) * P1 + k0 + 2 * tig;
            a[mt][0] = *(const unsigned*)(ap);
            a[mt][1] = *(const unsigned*)(ap + 8 * P1);
            a[mt][2] = *(const unsigned*)(ap + 8);
            a[mt][3] = *(const unsigned*)(ap + 8 * P1 + 8);
        }
        #pragma unroll
        for (int nt = 0; nt < 6; nt++) {
            const __nv_bfloat16* bp = sB + (wn * 48 + nt * 8 + g) * P1 + k0 + 2 * tig;
            unsigned b0 = *(const unsigned*)(bp);
            unsigned b1v = *(const unsigned*)(bp + 8);
            mma_bf16(acc[0][nt], a[0], b0, b1v);
            mma_bf16(acc[1][nt], a[1], b0, b1v);
        }
    }
    __syncthreads();

    // stage [row 0..127][c 0..95] bf16
    #pragma unroll
    for (int mt = 0; mt < 2; mt++)
        #pragma unroll
        for (int nt = 0; nt < 6; nt++) {
            int row0 = wm * 32 + mt * 16 + g;
            int jj = wn * 48 + nt * 8 + 2 * tig;
            *(__nv_bfloat162*)(stg + row0 * STG_P + jj) =
                __floats2bfloat162_rn(acc[mt][nt][0], acc[mt][nt][1]);
            *(__nv_bfloat162*)(stg + (row0 + 8) * STG_P + jj) =
                __floats2bfloat162_rn(acc[mt][nt][2], acc[mt][nt][3]);
        }
    __syncthreads();

    // pack (Yr, Yi) -> g_A2 ; Yi[0] = Yi[64] = 0
    {
        __nv_bfloat162* pa = g_A2 + (size_t)bh * WF * CH + c0;
        const __nv_bfloat16 z = __float2bfloat16_rn(0.0f);
        for (int idx = tid; idx < 65 * 96; idx += 256) {
            int k = idx / 96, c = idx - (idx / 96) * 96;
            __nv_bfloat16 re = stg[k * STG_P + c];
            __nv_bfloat16 im = (k >= 1 && k <= 63) ? stg[(64 + k) * STG_P + c] : z;
            pa[(size_t)k * CH + c] = __halves2bfloat162(re, im);
        }
    }
}

// ---------------------------------------------------------------------------
// KMID: per-(b,wf,n) fused H-DFT -> complex MLP -> inverse H-DFT. (unchanged)
// ---------------------------------------------------------------------------
#define GP  264
#define XT  264
#define XP  200
#define WP  104
#define SM_G   0
#define SM_X   67584
#define SM_W   118784
#define SM_WI  138752
#define SM_B1  158720
#define SM_B2  159488
#define SM_TOT 160256

__global__ void __launch_bounds__(256) kmid(const float* __restrict__ w1,
                                            const float* __restrict__ b1,
                                            const float* __restrict__ w2,
                                            const float* __restrict__ b2)
{
    extern __shared__ char sm[];
    __nv_bfloat16* sG  = (__nv_bfloat16*)(sm + SM_G);
    __nv_bfloat16* sX  = (__nv_bfloat16*)(sm + SM_X);
    __nv_bfloat16* sXm = (__nv_bfloat16*)(sm + SM_X);
    __nv_bfloat16* sOt = (__nv_bfloat16*)(sm + SM_X);
    __nv_bfloat16* sWr = (__nv_bfloat16*)(sm + SM_W);
    __nv_bfloat16* sWi = (__nv_bfloat16*)(sm + SM_WI);
    __nv_bfloat16* stg = (__nv_bfloat16*)(sm + SM_G);
    float* sB1 = (float*)(sm + SM_B1);
    float* sB2 = (float*)(sm + SM_B2);

    const int tid = threadIdx.x;
    const int n   = blockIdx.x;
    const int b   = blockIdx.y / WF;
    const int wf  = blockIdx.y - b * WF;
    const int lane = tid & 31, warp = tid >> 5;
    const int g = lane >> 2, tig = lane & 3;
    const int wm = warp & 3, wn = warp >> 2;

    {
        const __nv_bfloat162* src = (const __nv_bfloat162*)g_G;
        for (int p = tid; p < 128 * 128; p += 256) {
            int hp = p >> 7, kp = p & 127;
            *(__nv_bfloat162*)(sG + hp * GP + 2 * kp) = src[p];
        }
    }
    {
        const float* wr = w1 + (size_t)n * BS * BS;
        const float* wi = w1 + (size_t)(NB + n) * BS * BS;
        for (int idx = tid; idx < BS * BS; idx += 256) {
            int i = idx / 96, o = idx - (idx / 96) * 96;
            sWr[o * WP + i] = __float2bfloat16_rn(wr[idx]);
            sWi[o * WP + i] = __float2bfloat16_rn(wi[idx]);
        }
        if (tid < 192) {
            int half = tid / 96, j = tid - half * 96;
            sB1[tid] = b1[half * (NB * BS) + n * BS + j];
            sB2[tid] = b2[half * (NB * BS) + n * BS + j];
        }
    }
    {
        const __nv_bfloat162* pa = g_A2 + ((size_t)(b * HH) * WF + wf) * CH + n * BS;
        const __nv_bfloat162 c128 = __float2bfloat162_rn(0.0078125f);
        for (int idx = tid; idx < HH * BS; idx += 256) {
            int h = idx / BS, c = idx - (idx / BS) * BS;
            __nv_bfloat162 v = __hmul2(pa[(size_t)h * WF * CH + c], c128);
            sX[c * XT + h]       = __low2bfloat16(v);
            sX[c * XT + 128 + h] = __high2bfloat16(v);
        }
    }
    __syncthreads();

    float acc[2][12][4];

    // GEMM1: forward H-DFT
    #pragma unroll
    for (int mt = 0; mt < 2; mt++)
        #pragma unroll
        for (int nt = 0; nt < 12; nt++)
            #pragma unroll
            for (int r = 0; r < 4; r++) acc[mt][nt][r] = 0.0f;

    for (int ks = 0; ks < 16; ks++) {
        const int k0 = ks * 16;
        unsigned a[2][4];
        #pragma unroll
        for (int mt = 0; mt < 2; mt++) {
            const __nv_bfloat16* ap = sG + (wm * 32 + mt * 16 + g) * GP + k0 + 2 * tig;
            a[mt][0] = *(const unsigned*)(ap);
            a[mt][1] = *(const unsigned*)(ap + 8 * GP);
            a[mt][2] = *(const unsigned*)(ap + 8);
            a[mt][3] = *(const unsigned*)(ap + 8 * GP + 8);
        }
        const int kk = wn ? (k0 ^ 128) : k0;
        const unsigned msk = (wn && k0 >= 128) ? 0x80008000u : 0u;
        #pragma unroll
        for (int nt = 0; nt < 12; nt++) {
            const __nv_bfloat16* bp = sX + (nt * 8 + g) * XT + kk + 2 * tig;
            unsigned b0 = *(const unsigned*)(bp) ^ msk;
            unsigned b1v = *(const unsigned*)(bp + 8) ^ msk;
            mma_bf16(acc[0][nt], a[0], b0, b1v);
            mma_bf16(acc[1][nt], a[1], b0, b1v);
        }
    }
    __syncthreads();

    #pragma unroll
    for (int mt = 0; mt < 2; mt++)
        #pragma unroll
        for (int nt = 0; nt < 12; nt++) {
            int row0 = wm * 32 + mt * 16 + g;
            int jj = wn * 96 + nt * 8 + 2 * tig;
            *(__nv_bfloat162*)(sXm + row0 * XP + jj) =
                __floats2bfloat162_rn(acc[mt][nt][0], acc[mt][nt][1]);
            *(__nv_bfloat162*)(sXm + (row0 + 8) * XP + jj) =
                __floats2bfloat162_rn(acc[mt][nt][2], acc[mt][nt][3]);
        }
    __syncthreads();

    // MLP layer 1
    #pragma unroll
    for (int mt = 0; mt < 2; mt++)
        #pragma unroll
        for (int nt = 0; nt < 12; nt++)
            #pragma unroll
            for (int r = 0; r < 4; r++) acc[mt][nt][r] = 0.0f;

    for (int ks = 0; ks < 12; ks++) {
        const int khalf = (ks >= 6);
        const int k0 = ks * 16, kkm = k0 - khalf * 96;
        const __nv_bfloat16* sW = (wn == 0) ? (khalf ? sWi : sWr)
                                            : (khalf ? sWr : sWi);
        const bool negA = (wn == 0) && khalf;
        unsigned a[2][4];
        #pragma unroll
        for (int mt = 0; mt < 2; mt++) {
            const __nv_bfloat16* ap = sXm + (wm * 32 + mt * 16 + g) * XP + k0 + 2 * tig;
            a[mt][0] = *(const unsigned*)(ap);
            a[mt][1] = *(const unsigned*)(ap + 8 * XP);
            a[mt][2] = *(const unsigned*)(ap + 8);
            a[mt][3] = *(const unsigned*)(ap + 8 * XP + 8);
        }
        if (negA) {
            #pragma unroll
            for (int mt = 0; mt < 2; mt++)
                #pragma unroll
                for (int r = 0; r < 4; r++) a[mt][r] ^= 0x80008000u;
        }
        #pragma unroll
        for (int nt = 0; nt < 12; nt++) {
            const __nv_bfloat16* bp = sW + (nt * 8 + g) * WP + kkm + 2 * tig;
            unsigned b0 = *(const unsigned*)(bp);
            unsigned b1v = *(const unsigned*)(bp + 8);
            mma_bf16(acc[0][nt], a[0], b0, b1v);
            mma_bf16(acc[1][nt], a[1], b0, b1v);
        }
    }
    __syncthreads();

    #pragma unroll
    for (int mt = 0; mt < 2; mt++)
        #pragma unroll
        for (int nt = 0; nt < 12; nt++) {
            int row0 = wm * 32 + mt * 16 + g;
            int jj = wn * 96 + nt * 8 + 2 * tig;
            float bb0 = sB1[jj], bb1 = sB1[jj + 1];
            *(__nv_bfloat162*)(sXm + row0 * XP + jj) = __floats2bfloat162_rn(
                fmaxf(acc[mt][nt][0] + bb0, 0.0f), fmaxf(acc[mt][nt][1] + bb1, 0.0f));
            *(__nv_bfloat162*)(sXm + (row0 + 8) * XP + jj) = __floats2bfloat162_rn(
                fmaxf(acc[mt][nt][2] + bb0, 0.0f), fmaxf(acc[mt][nt][3] + bb1, 0.0f));
        }
    {
        const float* wr = w2 + (size_t)n * BS * BS;
        const float* wi = w2 + (size_t)(NB + n) * BS * BS;
        for (int idx = tid; idx < BS * BS; idx += 256) {
            int i = idx / 96, o = idx - (idx / 96) * 96;
            sWr[o * WP + i] = __float2bfloat16_rn(wr[idx]);
            sWi[o * WP + i] = __float2bfloat16_rn(wi[idx]);
        }
    }
    __syncthreads();

    // MLP layer 2
    #pragma unroll
    for (int mt = 0; mt < 2; mt++)
        #pragma unroll
        for (int nt = 0; nt < 12; nt++)
            #pragma unroll
            for (int r = 0; r < 4; r++) acc[mt][nt][r] = 0.0f;

    for (int ks = 0; ks < 12; ks++) {
        const int khalf = (ks >= 6);
        const int k0 = ks * 16, kkm = k0 - khalf * 96;
        const __nv_bfloat16* sW = (wn == 0) ? (khalf ? sWi : sWr)
                                            : (khalf ? sWr : sWi);
        const bool negA = (wn == 0) && khalf;
        unsigned a[2][4];
        #pragma unroll
        for (int mt = 0; mt < 2; mt++) {
            const __nv_bfloat16* ap = sXm + (wm * 32 + mt * 16 + g) * XP + k0 + 2 * tig;
            a[mt][0] = *(const unsigned*)(ap);
            a[mt][1] = *(const unsigned*)(ap + 8 * XP);
            a[mt][2] = *(const unsigned*)(ap + 8);
            a[mt][3] = *(const unsigned*)(ap + 8 * XP + 8);
        }
        if (negA) {
            #pragma unroll
            for (int mt = 0; mt < 2; mt++)
                #pragma unroll
                for (int r = 0; r < 4; r++) a[mt][r] ^= 0x80008000u;
        }
        #pragma unroll
        for (int nt = 0; nt < 12; nt++) {
            const __nv_bfloat16* bp = sW + (nt * 8 + g) * WP + kkm + 2 * tig;
            unsigned b0 = *(const unsigned*)(bp);
            unsigned b1v = *(const unsigned*)(bp + 8);
            mma_bf16(acc[0][nt], a[0], b0, b1v);
            mma_bf16(acc[1][nt], a[1], b0, b1v);
        }
    }
    __syncthreads();

    // softshrink -> sOt (transposed)
    {
        const float lam = 0.01f;
        #pragma unroll
        for (int mt = 0; mt < 2; mt++)
            #pragma unroll
            for (int nt = 0; nt < 12; nt++) {
                int row0 = wm * 32 + mt * 16 + g;
                int jj = wn * 96 + nt * 8 + 2 * tig;
                int c = jj - wn * 96;
                float bb0 = sB2[jj], bb1 = sB2[jj + 1];
                #pragma unroll
                for (int r = 0; r < 4; r++) {
                    float v = acc[mt][nt][r] + ((r & 1) ? bb1 : bb0);
                    v = copysignf(fmaxf(fabsf(v) - lam, 0.0f), v);
                    int cc = c + (r & 1);
                    int kb = wn * 128 + row0 + (r >> 1) * 8;
                    sOt[cc * XT + kb] = __float2bfloat16_rn(v);
                }
            }
    }
    __syncthreads();

    // GEMM2: inverse H-DFT
    #pragma unroll
    for (int mt = 0; mt < 2; mt++)
        #pragma unroll
        for (int nt = 0; nt < 12; nt++)
            #pragma unroll
            for (int r = 0; r < 4; r++) acc[mt][nt][r] = 0.0f;

    for (int ks = 0; ks < 16; ks++) {
        const int k0 = ks * 16;
        unsigned a[2][4];
        #pragma unroll
        for (int mt = 0; mt < 2; mt++) {
            const __nv_bfloat16* ap = sG + (wm * 32 + mt * 16 + g) * GP + k0 + 2 * tig;
            a[mt][0] = *(const unsigned*)(ap);
            a[mt][1] = *(const unsigned*)(ap + 8 * GP);
            a[mt][2] = *(const unsigned*)(ap + 8);
            a[mt][3] = *(const unsigned*)(ap + 8 * GP + 8);
        }
        const int kk = wn ? (k0 ^ 128) : k0;
        const unsigned msk = (!wn && k0 >= 128) ? 0x80008000u : 0u;
        #pragma unroll
        for (int nt = 0; nt < 12; nt++) {
            const __nv_bfloat16* bp = sOt + (nt * 8 + g) * XT + kk + 2 * tig;
            unsigned b0 = *(const unsigned*)(bp) ^ msk;
            unsigned b1v = *(const unsigned*)(bp + 8) ^ msk;
            mma_bf16(acc[0][nt], a[0], b0, b1v);
            mma_bf16(acc[1][nt], a[1], b0, b1v);
        }
    }
    __syncthreads();

    #pragma unroll
    for (int mt = 0; mt < 2; mt++)
        #pragma unroll
        for (int nt = 0; nt < 12; nt++) {
            int row0 = wm * 32 + mt * 16 + g;
            int jj = wn * 96 + nt * 8 + 2 * tig;
            *(__nv_bfloat162*)(stg + row0 * XP + jj) =
                __floats2bfloat162_rn(acc[mt][nt][0], acc[mt][nt][1]);
            *(__nv_bfloat162*)(stg + (row0 + 8) * XP + jj) =
                __floats2bfloat162_rn(acc[mt][nt][2], acc[mt][nt][3]);
        }
    __syncthreads();

    {
        __nv_bfloat162* pb = g_B2 + ((size_t)(b * HH) * WF + wf) * CH + n * BS;
        for (int idx = tid; idx < HH * BS; idx += 256) {
            int h = idx / BS, c = idx - (idx / BS) * BS;
            pb[(size_t)h * WF * CH + c] =
                __halves2bfloat162(stg[h * XP + c], stg[h * XP + 96 + c]);
        }
    }
}

// ---------------------------------------------------------------------------
// K5: W-irfft as GEMM + residual. Per CTA: one bh row, one 96-channel tile.
//   out(128 x 96) = G5(128 x 144) * [Zr;Zi](144 x 96) + x
// ---------------------------------------------------------------------------
#define P5 146                 /* bf16 pitch: 73 words -> conflict-free */
#define K5_SG 0                /* 128*146*2 = 37376 */
#define K5_SB 37376            /* 96*146*2  = 28032 */
#define K5_TOT 65408

__global__ void __launch_bounds__(256) k5g(const float* __restrict__ x,
                                           float* __restrict__ out)
{
    extern __shared__ char sm[];
    __nv_bfloat16* sG = (__nv_bfloat16*)(sm + K5_SG);
    __nv_bfloat16* sB = (__nv_bfloat16*)(sm + K5_SB);

    const int tid = threadIdx.x;
    const int bh = blockIdx.y;
    const int c0 = blockIdx.x * 96;
    const int lane = tid & 31, warp = tid >> 5;
    const int g = lane >> 2, tig = lane & 3;
    const int wm = warp & 3, wn = warp >> 2;

    // load G5 (pitch matches source: 146)
    {
        const unsigned* src = (const unsigned*)g_G5;
        unsigned* dst = (unsigned*)sG;
        for (int p = tid; p < 128 * 73; p += 256) dst[p] = src[p];
    }
    // zero sB, then fill Zr -> cols 0..64, Zi -> cols 72..136
    {
        unsigned* dz = (unsigned*)sB;
        for (int p = tid; p < 96 * 73; p += 256) dz[p] = 0u;
    }
    __syncthreads();
    {
        const __nv_bfloat162* pb = g_B2 + (size_t)bh * WF * CH + c0;
        for (int idx = tid; idx < 65 * 96; idx += 256) {
            int k = idx / 96, c = idx - (idx / 96) * 96;
            __nv_bfloat162 v = pb[(size_t)k * CH + c];
            sB[c * P5 + k]      = __low2bfloat16(v);
            sB[c * P5 + 72 + k] = __high2bfloat16(v);
        }
    }
    __syncthreads();

    float acc[2][6][4];
    #pragma unroll
    for (int mt = 0; mt < 2; mt++)
        #pragma unroll
        for (int nt = 0; nt < 6; nt++)
            #pragma unroll
            for (int r = 0; r < 4; r++) acc[mt][nt][r] = 0.0f;

    for (int ks = 0; ks < 9; ks++) {
        const int k0 = ks * 16;
        unsigned a[2][4];
        #pragma unroll
        for (int mt = 0; mt < 2; mt++) {
            const __nv_bfloat16* ap = sG + (wm * 32 + mt * 16 + g) * P5 + k0 + 2 * tig;
            a[mt][0] = *(const unsigned*)(ap);
            a[mt][1] = *(const unsigned*)(ap + 8 * P5);
            a[mt][2] = *(const unsigned*)(ap + 8);
            a[mt][3] = *(const unsigned*)(ap + 8 * P5 + 8);
        }
        #pragma unroll
        for (int nt = 0; nt < 6; nt++) {
            const __nv_bfloat16* bp = sB + (wn * 48 + nt * 8 + g) * P5 + k0 + 2 * tig;
            unsigned b0 = *(const unsigned*)(bp);
            unsigned b1v = *(const unsigned*)(bp + 8);
            mma_bf16(acc[0][nt], a[0], b0, b1v);
            mma_bf16(acc[1][nt], a[1], b0, b1v);
        }
    }

    // epilogue: + x residual, write out (fp32), directly from accumulators
    {
        const float* px = x   + (size_t)bh * WW * CH + c0;
        float*       po = out + (size_t)bh * WW * CH + c0;
        #pragma unroll
        for (int mt = 0; mt < 2; mt++)
            #pragma unroll
            for (int nt = 0; nt < 6; nt++) {
                int row0 = wm * 32 + mt * 16 + g;
                int jj = wn * 48 + nt * 8 + 2 * tig;
                float2 xv0 = *(const float2*)(px + (size_t)row0 * CH + jj);
                float2 xv1 = *(const float2*)(px + (size_t)(row0 + 8) * CH + jj);
                *(float2*)(po + (size_t)row0 * CH + jj) =
                    make_float2(acc[mt][nt][0] + xv0.x, acc[mt][nt][1] + xv0.y);
                *(float2*)(po + (size_t)(row0 + 8) * CH + jj) =
                    make_float2(acc[mt][nt][2] + xv1.x, acc[mt][nt][3] + xv1.y);
            }
    }
}

// ---------------------------------------------------------------------------
extern "C" void kernel_launch(void* const* d_in, const int* in_sizes, int n_in,
                              void* d_out, int out_size)
{
    (void)in_sizes; (void)n_in; (void)out_size;
    const float* x  = (const float*)d_in[0];
    const float* w1 = (const float*)d_in[1];
    const float* b1 = (const float*)d_in[2];
    const float* w2 = (const float*)d_in[3];
    const float* b2 = (const float*)d_in[4];
    float* out = (float*)d_out;

    cudaFuncSetAttribute(k1g,  cudaFuncAttributeMaxDynamicSharedMemorySize, K1_TOT);
    cudaFuncSetAttribute(kmid, cudaFuncAttributeMaxDynamicSharedMemorySize, SM_TOT);
    cudaFuncSetAttribute(k5g,  cudaFuncAttributeMaxDynamicSharedMemorySize, K5_TOT);

    k0_build<<<1, 256>>>();
    k1g <<<dim3(CH / 96, BB * HH), 256, K1_TOT>>>(x);
    kmid<<<dim3(NB, BB * WF), 256, SM_TOT>>>(w1, b1, w2, b2);
    k5g <<<dim3(CH / 96, BB * HH), 256, K5_TOT>>>(x, out);
}

// round 8
// speedup vs baseline: 1.4223x; 1.0260x over previous
#include <cuda_runtime.h>
#include <cuda_bf16.h>

// ---------------------------------------------------------------------------
// AFNO2D: rfft2(128x128, ortho) -> blockwise complex MLP (8 blocks x 96ch,
// relu, softshrink 0.01) -> irfft2 -> + x.   All tensor-core GEMMs:
//   K1  W-rfft as GEMM:  Y = G1 . x          -> g_A2 (bf16x2)   [N=192/CTA]
//   KMID per (b,wf,n):   H-DFT -> MLP -> inv H-DFT, 512 threads
//   K5  W-irfft as GEMM: out = G5 . [Zr;Zi] + x                 [N=192/CTA]
// ---------------------------------------------------------------------------

#define BB 4
#define HH 128
#define WW 128
#define CH 768
#define NB 8
#define BS 96
#define WF 65
#define MPTS (BB*HH*WF)

__device__ __nv_bfloat162 g_A2[(size_t)MPTS * CH];
__device__ __nv_bfloat162 g_B2[(size_t)MPTS * CH];
__device__ __nv_bfloat16  g_G [128 * 256];
__device__ __nv_bfloat16  g_G1[128 * 128];
__device__ __nv_bfloat16  g_G5[128 * 146];

// ---------------- K0: build DFT matrices -----------------------------------
__global__ void k0_build()
{
    int tid = blockIdx.x * 256 + threadIdx.x;
    const int STR = 32 * 256;
    for (int idx = tid; idx < 128 * 256; idx += STR) {
        int hp = idx >> 8, k = idx & 255, kk = k & 127;
        int m = (hp * kk) & 127;
        float s, c; sincospif(m * (1.0f / 64.0f), &s, &c);
        g_G[idx] = __float2bfloat16_rn((k < 128) ? c : s);
    }
    for (int idx = tid; idx < 128 * 128; idx += STR) {
        int m = idx >> 7, w = idx & 127;
        float val;
        if (m < 65) {
            int a = (m * w) & 127;
            float s, c; sincospif(a * (1.0f / 64.0f), &s, &c);
            val = c;
        } else {
            int a = ((m - 64) * w) & 127;
            float s, c; sincospif(a * (1.0f / 64.0f), &s, &c);
            val = -s;
        }
        g_G1[idx] = __float2bfloat16_rn(val);
    }
    for (int idx = tid; idx < 128 * 146; idx += STR) {
        int w = idx / 146, k = idx - (idx / 146) * 146;
        float val = 0.0f;
        if (k < 65) {
            float eps = (k == 0 || k == 64) ? 1.0f : 2.0f;
            int a = (w * k) & 127;
            float s, c; sincospif(a * (1.0f / 64.0f), &s, &c);
            val = eps * c * (1.0f / 128.0f);
        } else if (k >= 72 && k < 137) {
            int kk = k - 72;
            float eps = (kk == 0 || kk == 64) ? 1.0f : 2.0f;
            int a = (w * kk) & 127;
            float s, c; sincospif(a * (1.0f / 64.0f), &s, &c);
            val = -eps * s * (1.0f / 128.0f);
        }
        g_G5[idx] = __float2bfloat16_rn(val);
    }
}

__device__ __forceinline__ void mma_bf16(float* d, const unsigned* a, unsigned b0, unsigned b1)
{
    asm volatile(
        "mma.sync.aligned.m16n8k16.row.col.f32.bf16.bf16.f32 "
        "{%0,%1,%2,%3},{%4,%5,%6,%7},{%8,%9},{%0,%1,%2,%3};"
        : "+f"(d[0]), "+f"(d[1]), "+f"(d[2]), "+f"(d[3])
        : "r"(a[0]), "r"(a[1]), "r"(a[2]), "r"(a[3]), "r"(b0), "r"(b1));
}

// ---------------------------------------------------------------------------
// K1: W-rfft as GEMM. Per CTA: one bh row, 192 channels (2 blocks of 96).
//   Y(128 x 192) = G1(128 x 128) * x^T(128 x 192)
// ---------------------------------------------------------------------------
#define P1 130
#define K1_SG 0                /* 128*130*2 = 33280 */
#define K1_SB 33280            /* 192*130*2 = 49920 */
#define K1_TOT 83200
#define STG_P 194

__global__ void __launch_bounds__(256) k1g(const float* __restrict__ x)
{
    extern __shared__ char sm[];
    __nv_bfloat16* sG  = (__nv_bfloat16*)(sm + K1_SG);
    __nv_bfloat16* sB  = (__nv_bfloat16*)(sm + K1_SB);
    __nv_bfloat16* stg = (__nv_bfloat16*)(sm + K1_SG);   // 128*194*2=49664, aliases after GEMM

    const int tid = threadIdx.x;
    const int bh = blockIdx.y;
    const int c0 = blockIdx.x * 192;
    const int lane = tid & 31, warp = tid >> 5;
    const int g = lane >> 2, tig = lane & 3;
    const int wm = warp & 3, wn = warp >> 2;

    {
        const unsigned* src = (const unsigned*)g_G1;
        unsigned* dst = (unsigned*)sG;
        for (int p = tid; p < 128 * 64; p += 256) {
            int row = p >> 6, kp = p & 63;
            dst[row * 65 + kp] = src[p];
        }
    }
    {
        const float* px = x + (size_t)bh * WW * CH + c0;
        for (int idx = tid; idx < 128 * 192; idx += 256) {
            int w = idx / 192, c = idx - (idx / 192) * 192;
            sB[c * P1 + w] = __float2bfloat16_rn(px[(size_t)w * CH + c]);
        }
    }
    __syncthreads();

    float acc[2][12][4];
    #pragma unroll
    for (int mt = 0; mt < 2; mt++)
        #pragma unroll
        for (int nt = 0; nt < 12; nt++)
            #pragma unroll
            for (int r = 0; r < 4; r++) acc[mt][nt][r] = 0.0f;

    for (int ks = 0; ks < 8; ks++) {
        const int k0 = ks * 16;
        unsigned a[2][4];
        #pragma unroll
        for (int mt = 0; mt < 2; mt++) {
            const __nv_bfloat16* ap = sG + (wm * 32 + mt * 16 + g) * P1 + k0 + 2 * tig;
            a[mt][0] = *(const unsigned*)(ap);
            a[mt][1] = *(const unsigned*)(ap + 8 * P1);
            a[mt][2] = *(const unsigned*)(ap + 8);
            a[mt][3] = *(const unsigned*)(ap + 8 * P1 + 8);
        }
        #pragma unroll
        for (int nt = 0; nt < 12; nt++) {
            const __nv_bfloat16* bp = sB + (wn * 96 + nt * 8 + g) * P1 + k0 + 2 * tig;
            unsigned b0 = *(const unsigned*)(bp);
            unsigned b1v = *(const unsigned*)(bp + 8);
            mma_bf16(acc[0][nt], a[0], b0, b1v);
            mma_bf16(acc[1][nt], a[1], b0, b1v);
        }
    }
    __syncthreads();

    #pragma unroll
    for (int mt = 0; mt < 2; mt++)
        #pragma unroll
        for (int nt = 0; nt < 12; nt++) {
            int row0 = wm * 32 + mt * 16 + g;
            int jj = wn * 96 + nt * 8 + 2 * tig;
            *(__nv_bfloat162*)(stg + row0 * STG_P + jj) =
                __floats2bfloat162_rn(acc[mt][nt][0], acc[mt][nt][1]);
            *(__nv_bfloat162*)(stg + (row0 + 8) * STG_P + jj) =
                __floats2bfloat162_rn(acc[mt][nt][2], acc[mt][nt][3]);
        }
    __syncthreads();

    {
        __nv_bfloat162* pa = g_A2 + (size_t)bh * WF * CH + c0;
        const __nv_bfloat16 z = __float2bfloat16_rn(0.0f);
        for (int idx = tid; idx < 65 * 192; idx += 256) {
            int k = idx / 192, c = idx - (idx / 192) * 192;
            __nv_bfloat16 re = stg[k * STG_P + c];
            __nv_bfloat16 im = (k >= 1 && k <= 63) ? stg[(64 + k) * STG_P + c] : z;
            pa[(size_t)k * CH + c] = __halves2bfloat162(re, im);
        }
    }
}

// ---------------------------------------------------------------------------
// KMID: per-(b,wf,n) fused H-DFT -> complex MLP -> inverse H-DFT.
// 512 threads, 16 warps: wm=warp&3 (M slab), wq=warp>>2 (48-col N group),
// wn=wq>>1 (re/im half), wh=wq&1 (48-col half within the 96-col block).
// ---------------------------------------------------------------------------
#define GP  264
#define XT  264
#define XP  200
#define WP  104
#define SM_G   0
#define SM_X   67584
#define SM_W   118784
#define SM_WI  138752
#define SM_B1  158720
#define SM_B2  159488
#define SM_TOT 160256

__global__ void __launch_bounds__(512) kmid(const float* __restrict__ w1,
                                            const float* __restrict__ b1,
                                            const float* __restrict__ w2,
                                            const float* __restrict__ b2)
{
    extern __shared__ char sm[];
    __nv_bfloat16* sG  = (__nv_bfloat16*)(sm + SM_G);
    __nv_bfloat16* sX  = (__nv_bfloat16*)(sm + SM_X);
    __nv_bfloat16* sXm = (__nv_bfloat16*)(sm + SM_X);
    __nv_bfloat16* sOt = (__nv_bfloat16*)(sm + SM_X);
    __nv_bfloat16* sWr = (__nv_bfloat16*)(sm + SM_W);
    __nv_bfloat16* sWi = (__nv_bfloat16*)(sm + SM_WI);
    __nv_bfloat16* stg = (__nv_bfloat16*)(sm + SM_G);
    float* sB1 = (float*)(sm + SM_B1);
    float* sB2 = (float*)(sm + SM_B2);

    const int tid = threadIdx.x;
    const int n   = blockIdx.x;
    const int b   = blockIdx.y / WF;
    const int wf  = blockIdx.y - b * WF;
    const int lane = tid & 31, warp = tid >> 5;
    const int g = lane >> 2, tig = lane & 3;
    const int wm = warp & 3, wq = warp >> 2;
    const int wn = wq >> 1, wh = wq & 1;

    {
        const __nv_bfloat162* src = (const __nv_bfloat162*)g_G;
        for (int p = tid; p < 128 * 128; p += 512) {
            int hp = p >> 7, kp = p & 127;
            *(__nv_bfloat162*)(sG + hp * GP + 2 * kp) = src[p];
        }
    }
    {
        const float* wr = w1 + (size_t)n * BS * BS;
        const float* wi = w1 + (size_t)(NB + n) * BS * BS;
        for (int idx = tid; idx < BS * BS; idx += 512) {
            int i = idx / 96, o = idx - (idx / 96) * 96;
            sWr[o * WP + i] = __float2bfloat16_rn(wr[idx]);
            sWi[o * WP + i] = __float2bfloat16_rn(wi[idx]);
        }
        if (tid < 192) {
            int half = tid / 96, j = tid - half * 96;
            sB1[tid] = b1[half * (NB * BS) + n * BS + j];
            sB2[tid] = b2[half * (NB * BS) + n * BS + j];
        }
    }
    {
        const __nv_bfloat162* pa = g_A2 + ((size_t)(b * HH) * WF + wf) * CH + n * BS;
        const __nv_bfloat162 c128 = __float2bfloat162_rn(0.0078125f);
        for (int idx = tid; idx < HH * BS; idx += 512) {
            int h = idx / BS, c = idx - (idx / BS) * BS;
            __nv_bfloat162 v = __hmul2(pa[(size_t)h * WF * CH + c], c128);
            sX[c * XT + h]       = __low2bfloat16(v);
            sX[c * XT + 128 + h] = __high2bfloat16(v);
        }
    }
    __syncthreads();

    float acc[2][6][4];

    // =============== GEMM1: forward H-DFT ================================
    #pragma unroll
    for (int mt = 0; mt < 2; mt++)
        #pragma unroll
        for (int nt = 0; nt < 6; nt++)
            #pragma unroll
            for (int r = 0; r < 4; r++) acc[mt][nt][r] = 0.0f;

    for (int ks = 0; ks < 16; ks++) {
        const int k0 = ks * 16;
        unsigned a[2][4];
        #pragma unroll
        for (int mt = 0; mt < 2; mt++) {
            const __nv_bfloat16* ap = sG + (wm * 32 + mt * 16 + g) * GP + k0 + 2 * tig;
            a[mt][0] = *(const unsigned*)(ap);
            a[mt][1] = *(const unsigned*)(ap + 8 * GP);
            a[mt][2] = *(const unsigned*)(ap + 8);
            a[mt][3] = *(const unsigned*)(ap + 8 * GP + 8);
        }
        const int kk = wn ? (k0 ^ 128) : k0;
        const unsigned msk = (wn && k0 >= 128) ? 0x80008000u : 0u;
        #pragma unroll
        for (int nt = 0; nt < 6; nt++) {
            const __nv_bfloat16* bp = sX + (wh * 48 + nt * 8 + g) * XT + kk + 2 * tig;
            unsigned b0 = *(const unsigned*)(bp) ^ msk;
            unsigned b1v = *(const unsigned*)(bp + 8) ^ msk;
            mma_bf16(acc[0][nt], a[0], b0, b1v);
            mma_bf16(acc[1][nt], a[1], b0, b1v);
        }
    }
    __syncthreads();

    #pragma unroll
    for (int mt = 0; mt < 2; mt++)
        #pragma unroll
        for (int nt = 0; nt < 6; nt++) {
            int row0 = wm * 32 + mt * 16 + g;
            int jj = wq * 48 + nt * 8 + 2 * tig;
            *(__nv_bfloat162*)(sXm + row0 * XP + jj) =
                __floats2bfloat162_rn(acc[mt][nt][0], acc[mt][nt][1]);
            *(__nv_bfloat162*)(sXm + (row0 + 8) * XP + jj) =
                __floats2bfloat162_rn(acc[mt][nt][2], acc[mt][nt][3]);
        }
    __syncthreads();

    // =============== MLP layer 1 ==========================================
    #pragma unroll
    for (int mt = 0; mt < 2; mt++)
        #pragma unroll
        for (int nt = 0; nt < 6; nt++)
            #pragma unroll
            for (int r = 0; r < 4; r++) acc[mt][nt][r] = 0.0f;

    for (int ks = 0; ks < 12; ks++) {
        const int khalf = (ks >= 6);
        const int k0 = ks * 16, kkm = k0 - khalf * 96;
        const __nv_bfloat16* sW = (wn == 0) ? (khalf ? sWi : sWr)
                                            : (khalf ? sWr : sWi);
        const bool negA = (wn == 0) && khalf;
        unsigned a[2][4];
        #pragma unroll
        for (int mt = 0; mt < 2; mt++) {
            const __nv_bfloat16* ap = sXm + (wm * 32 + mt * 16 + g) * XP + k0 + 2 * tig;
            a[mt][0] = *(const unsigned*)(ap);
            a[mt][1] = *(const unsigned*)(ap + 8 * XP);
            a[mt][2] = *(const unsigned*)(ap + 8);
            a[mt][3] = *(const unsigned*)(ap + 8 * XP + 8);
        }
        if (negA) {
            #pragma unroll
            for (int mt = 0; mt < 2; mt++)
                #pragma unroll
                for (int r = 0; r < 4; r++) a[mt][r] ^= 0x80008000u;
        }
        #pragma unroll
        for (int nt = 0; nt < 6; nt++) {
            const __nv_bfloat16* bp = sW + (wh * 48 + nt * 8 + g) * WP + kkm + 2 * tig;
            unsigned b0 = *(const unsigned*)(bp);
            unsigned b1v = *(const unsigned*)(bp + 8);
            mma_bf16(acc[0][nt], a[0], b0, b1v);
            mma_bf16(acc[1][nt], a[1], b0, b1v);
        }
    }
    __syncthreads();

    #pragma unroll
    for (int mt = 0; mt < 2; mt++)
        #pragma unroll
        for (int nt = 0; nt < 6; nt++) {
            int row0 = wm * 32 + mt * 16 + g;
            int jj = wq * 48 + nt * 8 + 2 * tig;
            float bb0 = sB1[jj], bb1 = sB1[jj + 1];
            *(__nv_bfloat162*)(sXm + row0 * XP + jj) = __floats2bfloat162_rn(
                fmaxf(acc[mt][nt][0] + bb0, 0.0f), fmaxf(acc[mt][nt][1] + bb1, 0.0f));
            *(__nv_bfloat162*)(sXm + (row0 + 8) * XP + jj) = __floats2bfloat162_rn(
                fmaxf(acc[mt][nt][2] + bb0, 0.0f), fmaxf(acc[mt][nt][3] + bb1, 0.0f));
        }
    {
        const float* wr = w2 + (size_t)n * BS * BS;
        const float* wi = w2 + (size_t)(NB + n) * BS * BS;
        for (int idx = tid; idx < BS * BS; idx += 512) {
            int i = idx / 96, o = idx - (idx / 96) * 96;
            sWr[o * WP + i] = __float2bfloat16_rn(wr[idx]);
            sWi[o * WP + i] = __float2bfloat16_rn(wi[idx]);
        }
    }
    __syncthreads();

    // =============== MLP layer 2 ==========================================
    #pragma unroll
    for (int mt = 0; mt < 2; mt++)
        #pragma unroll
        for (int nt = 0; nt < 6; nt++)
            #pragma unroll
            for (int r = 0; r < 4; r++) acc[mt][nt][r] = 0.0f;

    for (int ks = 0; ks < 12; ks++) {
        const int khalf = (ks >= 6);
        const int k0 = ks * 16, kkm = k0 - khalf * 96;
        const __nv_bfloat16* sW = (wn == 0) ? (khalf ? sWi : sWr)
                                            : (khalf ? sWr : sWi);
        const bool negA = (wn == 0) && khalf;
        unsigned a[2][4];
        #pragma unroll
        for (int mt = 0; mt < 2; mt++) {
            const __nv_bfloat16* ap = sXm + (wm * 32 + mt * 16 + g) * XP + k0 + 2 * tig;
            a[mt][0] = *(const unsigned*)(ap);
            a[mt][1] = *(const unsigned*)(ap + 8 * XP);
            a[mt][2] = *(const unsigned*)(ap + 8);
            a[mt][3] = *(const unsigned*)(ap + 8 * XP + 8);
        }
        if (negA) {
            #pragma unroll
            for (int mt = 0; mt < 2; mt++)
                #pragma unroll
                for (int r = 0; r < 4; r++) a[mt][r] ^= 0x80008000u;
        }
        #pragma unroll
        for (int nt = 0; nt < 6; nt++) {
            const __nv_bfloat16* bp = sW + (wh * 48 + nt * 8 + g) * WP + kkm + 2 * tig;
            unsigned b0 = *(const unsigned*)(bp);
            unsigned b1v = *(const unsigned*)(bp + 8);
            mma_bf16(acc[0][nt], a[0], b0, b1v);
            mma_bf16(acc[1][nt], a[1], b0, b1v);
        }
    }
    __syncthreads();

    // softshrink -> sOt (transposed)
    {
        const float lam = 0.01f;
        #pragma unroll
        for (int mt = 0; mt < 2; mt++)
            #pragma unroll
            for (int nt = 0; nt < 6; nt++) {
                int row0 = wm * 32 + mt * 16 + g;
                int c = wh * 48 + nt * 8 + 2 * tig;
                int jj = wn * 96 + c;
                float bb0 = sB2[jj], bb1 = sB2[jj + 1];
                #pragma unroll
                for (int r = 0; r < 4; r++) {
                    float v = acc[mt][nt][r] + ((r & 1) ? bb1 : bb0);
                    v = copysignf(fmaxf(fabsf(v) - lam, 0.0f), v);
                    int cc = c + (r & 1);
                    int kb = wn * 128 + row0 + (r >> 1) * 8;
                    sOt[cc * XT + kb] = __float2bfloat16_rn(v);
                }
            }
    }
    __syncthreads();

    // =============== GEMM2: inverse H-DFT =================================
    #pragma unroll
    for (int mt = 0; mt < 2; mt++)
        #pragma unroll
        for (int nt = 0; nt < 6; nt++)
            #pragma unroll
            for (int r = 0; r < 4; r++) acc[mt][nt][r] = 0.0f;

    for (int ks = 0; ks < 16; ks++) {
        const int k0 = ks * 16;
        unsigned a[2][4];
        #pragma unroll
        for (int mt = 0; mt < 2; mt++) {
            const __nv_bfloat16* ap = sG + (wm * 32 + mt * 16 + g) * GP + k0 + 2 * tig;
            a[mt][0] = *(const unsigned*)(ap);
            a[mt][1] = *(const unsigned*)(ap + 8 * GP);
            a[mt][2] = *(const unsigned*)(ap + 8);
            a[mt][3] = *(const unsigned*)(ap + 8 * GP + 8);
        }
        const int kk = wn ? (k0 ^ 128) : k0;
        const unsigned msk = (!wn && k0 >= 128) ? 0x80008000u : 0u;
        #pragma unroll
        for (int nt = 0; nt < 6; nt++) {
            const __nv_bfloat16* bp = sOt + (wh * 48 + nt * 8 + g) * XT + kk + 2 * tig;
            unsigned b0 = *(const unsigned*)(bp) ^ msk;
            unsigned b1v = *(const unsigned*)(bp + 8) ^ msk;
            mma_bf16(acc[0][nt], a[0], b0, b1v);
            mma_bf16(acc[1][nt], a[1], b0, b1v);
        }
    }
    __syncthreads();

    #pragma unroll
    for (int mt = 0; mt < 2; mt++)
        #pragma unroll
        for (int nt = 0; nt < 6; nt++) {
            int row0 = wm * 32 + mt * 16 + g;
            int jj = wq * 48 + nt * 8 + 2 * tig;
            *(__nv_bfloat162*)(stg + row0 * XP + jj) =
                __floats2bfloat162_rn(acc[mt][nt][0], acc[mt][nt][1]);
            *(__nv_bfloat162*)(stg + (row0 + 8) * XP + jj) =
                __floats2bfloat162_rn(acc[mt][nt][2], acc[mt][nt][3]);
        }
    __syncthreads();

    {
        __nv_bfloat162* pb = g_B2 + ((size_t)(b * HH) * WF + wf) * CH + n * BS;
        for (int idx = tid; idx < HH * BS; idx += 512) {
            int h = idx / BS, c = idx - (idx / BS) * BS;
            pb[(size_t)h * WF * CH + c] =
                __halves2bfloat162(stg[h * XP + c], stg[h * XP + 96 + c]);
        }
    }
}

// ---------------------------------------------------------------------------
// K5: W-irfft as GEMM + residual. Per CTA: one bh row, 192 channels.
//   out(128 x 192) = G5(128 x 144) * [Zr;Zi](144 x 192) + x
// ---------------------------------------------------------------------------
#define P5 146
#define K5_SG 0                /* 128*146*2 = 37376 */
#define K5_SB 37376            /* 192*146*2 = 56064 */
#define K5_TOT 93440

__global__ void __launch_bounds__(256) k5g(const float* __restrict__ x,
                                           float* __restrict__ out)
{
    extern __shared__ char sm[];
    __nv_bfloat16* sG = (__nv_bfloat16*)(sm + K5_SG);
    __nv_bfloat16* sB = (__nv_bfloat16*)(sm + K5_SB);

    const int tid = threadIdx.x;
    const int bh = blockIdx.y;
    const int c0 = blockIdx.x * 192;
    const int lane = tid & 31, warp = tid >> 5;
    const int g = lane >> 2, tig = lane & 3;
    const int wm = warp & 3, wn = warp >> 2;

    {
        const unsigned* src = (const unsigned*)g_G5;
        unsigned* dst = (unsigned*)sG;
        for (int p = tid; p < 128 * 73; p += 256) dst[p] = src[p];
    }
    {
        unsigned* dz = (unsigned*)sB;
        for (int p = tid; p < 192 * 73; p += 256) dz[p] = 0u;
    }
    __syncthreads();
    {
        const __nv_bfloat162* pb = g_B2 + (size_t)bh * WF * CH + c0;
        for (int idx = tid; idx < 65 * 192; idx += 256) {
            int k = idx / 192, c = idx - (idx / 192) * 192;
            __nv_bfloat162 v = pb[(size_t)k * CH + c];
            sB[c * P5 + k]      = __low2bfloat16(v);
            sB[c * P5 + 72 + k] = __high2bfloat16(v);
        }
    }
    __syncthreads();

    float acc[2][12][4];
    #pragma unroll
    for (int mt = 0; mt < 2; mt++)
        #pragma unroll
        for (int nt = 0; nt < 12; nt++)
            #pragma unroll
            for (int r = 0; r < 4; r++) acc[mt][nt][r] = 0.0f;

    for (int ks = 0; ks < 9; ks++) {
        const int k0 = ks * 16;
        unsigned a[2][4];
        #pragma unroll
        for (int mt = 0; mt < 2; mt++) {
            const __nv_bfloat16* ap = sG + (wm * 32 + mt * 16 + g) * P5 + k0 + 2 * tig;
            a[mt][0] = *(const unsigned*)(ap);
            a[mt][1] = *(const unsigned*)(ap + 8 * P5);
            a[mt][2] = *(const unsigned*)(ap + 8);
            a[mt][3] = *(const unsigned*)(ap + 8 * P5 + 8);
        }
        #pragma unroll
        for (int nt = 0; nt < 12; nt++) {
            const __nv_bfloat16* bp = sB + (wn * 96 + nt * 8 + g) * P5 + k0 + 2 * tig;
            unsigned b0 = *(const unsigned*)(bp);
            unsigned b1v = *(const unsigned*)(bp + 8);
            mma_bf16(acc[0][nt], a[0], b0, b1v);
            mma_bf16(acc[1][nt], a[1], b0, b1v);
        }
    }

    {
        const float* px = x   + (size_t)bh * WW * CH + c0;
        float*       po = out + (size_t)bh * WW * CH + c0;
        #pragma unroll
        for (int mt = 0; mt < 2; mt++)
            #pragma unroll
            for (int nt = 0; nt < 12; nt++) {
                int row0 = wm * 32 + mt * 16 + g;
                int jj = wn * 96 + nt * 8 + 2 * tig;
                float2 xv0 = *(const float2*)(px + (size_t)row0 * CH + jj);
                float2 xv1 = *(const float2*)(px + (size_t)(row0 + 8) * CH + jj);
                *(float2*)(po + (size_t)row0 * CH + jj) =
                    make_float2(acc[mt][nt][0] + xv0.x, acc[mt][nt][1] + xv0.y);
                *(float2*)(po + (size_t)(row0 + 8) * CH + jj) =
                    make_float2(acc[mt][nt][2] + xv1.x, acc[mt][nt][3] + xv1.y);
            }
    }
}

// ---------------------------------------------------------------------------
extern "C" void kernel_launch(void* const* d_in, const int* in_sizes, int n_in,
                              void* d_out, int out_size)
{
    (void)in_sizes; (void)n_in; (void)out_size;
    const float* x  = (const float*)d_in[0];
    const float* w1 = (const float*)d_in[1];
    const float* b1 = (const float*)d_in[2];
    const float* w2 = (const float*)d_in[3];
    const float* b2 = (const float*)d_in[4];
    float* out = (float*)d_out;

    cudaFuncSetAttribute(k1g,  cudaFuncAttributeMaxDynamicSharedMemorySize, K1_TOT);
    cudaFuncSetAttribute(kmid, cudaFuncAttributeMaxDynamicSharedMemorySize, SM_TOT);
    cudaFuncSetAttribute(k5g,  cudaFuncAttributeMaxDynamicSharedMemorySize, K5_TOT);

    k0_build<<<32, 256>>>();
    k1g <<<dim3(CH / 192, BB * HH), 256, K1_TOT>>>(x);
    kmid<<<dim3(NB, BB * WF), 512, SM_TOT>>>(w1, b1, w2, b2);
    k5g <<<dim3(CH / 192, BB * HH), 256, K5_TOT>>>(x, out);
}

// round 9
// speedup vs baseline: 1.6111x; 1.1327x over previous
#include <cuda_runtime.h>
#include <cuda_bf16.h>

// ---------------------------------------------------------------------------
// AFNO2D: rfft2(128x128, ortho) -> blockwise complex MLP (8 blocks x 96ch,
// relu, softshrink 0.01) -> irfft2 -> + x.   All tensor-core GEMMs, ldmatrix
// fragment loads:
//   K1  W-rfft as GEMM:  Y = G1 . x          -> g_A2 (bf16x2)   [N=96/CTA]
//   KMID per (b,wf,n):   H-DFT -> MLP -> inv H-DFT, 512 threads
//   K5  W-irfft as GEMM: out = G5 . [Zr;Zi] + x                 [N=96/CTA]
// ---------------------------------------------------------------------------

#define BB 4
#define HH 128
#define WW 128
#define CH 768
#define NB 8
#define BS 96
#define WF 65
#define MPTS (BB*HH*WF)

__device__ __nv_bfloat162 g_A2[(size_t)MPTS * CH];
__device__ __nv_bfloat162 g_B2[(size_t)MPTS * CH];
__device__ __nv_bfloat16  g_G [128 * 256];
__device__ __nv_bfloat16  g_G1[128 * 128];
__device__ __nv_bfloat16  g_G5[128 * 146];

// ---------------- K0: build DFT matrices -----------------------------------
__global__ void k0_build()
{
    int tid = blockIdx.x * 256 + threadIdx.x;
    const int STR = 32 * 256;
    for (int idx = tid; idx < 128 * 256; idx += STR) {
        int hp = idx >> 8, k = idx & 255, kk = k & 127;
        int m = (hp * kk) & 127;
        float s, c; sincospif(m * (1.0f / 64.0f), &s, &c);
        g_G[idx] = __float2bfloat16_rn((k < 128) ? c : s);
    }
    for (int idx = tid; idx < 128 * 128; idx += STR) {
        int m = idx >> 7, w = idx & 127;
        float val;
        if (m < 65) {
            int a = (m * w) & 127;
            float s, c; sincospif(a * (1.0f / 64.0f), &s, &c);
            val = c;
        } else {
            int a = ((m - 64) * w) & 127;
            float s, c; sincospif(a * (1.0f / 64.0f), &s, &c);
            val = -s;
        }
        g_G1[idx] = __float2bfloat16_rn(val);
    }
    for (int idx = tid; idx < 128 * 146; idx += STR) {
        int w = idx / 146, k = idx - (idx / 146) * 146;
        float val = 0.0f;
        if (k < 65) {
            float eps = (k == 0 || k == 64) ? 1.0f : 2.0f;
            int a = (w * k) & 127;
            float s, c; sincospif(a * (1.0f / 64.0f), &s, &c);
            val = eps * c * (1.0f / 128.0f);
        } else if (k >= 72 && k < 137) {
            int kk = k - 72;
            float eps = (kk == 0 || kk == 64) ? 1.0f : 2.0f;
            int a = (w * kk) & 127;
            float s, c; sincospif(a * (1.0f / 64.0f), &s, &c);
            val = -eps * s * (1.0f / 128.0f);
        }
        g_G5[idx] = __float2bfloat16_rn(val);
    }
}

// ---------------- fragment helpers -----------------------------------------
__device__ __forceinline__ void mma_bf16(float* d, const unsigned* a, unsigned b0, unsigned b1)
{
    asm volatile(
        "mma.sync.aligned.m16n8k16.row.col.f32.bf16.bf16.f32 "
        "{%0,%1,%2,%3},{%4,%5,%6,%7},{%8,%9},{%0,%1,%2,%3};"
        : "+f"(d[0]), "+f"(d[1]), "+f"(d[2]), "+f"(d[3])
        : "r"(a[0]), "r"(a[1]), "r"(a[2]), "r"(a[3]), "r"(b0), "r"(b1));
}
__device__ __forceinline__ unsigned s2u(const void* p)
{
    unsigned r;
    asm("{ .reg .u64 t; cvta.to.shared.u64 t, %1; cvt.u32.u64 %0, t; }" : "=r"(r) : "l"(p));
    return r;
}
__device__ __forceinline__ void ldsm_x4(unsigned* r, unsigned a)
{
    asm volatile("ldmatrix.sync.aligned.m8n8.x4.shared.b16 {%0,%1,%2,%3},[%4];"
                 : "=r"(r[0]), "=r"(r[1]), "=r"(r[2]), "=r"(r[3]) : "r"(a));
}
__device__ __forceinline__ void ldsm_x2(unsigned* r, unsigned a)
{
    asm volatile("ldmatrix.sync.aligned.m8n8.x2.shared.b16 {%0,%1},[%2];"
                 : "=r"(r[0]), "=r"(r[1]) : "r"(a));
}
// A-fragment lane byte offset for pitch P (bf16 elems): rows lane&15, col-half lane>>4
#define AOFF(lane, P) ((((lane) & 15) * (P) + (((lane) >> 4) << 3)) * 2)
// B-fragment lane byte offset (x2): n-row lane&7, k-half (lane>>3)&1
#define BOFF(lane, P) (((((lane) & 15) & 7) * (P) + (((((lane) & 15) >> 3) & 1) << 3)) * 2)

// ---------------------------------------------------------------------------
// K1: W-rfft as GEMM. Per CTA: one bh row, 96 channels.
//   Y(128 x 96) = G1(128 x 128) * x^T(128 x 96)
// ---------------------------------------------------------------------------
#define P1 136                 /* 272B row: 16B-aligned, conflict-free LDSM */
#define K1_SG 0                /* 128*136*2 = 34816 */
#define K1_SB 34816            /* 96*136*2  = 26112 */
#define K1_TOT 60928
#define STG_P 98

__global__ void __launch_bounds__(256) k1g(const float* __restrict__ x)
{
    extern __shared__ char sm[];
    __nv_bfloat16* sG  = (__nv_bfloat16*)(sm + K1_SG);
    __nv_bfloat16* sB  = (__nv_bfloat16*)(sm + K1_SB);
    __nv_bfloat16* stg = (__nv_bfloat16*)(sm + K1_SG);

    const int tid = threadIdx.x;
    const int bh = blockIdx.y;
    const int c0 = blockIdx.x * 96;
    const int lane = tid & 31, warp = tid >> 5;
    const int g = lane >> 2, tig = lane & 3;
    const int wm = warp & 3, wn = warp >> 2;

    {
        const unsigned* src = (const unsigned*)g_G1;
        unsigned* dst = (unsigned*)sG;
        for (int p = tid; p < 128 * 64; p += 256) {
            int row = p >> 6, kp = p & 63;
            dst[row * 68 + kp] = src[p];
        }
    }
    {
        const float* px = x + (size_t)bh * WW * CH + c0;
        for (int idx = tid; idx < 128 * 96; idx += 256) {
            int w = idx / 96, c = idx - (idx / 96) * 96;
            sB[c * P1 + w] = __float2bfloat16_rn(px[(size_t)w * CH + c]);
        }
    }
    __syncthreads();

    const unsigned sG_u = s2u(sG), sB_u = s2u(sB);
    const unsigned abase = sG_u + (wm * 32) * P1 * 2 + AOFF(lane, P1);
    const unsigned bbase = sB_u + (wn * 48) * P1 * 2 + BOFF(lane, P1);

    float acc[2][6][4];
    #pragma unroll
    for (int mt = 0; mt < 2; mt++)
        #pragma unroll
        for (int nt = 0; nt < 6; nt++)
            #pragma unroll
            for (int r = 0; r < 4; r++) acc[mt][nt][r] = 0.0f;

    for (int ks = 0; ks < 8; ks++) {
        const int k0 = ks * 16;
        unsigned a[2][4];
        ldsm_x4(a[0], abase + k0 * 2);
        ldsm_x4(a[1], abase + (16 * P1 + k0) * 2);
        #pragma unroll
        for (int nt = 0; nt < 6; nt++) {
            unsigned bb[2];
            ldsm_x2(bb, bbase + (nt * 8 * P1 + k0) * 2);
            mma_bf16(acc[0][nt], a[0], bb[0], bb[1]);
            mma_bf16(acc[1][nt], a[1], bb[0], bb[1]);
        }
    }
    __syncthreads();

    #pragma unroll
    for (int mt = 0; mt < 2; mt++)
        #pragma unroll
        for (int nt = 0; nt < 6; nt++) {
            int row0 = wm * 32 + mt * 16 + g;
            int jj = wn * 48 + nt * 8 + 2 * tig;
            *(__nv_bfloat162*)(stg + row0 * STG_P + jj) =
                __floats2bfloat162_rn(acc[mt][nt][0], acc[mt][nt][1]);
            *(__nv_bfloat162*)(stg + (row0 + 8) * STG_P + jj) =
                __floats2bfloat162_rn(acc[mt][nt][2], acc[mt][nt][3]);
        }
    __syncthreads();

    {
        __nv_bfloat162* pa = g_A2 + (size_t)bh * WF * CH + c0;
        const __nv_bfloat16 z = __float2bfloat16_rn(0.0f);
        for (int idx = tid; idx < 65 * 96; idx += 256) {
            int k = idx / 96, c = idx - (idx / 96) * 96;
            __nv_bfloat16 re = stg[k * STG_P + c];
            __nv_bfloat16 im = (k >= 1 && k <= 63) ? stg[(64 + k) * STG_P + c] : z;
            pa[(size_t)k * CH + c] = __halves2bfloat162(re, im);
        }
    }
}

// ---------------------------------------------------------------------------
// KMID: per-(b,wf,n) fused H-DFT -> complex MLP -> inverse H-DFT.
// 512 threads, 16 warps: wm=warp&3 (M slab), wq=warp>>2 (48-col N group),
// wn=wq>>1 (re/im half), wh=wq&1.
// ---------------------------------------------------------------------------
#define GP  264
#define XT  264
#define XP  200
#define WP  104
#define SM_G   0
#define SM_X   67584
#define SM_W   118784
#define SM_WI  138752
#define SM_B1  158720
#define SM_B2  159488
#define SM_TOT 160256

__global__ void __launch_bounds__(512) kmid(const float* __restrict__ w1,
                                            const float* __restrict__ b1,
                                            const float* __restrict__ w2,
                                            const float* __restrict__ b2)
{
    extern __shared__ char sm[];
    __nv_bfloat16* sG  = (__nv_bfloat16*)(sm + SM_G);
    __nv_bfloat16* sX  = (__nv_bfloat16*)(sm + SM_X);
    __nv_bfloat16* sXm = (__nv_bfloat16*)(sm + SM_X);
    __nv_bfloat16* sOt = (__nv_bfloat16*)(sm + SM_X);
    __nv_bfloat16* sWr = (__nv_bfloat16*)(sm + SM_W);
    __nv_bfloat16* sWi = (__nv_bfloat16*)(sm + SM_WI);
    __nv_bfloat16* stg = (__nv_bfloat16*)(sm + SM_G);
    float* sB1 = (float*)(sm + SM_B1);
    float* sB2 = (float*)(sm + SM_B2);

    const int tid = threadIdx.x;
    const int n   = blockIdx.x;
    const int b   = blockIdx.y / WF;
    const int wf  = blockIdx.y - b * WF;
    const int lane = tid & 31, warp = tid >> 5;
    const int g = lane >> 2, tig = lane & 3;
    const int wm = warp & 3, wq = warp >> 2;
    const int wn = wq >> 1, wh = wq & 1;

    {
        const __nv_bfloat162* src = (const __nv_bfloat162*)g_G;
        for (int p = tid; p < 128 * 128; p += 512) {
            int hp = p >> 7, kp = p & 127;
            *(__nv_bfloat162*)(sG + hp * GP + 2 * kp) = src[p];
        }
    }
    {
        const float* wr = w1 + (size_t)n * BS * BS;
        const float* wi = w1 + (size_t)(NB + n) * BS * BS;
        for (int idx = tid; idx < BS * BS; idx += 512) {
            int i = idx / 96, o = idx - (idx / 96) * 96;
            sWr[o * WP + i] = __float2bfloat16_rn(wr[idx]);
            sWi[o * WP + i] = __float2bfloat16_rn(wi[idx]);
        }
        if (tid < 192) {
            int half = tid / 96, j = tid - half * 96;
            sB1[tid] = b1[half * (NB * BS) + n * BS + j];
            sB2[tid] = b2[half * (NB * BS) + n * BS + j];
        }
    }
    {
        const __nv_bfloat162* pa = g_A2 + ((size_t)(b * HH) * WF + wf) * CH + n * BS;
        const __nv_bfloat162 c128 = __float2bfloat162_rn(0.0078125f);
        for (int idx = tid; idx < HH * BS; idx += 512) {
            int h = idx / BS, c = idx - (idx / BS) * BS;
            __nv_bfloat162 v = __hmul2(pa[(size_t)h * WF * CH + c], c128);
            sX[c * XT + h]       = __low2bfloat16(v);
            sX[c * XT + 128 + h] = __high2bfloat16(v);
        }
    }
    __syncthreads();

    const unsigned sG_u = s2u(sG), sX_u = s2u(sX);
    const unsigned sWr_u = s2u(sWr), sWi_u = s2u(sWi);
    const unsigned abaseG = sG_u + (wm * 32) * GP * 2 + AOFF(lane, GP);
    const unsigned abaseX = sX_u + (wm * 32) * XP * 2 + AOFF(lane, XP);
    const unsigned bbaseT = sX_u + (wh * 48) * XT * 2 + BOFF(lane, XT);
    const unsigned boffW  = (wh * 48) * WP * 2 + BOFF(lane, WP);

    float acc[2][6][4];

    // =============== GEMM1: forward H-DFT ================================
    #pragma unroll
    for (int mt = 0; mt < 2; mt++)
        #pragma unroll
        for (int nt = 0; nt < 6; nt++)
            #pragma unroll
            for (int r = 0; r < 4; r++) acc[mt][nt][r] = 0.0f;

    for (int ks = 0; ks < 16; ks++) {
        const int k0 = ks * 16;
        unsigned a[2][4];
        ldsm_x4(a[0], abaseG + k0 * 2);
        ldsm_x4(a[1], abaseG + (16 * GP + k0) * 2);
        const int kk = wn ? (k0 ^ 128) : k0;
        const unsigned msk = (wn && k0 >= 128) ? 0x80008000u : 0u;
        #pragma unroll
        for (int nt = 0; nt < 6; nt++) {
            unsigned bb[2];
            ldsm_x2(bb, bbaseT + (nt * 8 * XT + kk) * 2);
            bb[0] ^= msk; bb[1] ^= msk;
            mma_bf16(acc[0][nt], a[0], bb[0], bb[1]);
            mma_bf16(acc[1][nt], a[1], bb[0], bb[1]);
        }
    }
    __syncthreads();

    #pragma unroll
    for (int mt = 0; mt < 2; mt++)
        #pragma unroll
        for (int nt = 0; nt < 6; nt++) {
            int row0 = wm * 32 + mt * 16 + g;
            int jj = wq * 48 + nt * 8 + 2 * tig;
            *(__nv_bfloat162*)(sXm + row0 * XP + jj) =
                __floats2bfloat162_rn(acc[mt][nt][0], acc[mt][nt][1]);
            *(__nv_bfloat162*)(sXm + (row0 + 8) * XP + jj) =
                __floats2bfloat162_rn(acc[mt][nt][2], acc[mt][nt][3]);
        }
    __syncthreads();

    // =============== MLP layer 1 ==========================================
    #pragma unroll
    for (int mt = 0; mt < 2; mt++)
        #pragma unroll
        for (int nt = 0; nt < 6; nt++)
            #pragma unroll
            for (int r = 0; r < 4; r++) acc[mt][nt][r] = 0.0f;

    for (int ks = 0; ks < 12; ks++) {
        const int khalf = (ks >= 6);
        const int k0 = ks * 16, kkm = k0 - khalf * 96;
        const unsigned sW_u = (wn == 0) ? (khalf ? sWi_u : sWr_u)
                                        : (khalf ? sWr_u : sWi_u);
        const unsigned amsk = ((wn == 0) && khalf) ? 0x80008000u : 0u;
        unsigned a[2][4];
        ldsm_x4(a[0], abaseX + k0 * 2);
        ldsm_x4(a[1], abaseX + (16 * XP + k0) * 2);
        if (amsk) {
            #pragma unroll
            for (int mt = 0; mt < 2; mt++)
                #pragma unroll
                for (int r = 0; r < 4; r++) a[mt][r] ^= amsk;
        }
        #pragma unroll
        for (int nt = 0; nt < 6; nt++) {
            unsigned bb[2];
            ldsm_x2(bb, sW_u + boffW + (nt * 8 * WP + kkm) * 2);
            mma_bf16(acc[0][nt], a[0], bb[0], bb[1]);
            mma_bf16(acc[1][nt], a[1], bb[0], bb[1]);
        }
    }
    __syncthreads();

    #pragma unroll
    for (int mt = 0; mt < 2; mt++)
        #pragma unroll
        for (int nt = 0; nt < 6; nt++) {
            int row0 = wm * 32 + mt * 16 + g;
            int jj = wq * 48 + nt * 8 + 2 * tig;
            float bb0 = sB1[jj], bb1 = sB1[jj + 1];
            *(__nv_bfloat162*)(sXm + row0 * XP + jj) = __floats2bfloat162_rn(
                fmaxf(acc[mt][nt][0] + bb0, 0.0f), fmaxf(acc[mt][nt][1] + bb1, 0.0f));
            *(__nv_bfloat162*)(sXm + (row0 + 8) * XP + jj) = __floats2bfloat162_rn(
                fmaxf(acc[mt][nt][2] + bb0, 0.0f), fmaxf(acc[mt][nt][3] + bb1, 0.0f));
        }
    {
        const float* wr = w2 + (size_t)n * BS * BS;
        const float* wi = w2 + (size_t)(NB + n) * BS * BS;
        for (int idx = tid; idx < BS * BS; idx += 512) {
            int i = idx / 96, o = idx - (idx / 96) * 96;
            sWr[o * WP + i] = __float2bfloat16_rn(wr[idx]);
            sWi[o * WP + i] = __float2bfloat16_rn(wi[idx]);
        }
    }
    __syncthreads();

    // =============== MLP layer 2 ==========================================
    #pragma unroll
    for (int mt = 0; mt < 2; mt++)
        #pragma unroll
        for (int nt = 0; nt < 6; nt++)
            #pragma unroll
            for (int r = 0; r < 4; r++) acc[mt][nt][r] = 0.0f;

    for (int ks = 0; ks < 12; ks++) {
        const int khalf = (ks >= 6);
        const int k0 = ks * 16, kkm = k0 - khalf * 96;
        const unsigned sW_u = (wn == 0) ? (khalf ? sWi_u : sWr_u)
                                        : (khalf ? sWr_u : sWi_u);
        const unsigned amsk = ((wn == 0) && khalf) ? 0x80008000u : 0u;
        unsigned a[2][4];
        ldsm_x4(a[0], abaseX + k0 * 2);
        ldsm_x4(a[1], abaseX + (16 * XP + k0) * 2);
        if (amsk) {
            #pragma unroll
            for (int mt = 0; mt < 2; mt++)
                #pragma unroll
                for (int r = 0; r < 4; r++) a[mt][r] ^= amsk;
        }
        #pragma unroll
        for (int nt = 0; nt < 6; nt++) {
            unsigned bb[2];
            ldsm_x2(bb, sW_u + boffW + (nt * 8 * WP + kkm) * 2);
            mma_bf16(acc[0][nt], a[0], bb[0], bb[1]);
            mma_bf16(acc[1][nt], a[1], bb[0], bb[1]);
        }
    }
    __syncthreads();

    // softshrink -> sOt (transposed)
    {
        const float lam = 0.01f;
        #pragma unroll
        for (int mt = 0; mt < 2; mt++)
            #pragma unroll
            for (int nt = 0; nt < 6; nt++) {
                int row0 = wm * 32 + mt * 16 + g;
                int c = wh * 48 + nt * 8 + 2 * tig;
                int jj = wn * 96 + c;
                float bb0 = sB2[jj], bb1 = sB2[jj + 1];
                #pragma unroll
                for (int r = 0; r < 4; r++) {
                    float v = acc[mt][nt][r] + ((r & 1) ? bb1 : bb0);
                    v = copysignf(fmaxf(fabsf(v) - lam, 0.0f), v);
                    int cc = c + (r & 1);
                    int kb = wn * 128 + row0 + (r >> 1) * 8;
                    sOt[cc * XT + kb] = __float2bfloat16_rn(v);
                }
            }
    }
    __syncthreads();

    // =============== GEMM2: inverse H-DFT =================================
    #pragma unroll
    for (int mt = 0; mt < 2; mt++)
        #pragma unroll
        for (int nt = 0; nt < 6; nt++)
            #pragma unroll
            for (int r = 0; r < 4; r++) acc[mt][nt][r] = 0.0f;

    for (int ks = 0; ks < 16; ks++) {
        const int k0 = ks * 16;
        unsigned a[2][4];
        ldsm_x4(a[0], abaseG + k0 * 2);
        ldsm_x4(a[1], abaseG + (16 * GP + k0) * 2);
        const int kk = wn ? (k0 ^ 128) : k0;
        const unsigned msk = (!wn && k0 >= 128) ? 0x80008000u : 0u;
        #pragma unroll
        for (int nt = 0; nt < 6; nt++) {
            unsigned bb[2];
            ldsm_x2(bb, bbaseT + (nt * 8 * XT + kk) * 2);
            bb[0] ^= msk; bb[1] ^= msk;
            mma_bf16(acc[0][nt], a[0], bb[0], bb[1]);
            mma_bf16(acc[1][nt], a[1], bb[0], bb[1]);
        }
    }
    __syncthreads();

    #pragma unroll
    for (int mt = 0; mt < 2; mt++)
        #pragma unroll
        for (int nt = 0; nt < 6; nt++) {
            int row0 = wm * 32 + mt * 16 + g;
            int jj = wq * 48 + nt * 8 + 2 * tig;
            *(__nv_bfloat162*)(stg + row0 * XP + jj) =
                __floats2bfloat162_rn(acc[mt][nt][0], acc[mt][nt][1]);
            *(__nv_bfloat162*)(stg + (row0 + 8) * XP + jj) =
                __floats2bfloat162_rn(acc[mt][nt][2], acc[mt][nt][3]);
        }
    __syncthreads();

    {
        __nv_bfloat162* pb = g_B2 + ((size_t)(b * HH) * WF + wf) * CH + n * BS;
        for (int idx = tid; idx < HH * BS; idx += 512) {
            int h = idx / BS, c = idx - (idx / BS) * BS;
            pb[(size_t)h * WF * CH + c] =
                __halves2bfloat162(stg[h * XP + c], stg[h * XP + 96 + c]);
        }
    }
}

// ---------------------------------------------------------------------------
// K5: W-irfft as GEMM + residual. Per CTA: one bh row, 96 channels.
//   out(128 x 96) = G5(128 x 144) * [Zr;Zi](144 x 96) + x
// ---------------------------------------------------------------------------
#define P5 152                 /* 304B row: 16B-aligned, conflict-free LDSM */
#define K5_SG 0                /* 128*152*2 = 38912 */
#define K5_SB 38912            /* 96*152*2  = 29184 */
#define K5_TOT 68096

__global__ void __launch_bounds__(256) k5g(const float* __restrict__ x,
                                           float* __restrict__ out)
{
    extern __shared__ char sm[];
    __nv_bfloat16* sG = (__nv_bfloat16*)(sm + K5_SG);
    __nv_bfloat16* sB = (__nv_bfloat16*)(sm + K5_SB);

    const int tid = threadIdx.x;
    const int bh = blockIdx.y;
    const int c0 = blockIdx.x * 96;
    const int lane = tid & 31, warp = tid >> 5;
    const int g = lane >> 2, tig = lane & 3;
    const int wm = warp & 3, wn = warp >> 2;

    {
        const unsigned* src = (const unsigned*)g_G5;
        unsigned* dst = (unsigned*)sG;
        for (int p = tid; p < 128 * 73; p += 256) {
            int row = p / 73, c = p - row * 73;
            dst[row * 76 + c] = src[p];
        }
    }
    {
        unsigned* dz = (unsigned*)sB;
        for (int p = tid; p < 96 * 76; p += 256) dz[p] = 0u;
    }
    __syncthreads();
    {
        const __nv_bfloat162* pb = g_B2 + (size_t)bh * WF * CH + c0;
        for (int idx = tid; idx < 65 * 96; idx += 256) {
            int k = idx / 96, c = idx - (idx / 96) * 96;
            __nv_bfloat162 v = pb[(size_t)k * CH + c];
            sB[c * P5 + k]      = __low2bfloat16(v);
            sB[c * P5 + 72 + k] = __high2bfloat16(v);
        }
    }
    __syncthreads();

    const unsigned sG_u = s2u(sG), sB_u = s2u(sB);
    const unsigned abase = sG_u + (wm * 32) * P5 * 2 + AOFF(lane, P5);
    const unsigned bbase = sB_u + (wn * 48) * P5 * 2 + BOFF(lane, P5);

    float acc[2][6][4];
    #pragma unroll
    for (int mt = 0; mt < 2; mt++)
        #pragma unroll
        for (int nt = 0; nt < 6; nt++)
            #pragma unroll
            for (int r = 0; r < 4; r++) acc[mt][nt][r] = 0.0f;

    for (int ks = 0; ks < 9; ks++) {
        const int k0 = ks * 16;
        unsigned a[2][4];
        ldsm_x4(a[0], abase + k0 * 2);
        ldsm_x4(a[1], abase + (16 * P5 + k0) * 2);
        #pragma unroll
        for (int nt = 0; nt < 6; nt++) {
            unsigned bb[2];
            ldsm_x2(bb, bbase + (nt * 8 * P5 + k0) * 2);
            mma_bf16(acc[0][nt], a[0], bb[0], bb[1]);
            mma_bf16(acc[1][nt], a[1], bb[0], bb[1]);
        }
    }

    {
        const float* px = x   + (size_t)bh * WW * CH + c0;
        float*       po = out + (size_t)bh * WW * CH + c0;
        #pragma unroll
        for (int mt = 0; mt < 2; mt++)
            #pragma unroll
            for (int nt = 0; nt < 6; nt++) {
                int row0 = wm * 32 + mt * 16 + g;
                int jj = wn * 48 + nt * 8 + 2 * tig;
                float2 xv0 = *(const float2*)(px + (size_t)row0 * CH + jj);
                float2 xv1 = *(const float2*)(px + (size_t)(row0 + 8) * CH + jj);
                *(float2*)(po + (size_t)row0 * CH + jj) =
                    make_float2(acc[mt][nt][0] + xv0.x, acc[mt][nt][1] + xv0.y);
                *(float2*)(po + (size_t)(row0 + 8) * CH + jj) =
                    make_float2(acc[mt][nt][2] + xv1.x, acc[mt][nt][3] + xv1.y);
            }
    }
}

// ---------------------------------------------------------------------------
extern "C" void kernel_launch(void* const* d_in, const int* in_sizes, int n_in,
                              void* d_out, int out_size)
{
    (void)in_sizes; (void)n_in; (void)out_size;
    const float* x  = (const float*)d_in[0];
    const float* w1 = (const float*)d_in[1];
    const float* b1 = (const float*)d_in[2];
    const float* w2 = (const float*)d_in[3];
    const float* b2 = (const float*)d_in[4];
    float* out = (float*)d_out;

    cudaFuncSetAttribute(k1g,  cudaFuncAttributeMaxDynamicSharedMemorySize, K1_TOT);
    cudaFuncSetAttribute(kmid, cudaFuncAttributeMaxDynamicSharedMemorySize, SM_TOT);
    cudaFuncSetAttribute(k5g,  cudaFuncAttributeMaxDynamicSharedMemorySize, K5_TOT);

    k0_build<<<32, 256>>>();
    k1g <<<dim3(CH / 96, BB * HH), 256, K1_TOT>>>(x);
    kmid<<<dim3(NB, BB * WF), 512, SM_TOT>>>(w1, b1, w2, b2);
    k5g <<<dim3(CH / 96, BB * HH), 256, K5_TOT>>>(x, out);
}

// round 10
// speedup vs baseline: 1.7544x; 1.0889x over previous
#include <cuda_runtime.h>
#include <cuda_bf16.h>

// ---------------------------------------------------------------------------
// AFNO2D: rfft2(128x128, ortho) -> blockwise complex MLP (8 blocks x 96ch,
// relu, softshrink 0.01) -> irfft2 -> + x.   All tensor-core GEMMs.
//   K1  W-rfft GEMM:  Y = G1 . x  -> g_A2      [B natural layout + ldsm.trans]
//   KMID per (b,wf,n): H-DFT -> MLP -> inv H-DFT, 512 threads
//   K5  W-irfft GEMM: out = G5 . [Zr;Zi] + x   [B natural layout + ldsm.trans]
// k1g/k5g loop over 2 bh tiles per CTA to amortize G loads.
// ---------------------------------------------------------------------------

#define BB 4
#define HH 128
#define WW 128
#define CH 768
#define NB 8
#define BS 96
#define WF 65
#define MPTS (BB*HH*WF)

__device__ __nv_bfloat162 g_A2[(size_t)MPTS * CH];
__device__ __nv_bfloat162 g_B2[(size_t)MPTS * CH];
__device__ __nv_bfloat16  g_G [128 * 256];
__device__ __nv_bfloat16  g_G1[128 * 128];
__device__ __nv_bfloat16  g_G5[128 * 146];

// ---------------- K0: build DFT matrices -----------------------------------
__global__ void k0_build()
{
    int tid = blockIdx.x * 256 + threadIdx.x;
    const int STR = 32 * 256;
    for (int idx = tid; idx < 128 * 256; idx += STR) {
        int hp = idx >> 8, k = idx & 255, kk = k & 127;
        int m = (hp * kk) & 127;
        float s, c; sincospif(m * (1.0f / 64.0f), &s, &c);
        g_G[idx] = __float2bfloat16_rn((k < 128) ? c : s);
    }
    for (int idx = tid; idx < 128 * 128; idx += STR) {
        int m = idx >> 7, w = idx & 127;
        float val;
        if (m < 65) {
            int a = (m * w) & 127;
            float s, c; sincospif(a * (1.0f / 64.0f), &s, &c);
            val = c;
        } else {
            int a = ((m - 64) * w) & 127;
            float s, c; sincospif(a * (1.0f / 64.0f), &s, &c);
            val = -s;
        }
        g_G1[idx] = __float2bfloat16_rn(val);
    }
    for (int idx = tid; idx < 128 * 146; idx += STR) {
        int w = idx / 146, k = idx - (idx / 146) * 146;
        float val = 0.0f;
        if (k < 65) {
            float eps = (k == 0 || k == 64) ? 1.0f : 2.0f;
            int a = (w * k) & 127;
            float s, c; sincospif(a * (1.0f / 64.0f), &s, &c);
            val = eps * c * (1.0f / 128.0f);
        } else if (k >= 72 && k < 137) {
            int kk = k - 72;
            float eps = (kk == 0 || kk == 64) ? 1.0f : 2.0f;
            int a = (w * kk) & 127;
            float s, c; sincospif(a * (1.0f / 64.0f), &s, &c);
            val = -eps * s * (1.0f / 128.0f);
        }
        g_G5[idx] = __float2bfloat16_rn(val);
    }
}

// ---------------- fragment helpers -----------------------------------------
__device__ __forceinline__ void mma_bf16(float* d, const unsigned* a, unsigned b0, unsigned b1)
{
    asm volatile(
        "mma.sync.aligned.m16n8k16.row.col.f32.bf16.bf16.f32 "
        "{%0,%1,%2,%3},{%4,%5,%6,%7},{%8,%9},{%0,%1,%2,%3};"
        : "+f"(d[0]), "+f"(d[1]), "+f"(d[2]), "+f"(d[3])
        : "r"(a[0]), "r"(a[1]), "r"(a[2]), "r"(a[3]), "r"(b0), "r"(b1));
}
__device__ __forceinline__ unsigned s2u(const void* p)
{
    unsigned r;
    asm("{ .reg .u64 t; cvta.to.shared.u64 t, %1; cvt.u32.u64 %0, t; }" : "=r"(r) : "l"(p));
    return r;
}
__device__ __forceinline__ void ldsm_x4(unsigned* r, unsigned a)
{
    asm volatile("ldmatrix.sync.aligned.m8n8.x4.shared.b16 {%0,%1,%2,%3},[%4];"
                 : "=r"(r[0]), "=r"(r[1]), "=r"(r[2]), "=r"(r[3]) : "r"(a));
}
__device__ __forceinline__ void ldsm_x2(unsigned* r, unsigned a)
{
    asm volatile("ldmatrix.sync.aligned.m8n8.x2.shared.b16 {%0,%1},[%2];"
                 : "=r"(r[0]), "=r"(r[1]) : "r"(a));
}
__device__ __forceinline__ void ldsm_x2t(unsigned* r, unsigned a)
{
    asm volatile("ldmatrix.sync.aligned.m8n8.x2.trans.shared.b16 {%0,%1},[%2];"
                 : "=r"(r[0]), "=r"(r[1]) : "r"(a));
}
// A-fragment lane byte offset for pitch P (bf16 elems)
#define AOFF(lane, P) ((((lane) & 15) * (P) + (((lane) >> 4) << 3)) * 2)
// B-fragment (x2, non-trans, [n][k] layout)
#define BOFF(lane, P) (((((lane) & 15) & 7) * (P) + (((((lane) & 15) >> 3) & 1) << 3)) * 2)
// B-fragment (x2 TRANS, [k][n] layout): lane -> k-row (lane&15)
#define BTOFF(lane, P) (((lane) & 15) * (P) * 2)

// ---------------------------------------------------------------------------
// K1: W-rfft as GEMM. Per CTA: 2 bh rows (looped), 96 channels.
//   Y(128 x 96) = G1(128 x 128) * x^T(128 x 96)
// sB natural [w][c] layout, ldsm.trans for B fragments.
// ---------------------------------------------------------------------------
#define P1 136                 /* sG pitch: 272B rows, LDSM conflict-free */
#define PB1 104                /* sB pitch: 208B rows = 13 quads, cf trans  */
#define K1_SG 0                /* 128*136*2 = 34816 */
#define K1_SB 34816            /* 128*104*2 = 26624 */
#define K1_TOT 61440
#define STG_P 98               /* stg aliases sB: 128*98*2 = 25088 <= 26624 */

__global__ void __launch_bounds__(256) k1g(const float* __restrict__ x)
{
    extern __shared__ char sm[];
    __nv_bfloat16* sG  = (__nv_bfloat16*)(sm + K1_SG);
    __nv_bfloat16* sB  = (__nv_bfloat16*)(sm + K1_SB);
    __nv_bfloat16* stg = (__nv_bfloat16*)(sm + K1_SB);   // aliases sB

    const int tid = threadIdx.x;
    const int c0 = blockIdx.x * 96;
    const int lane = tid & 31, warp = tid >> 5;
    const int g = lane >> 2, tig = lane & 3;
    const int wm = warp & 3, wn = warp >> 2;

    {
        const unsigned* src = (const unsigned*)g_G1;
        unsigned* dst = (unsigned*)sG;
        for (int p = tid; p < 128 * 64; p += 256) {
            int row = p >> 6, kp = p & 63;
            dst[row * 68 + kp] = src[p];
        }
    }

    const unsigned sG_u = s2u(sG), sB_u = s2u(sB);
    const unsigned abase  = sG_u + (wm * 32) * P1 * 2 + AOFF(lane, P1);
    const unsigned btbase = sB_u + BTOFF(lane, PB1) + (wn * 48) * 2;

    for (int t = 0; t < 2; t++) {
        const int bh = blockIdx.y * 2 + t;
        __syncthreads();   // sG ready / previous stg reads done

        // ingest x natural layout [w][c], bf16x2 vectorized
        {
            const float* px = x + (size_t)bh * WW * CH + c0;
            for (int idx = tid; idx < 128 * 48; idx += 256) {
                int w = idx / 48, c2 = idx - (idx / 48) * 48;
                float2 v = *(const float2*)(px + (size_t)w * CH + 2 * c2);
                *(__nv_bfloat162*)(sB + w * PB1 + 2 * c2) = __floats2bfloat162_rn(v.x, v.y);
            }
        }
        __syncthreads();

        float acc[2][6][4];
        #pragma unroll
        for (int mt = 0; mt < 2; mt++)
            #pragma unroll
            for (int nt = 0; nt < 6; nt++)
                #pragma unroll
                for (int r = 0; r < 4; r++) acc[mt][nt][r] = 0.0f;

        for (int ks = 0; ks < 8; ks++) {
            const int k0 = ks * 16;
            unsigned a[2][4];
            ldsm_x4(a[0], abase + k0 * 2);
            ldsm_x4(a[1], abase + (16 * P1 + k0) * 2);
            #pragma unroll
            for (int nt = 0; nt < 6; nt++) {
                unsigned bb[2];
                ldsm_x2t(bb, btbase + (k0 * PB1 + nt * 8) * 2);
                mma_bf16(acc[0][nt], a[0], bb[0], bb[1]);
                mma_bf16(acc[1][nt], a[1], bb[0], bb[1]);
            }
        }
        __syncthreads();   // all sB reads done -> stg may overwrite

        #pragma unroll
        for (int mt = 0; mt < 2; mt++)
            #pragma unroll
            for (int nt = 0; nt < 6; nt++) {
                int row0 = wm * 32 + mt * 16 + g;
                int jj = wn * 48 + nt * 8 + 2 * tig;
                *(__nv_bfloat162*)(stg + row0 * STG_P + jj) =
                    __floats2bfloat162_rn(acc[mt][nt][0], acc[mt][nt][1]);
                *(__nv_bfloat162*)(stg + (row0 + 8) * STG_P + jj) =
                    __floats2bfloat162_rn(acc[mt][nt][2], acc[mt][nt][3]);
            }
        __syncthreads();

        {
            __nv_bfloat162* pa = g_A2 + (size_t)bh * WF * CH + c0;
            const __nv_bfloat16 z = __float2bfloat16_rn(0.0f);
            for (int idx = tid; idx < 65 * 96; idx += 256) {
                int k = idx / 96, c = idx - (idx / 96) * 96;
                __nv_bfloat16 re = stg[k * STG_P + c];
                __nv_bfloat16 im = (k >= 1 && k <= 63) ? stg[(64 + k) * STG_P + c] : z;
                pa[(size_t)k * CH + c] = __halves2bfloat162(re, im);
            }
        }
    }
}

// ---------------------------------------------------------------------------
// KMID: per-(b,wf,n) fused H-DFT -> complex MLP -> inverse H-DFT. (unchanged)
// ---------------------------------------------------------------------------
#define GP  264
#define XT  264
#define XP  200
#define WP  104
#define SM_G   0
#define SM_X   67584
#define SM_W   118784
#define SM_WI  138752
#define SM_B1  158720
#define SM_B2  159488
#define SM_TOT 160256

__global__ void __launch_bounds__(512) kmid(const float* __restrict__ w1,
                                            const float* __restrict__ b1,
                                            const float* __restrict__ w2,
                                            const float* __restrict__ b2)
{
    extern __shared__ char sm[];
    __nv_bfloat16* sG  = (__nv_bfloat16*)(sm + SM_G);
    __nv_bfloat16* sX  = (__nv_bfloat16*)(sm + SM_X);
    __nv_bfloat16* sXm = (__nv_bfloat16*)(sm + SM_X);
    __nv_bfloat16* sOt = (__nv_bfloat16*)(sm + SM_X);
    __nv_bfloat16* sWr = (__nv_bfloat16*)(sm + SM_W);
    __nv_bfloat16* sWi = (__nv_bfloat16*)(sm + SM_WI);
    __nv_bfloat16* stg = (__nv_bfloat16*)(sm + SM_G);
    float* sB1 = (float*)(sm + SM_B1);
    float* sB2 = (float*)(sm + SM_B2);

    const int tid = threadIdx.x;
    const int n   = blockIdx.x;
    const int b   = blockIdx.y / WF;
    const int wf  = blockIdx.y - b * WF;
    const int lane = tid & 31, warp = tid >> 5;
    const int g = lane >> 2, tig = lane & 3;
    const int wm = warp & 3, wq = warp >> 2;
    const int wn = wq >> 1, wh = wq & 1;

    {
        const __nv_bfloat162* src = (const __nv_bfloat162*)g_G;
        for (int p = tid; p < 128 * 128; p += 512) {
            int hp = p >> 7, kp = p & 127;
            *(__nv_bfloat162*)(sG + hp * GP + 2 * kp) = src[p];
        }
    }
    {
        const float* wr = w1 + (size_t)n * BS * BS;
        const float* wi = w1 + (size_t)(NB + n) * BS * BS;
        for (int idx = tid; idx < BS * BS; idx += 512) {
            int i = idx / 96, o = idx - (idx / 96) * 96;
            sWr[o * WP + i] = __float2bfloat16_rn(wr[idx]);
            sWi[o * WP + i] = __float2bfloat16_rn(wi[idx]);
        }
        if (tid < 192) {
            int half = tid / 96, j = tid - half * 96;
            sB1[tid] = b1[half * (NB * BS) + n * BS + j];
            sB2[tid] = b2[half * (NB * BS) + n * BS + j];
        }
    }
    {
        const __nv_bfloat162* pa = g_A2 + ((size_t)(b * HH) * WF + wf) * CH + n * BS;
        const __nv_bfloat162 c128 = __float2bfloat162_rn(0.0078125f);
        for (int idx = tid; idx < HH * BS; idx += 512) {
            int h = idx / BS, c = idx - (idx / BS) * BS;
            __nv_bfloat162 v = __hmul2(pa[(size_t)h * WF * CH + c], c128);
            sX[c * XT + h]       = __low2bfloat16(v);
            sX[c * XT + 128 + h] = __high2bfloat16(v);
        }
    }
    __syncthreads();

    const unsigned sG_u = s2u(sG), sX_u = s2u(sX);
    const unsigned sWr_u = s2u(sWr), sWi_u = s2u(sWi);
    const unsigned abaseG = sG_u + (wm * 32) * GP * 2 + AOFF(lane, GP);
    const unsigned abaseX = sX_u + (wm * 32) * XP * 2 + AOFF(lane, XP);
    const unsigned bbaseT = sX_u + (wh * 48) * XT * 2 + BOFF(lane, XT);
    const unsigned boffW  = (wh * 48) * WP * 2 + BOFF(lane, WP);

    float acc[2][6][4];

    // =============== GEMM1: forward H-DFT ================================
    #pragma unroll
    for (int mt = 0; mt < 2; mt++)
        #pragma unroll
        for (int nt = 0; nt < 6; nt++)
            #pragma unroll
            for (int r = 0; r < 4; r++) acc[mt][nt][r] = 0.0f;

    for (int ks = 0; ks < 16; ks++) {
        const int k0 = ks * 16;
        unsigned a[2][4];
        ldsm_x4(a[0], abaseG + k0 * 2);
        ldsm_x4(a[1], abaseG + (16 * GP + k0) * 2);
        const int kk = wn ? (k0 ^ 128) : k0;
        const unsigned msk = (wn && k0 >= 128) ? 0x80008000u : 0u;
        #pragma unroll
        for (int nt = 0; nt < 6; nt++) {
            unsigned bb[2];
            ldsm_x2(bb, bbaseT + (nt * 8 * XT + kk) * 2);
            bb[0] ^= msk; bb[1] ^= msk;
            mma_bf16(acc[0][nt], a[0], bb[0], bb[1]);
            mma_bf16(acc[1][nt], a[1], bb[0], bb[1]);
        }
    }
    __syncthreads();

    #pragma unroll
    for (int mt = 0; mt < 2; mt++)
        #pragma unroll
        for (int nt = 0; nt < 6; nt++) {
            int row0 = wm * 32 + mt * 16 + g;
            int jj = wq * 48 + nt * 8 + 2 * tig;
            *(__nv_bfloat162*)(sXm + row0 * XP + jj) =
                __floats2bfloat162_rn(acc[mt][nt][0], acc[mt][nt][1]);
            *(__nv_bfloat162*)(sXm + (row0 + 8) * XP + jj) =
                __floats2bfloat162_rn(acc[mt][nt][2], acc[mt][nt][3]);
        }
    __syncthreads();

    // =============== MLP layer 1 ==========================================
    #pragma unroll
    for (int mt = 0; mt < 2; mt++)
        #pragma unroll
        for (int nt = 0; nt < 6; nt++)
            #pragma unroll
            for (int r = 0; r < 4; r++) acc[mt][nt][r] = 0.0f;

    for (int ks = 0; ks < 12; ks++) {
        const int khalf = (ks >= 6);
        const int k0 = ks * 16, kkm = k0 - khalf * 96;
        const unsigned sW_u = (wn == 0) ? (khalf ? sWi_u : sWr_u)
                                        : (khalf ? sWr_u : sWi_u);
        const unsigned amsk = ((wn == 0) && khalf) ? 0x80008000u : 0u;
        unsigned a[2][4];
        ldsm_x4(a[0], abaseX + k0 * 2);
        ldsm_x4(a[1], abaseX + (16 * XP + k0) * 2);
        if (amsk) {
            #pragma unroll
            for (int mt = 0; mt < 2; mt++)
                #pragma unroll
                for (int r = 0; r < 4; r++) a[mt][r] ^= amsk;
        }
        #pragma unroll
        for (int nt = 0; nt < 6; nt++) {
            unsigned bb[2];
            ldsm_x2(bb, sW_u + boffW + (nt * 8 * WP + kkm) * 2);
            mma_bf16(acc[0][nt], a[0], bb[0], bb[1]);
            mma_bf16(acc[1][nt], a[1], bb[0], bb[1]);
        }
    }
    __syncthreads();

    #pragma unroll
    for (int mt = 0; mt < 2; mt++)
        #pragma unroll
        for (int nt = 0; nt < 6; nt++) {
            int row0 = wm * 32 + mt * 16 + g;
            int jj = wq * 48 + nt * 8 + 2 * tig;
            float bb0 = sB1[jj], bb1 = sB1[jj + 1];
            *(__nv_bfloat162*)(sXm + row0 * XP + jj) = __floats2bfloat162_rn(
                fmaxf(acc[mt][nt][0] + bb0, 0.0f), fmaxf(acc[mt][nt][1] + bb1, 0.0f));
            *(__nv_bfloat162*)(sXm + (row0 + 8) * XP + jj) = __floats2bfloat162_rn(
                fmaxf(acc[mt][nt][2] + bb0, 0.0f), fmaxf(acc[mt][nt][3] + bb1, 0.0f));
        }
    {
        const float* wr = w2 + (size_t)n * BS * BS;
        const float* wi = w2 + (size_t)(NB + n) * BS * BS;
        for (int idx = tid; idx < BS * BS; idx += 512) {
            int i = idx / 96, o = idx - (idx / 96) * 96;
            sWr[o * WP + i] = __float2bfloat16_rn(wr[idx]);
            sWi[o * WP + i] = __float2bfloat16_rn(wi[idx]);
        }
    }
    __syncthreads();

    // =============== MLP layer 2 ==========================================
    #pragma unroll
    for (int mt = 0; mt < 2; mt++)
        #pragma unroll
        for (int nt = 0; nt < 6; nt++)
            #pragma unroll
            for (int r = 0; r < 4; r++) acc[mt][nt][r] = 0.0f;

    for (int ks = 0; ks < 12; ks++) {
        const int khalf = (ks >= 6);
        const int k0 = ks * 16, kkm = k0 - khalf * 96;
        const unsigned sW_u = (wn == 0) ? (khalf ? sWi_u : sWr_u)
                                        : (khalf ? sWr_u : sWi_u);
        const unsigned amsk = ((wn == 0) && khalf) ? 0x80008000u : 0u;
        unsigned a[2][4];
        ldsm_x4(a[0], abaseX + k0 * 2);
        ldsm_x4(a[1], abaseX + (16 * XP + k0) * 2);
        if (amsk) {
            #pragma unroll
            for (int mt = 0; mt < 2; mt++)
                #pragma unroll
                for (int r = 0; r < 4; r++) a[mt][r] ^= amsk;
        }
        #pragma unroll
        for (int nt = 0; nt < 6; nt++) {
            unsigned bb[2];
            ldsm_x2(bb, sW_u + boffW + (nt * 8 * WP + kkm) * 2);
            mma_bf16(acc[0][nt], a[0], bb[0], bb[1]);
            mma_bf16(acc[1][nt], a[1], bb[0], bb[1]);
        }
    }
    __syncthreads();

    // softshrink -> sOt (transposed)
    {
        const float lam = 0.01f;
        #pragma unroll
        for (int mt = 0; mt < 2; mt++)
            #pragma unroll
            for (int nt = 0; nt < 6; nt++) {
                int row0 = wm * 32 + mt * 16 + g;
                int c = wh * 48 + nt * 8 + 2 * tig;
                int jj = wn * 96 + c;
                float bb0 = sB2[jj], bb1 = sB2[jj + 1];
                #pragma unroll
                for (int r = 0; r < 4; r++) {
                    float v = acc[mt][nt][r] + ((r & 1) ? bb1 : bb0);
                    v = copysignf(fmaxf(fabsf(v) - lam, 0.0f), v);
                    int cc = c + (r & 1);
                    int kb = wn * 128 + row0 + (r >> 1) * 8;
                    sOt[cc * XT + kb] = __float2bfloat16_rn(v);
                }
            }
    }
    __syncthreads();

    // =============== GEMM2: inverse H-DFT =================================
    #pragma unroll
    for (int mt = 0; mt < 2; mt++)
        #pragma unroll
        for (int nt = 0; nt < 6; nt++)
            #pragma unroll
            for (int r = 0; r < 4; r++) acc[mt][nt][r] = 0.0f;

    for (int ks = 0; ks < 16; ks++) {
        const int k0 = ks * 16;
        unsigned a[2][4];
        ldsm_x4(a[0], abaseG + k0 * 2);
        ldsm_x4(a[1], abaseG + (16 * GP + k0) * 2);
        const int kk = wn ? (k0 ^ 128) : k0;
        const unsigned msk = (!wn && k0 >= 128) ? 0x80008000u : 0u;
        #pragma unroll
        for (int nt = 0; nt < 6; nt++) {
            unsigned bb[2];
            ldsm_x2(bb, bbaseT + (nt * 8 * XT + kk) * 2);
            bb[0] ^= msk; bb[1] ^= msk;
            mma_bf16(acc[0][nt], a[0], bb[0], bb[1]);
            mma_bf16(acc[1][nt], a[1], bb[0], bb[1]);
        }
    }
    __syncthreads();

    #pragma unroll
    for (int mt = 0; mt < 2; mt++)
        #pragma unroll
        for (int nt = 0; nt < 6; nt++) {
            int row0 = wm * 32 + mt * 16 + g;
            int jj = wq * 48 + nt * 8 + 2 * tig;
            *(__nv_bfloat162*)(stg + row0 * XP + jj) =
                __floats2bfloat162_rn(acc[mt][nt][0], acc[mt][nt][1]);
            *(__nv_bfloat162*)(stg + (row0 + 8) * XP + jj) =
                __floats2bfloat162_rn(acc[mt][nt][2], acc[mt][nt][3]);
        }
    __syncthreads();

    {
        __nv_bfloat162* pb = g_B2 + ((size_t)(b * HH) * WF + wf) * CH + n * BS;
        for (int idx = tid; idx < HH * BS; idx += 512) {
            int h = idx / BS, c = idx - (idx / BS) * BS;
            pb[(size_t)h * WF * CH + c] =
                __halves2bfloat162(stg[h * XP + c], stg[h * XP + 96 + c]);
        }
    }
}

// ---------------------------------------------------------------------------
// K5: W-irfft as GEMM + residual. Per CTA: 2 bh rows (looped), 96 channels.
//   out(128 x 96) = G5(128 x 144) * [Zr;Zi](144 x 96) + x
// sB natural [k][c] layout (Zr rows 0..64, Zi rows 72..136, pads zero),
// ldsm.trans for B fragments.
// ---------------------------------------------------------------------------
#define P5 152                 /* sG pitch: 304B rows, LDSM cf */
#define PB5 104                /* sB pitch: 208B rows, cf trans */
#define K5_SG 0                /* 128*152*2 = 38912 */
#define K5_SB 38912            /* 144*104*2 = 29952 */
#define K5_TOT 68864

__global__ void __launch_bounds__(256) k5g(const float* __restrict__ x,
                                           float* __restrict__ out)
{
    extern __shared__ char sm[];
    __nv_bfloat16* sG = (__nv_bfloat16*)(sm + K5_SG);
    __nv_bfloat16* sB = (__nv_bfloat16*)(sm + K5_SB);

    const int tid = threadIdx.x;
    const int c0 = blockIdx.x * 96;
    const int lane = tid & 31, warp = tid >> 5;
    const int g = lane >> 2, tig = lane & 3;
    const int wm = warp & 3, wn = warp >> 2;

    {
        const unsigned* src = (const unsigned*)g_G5;
        unsigned* dst = (unsigned*)sG;
        for (int p = tid; p < 128 * 73; p += 256) {
            int row = p / 73, c = p - row * 73;
            dst[row * 76 + c] = src[p];
        }
    }
    {   // zero entire sB once (pad rows 65..71 / 137..143 stay zero)
        unsigned* dz = (unsigned*)sB;
        for (int p = tid; p < 144 * 52; p += 256) dz[p] = 0u;
    }

    const unsigned sG_u = s2u(sG), sB_u = s2u(sB);
    const unsigned abase  = sG_u + (wm * 32) * P5 * 2 + AOFF(lane, P5);
    const unsigned btbase = sB_u + BTOFF(lane, PB5) + (wn * 48) * 2;

    for (int t = 0; t < 2; t++) {
        const int bh = blockIdx.y * 2 + t;
        __syncthreads();   // sG/zero ready; previous GEMM reads done

        {
            const __nv_bfloat162* pb = g_B2 + (size_t)bh * WF * CH + c0;
            for (int idx = tid; idx < 65 * 96; idx += 256) {
                int k = idx / 96, c = idx - (idx / 96) * 96;
                __nv_bfloat162 v = pb[(size_t)k * CH + c];
                sB[k * PB5 + c]        = __low2bfloat16(v);
                sB[(72 + k) * PB5 + c] = __high2bfloat16(v);
            }
        }
        __syncthreads();

        float acc[2][6][4];
        #pragma unroll
        for (int mt = 0; mt < 2; mt++)
            #pragma unroll
            for (int nt = 0; nt < 6; nt++)
                #pragma unroll
                for (int r = 0; r < 4; r++) acc[mt][nt][r] = 0.0f;

        for (int ks = 0; ks < 9; ks++) {
            const int k0 = ks * 16;
            unsigned a[2][4];
            ldsm_x4(a[0], abase + k0 * 2);
            ldsm_x4(a[1], abase + (16 * P5 + k0) * 2);
            #pragma unroll
            for (int nt = 0; nt < 6; nt++) {
                unsigned bb[2];
                ldsm_x2t(bb, btbase + (k0 * PB5 + nt * 8) * 2);
                mma_bf16(acc[0][nt], a[0], bb[0], bb[1]);
                mma_bf16(acc[1][nt], a[1], bb[0], bb[1]);
            }
        }

        {   // epilogue: + residual, direct to global
            const float* px = x   + (size_t)bh * WW * CH + c0;
            float*       po = out + (size_t)bh * WW * CH + c0;
            #pragma unroll
            for (int mt = 0; mt < 2; mt++)
                #pragma unroll
                for (int nt = 0; nt < 6; nt++) {
                    int row0 = wm * 32 + mt * 16 + g;
                    int jj = wn * 48 + nt * 8 + 2 * tig;
                    float2 xv0 = *(const float2*)(px + (size_t)row0 * CH + jj);
                    float2 xv1 = *(const float2*)(px + (size_t)(row0 + 8) * CH + jj);
                    *(float2*)(po + (size_t)row0 * CH + jj) =
                        make_float2(acc[mt][nt][0] + xv0.x, acc[mt][nt][1] + xv0.y);
                    *(float2*)(po + (size_t)(row0 + 8) * CH + jj) =
                        make_float2(acc[mt][nt][2] + xv1.x, acc[mt][nt][3] + xv1.y);
                }
        }
    }
}

// ---------------------------------------------------------------------------
extern "C" void kernel_launch(void* const* d_in, const int* in_sizes, int n_in,
                              void* d_out, int out_size)
{
    (void)in_sizes; (void)n_in; (void)out_size;
    const float* x  = (const float*)d_in[0];
    const float* w1 = (const float*)d_in[1];
    const float* b1 = (const float*)d_in[2];
    const float* w2 = (const float*)d_in[3];
    const float* b2 = (const float*)d_in[4];
    float* out = (float*)d_out;

    cudaFuncSetAttribute(k1g,  cudaFuncAttributeMaxDynamicSharedMemorySize, K1_TOT);
    cudaFuncSetAttribute(kmid, cudaFuncAttributeMaxDynamicSharedMemorySize, SM_TOT);
    cudaFuncSetAttribute(k5g,  cudaFuncAttributeMaxDynamicSharedMemorySize, K5_TOT);

    k0_build<<<32, 256>>>();
    k1g <<<dim3(CH / 96, BB * HH / 2), 256, K1_TOT>>>(x);
    kmid<<<dim3(NB, BB * WF), 512, SM_TOT>>>(w1, b1, w2, b2);
    k5g <<<dim3(CH / 96, BB * HH / 2), 256, K5_TOT>>>(x, out);
}

// round 11
// speedup vs baseline: 1.8721x; 1.0671x over previous
#include <cuda_runtime.h>
#include <cuda_bf16.h>

// ---------------------------------------------------------------------------
// AFNO2D: rfft2(128x128, ortho) -> blockwise complex MLP (8 blocks x 96ch,
// relu, softshrink 0.01) -> irfft2 -> + x.   All tensor-core GEMMs.
//   K1  W-rfft GEMM:  Y = G1 . x  -> g_A2       [natural B + ldsm.trans]
//   KMID per (b,wf,n): H-DFT -> MLP -> inv H-DFT, 512 thr, natural B + trans
//   K5  W-irfft GEMM: out = G5 . [Zr;Zi] + x    [natural B + ldsm.trans]
// k0 prebuilds DFT matrices AND bf16-converted transposed MLP weights.
// ---------------------------------------------------------------------------

#define BB 4
#define HH 128
#define WW 128
#define CH 768
#define NB 8
#define BS 96
#define WF 65
#define MPTS (BB*HH*WF)

__device__ __nv_bfloat162 g_A2[(size_t)MPTS * CH];
__device__ __nv_bfloat162 g_B2[(size_t)MPTS * CH];
__device__ __nv_bfloat16  g_G [128 * 256];
__device__ __nv_bfloat16  g_G1[128 * 128];
__device__ __nv_bfloat16  g_G5[128 * 146];
// [layer][ri][n][o*104+i] bf16, pre-transposed, pitch 104
__device__ __align__(16) __nv_bfloat16 g_Wb[2][2][NB][96 * 104];

// ---------------- K0: build DFT matrices + bf16 weights --------------------
__global__ void k0_build(const float* __restrict__ w1, const float* __restrict__ w2)
{
    int tid = blockIdx.x * 256 + threadIdx.x;
    const int STR = 32 * 256;
    for (int idx = tid; idx < 128 * 256; idx += STR) {
        int hp = idx >> 8, k = idx & 255, kk = k & 127;
        int m = (hp * kk) & 127;
        float s, c; sincospif(m * (1.0f / 64.0f), &s, &c);
        g_G[idx] = __float2bfloat16_rn((k < 128) ? c : s);
    }
    for (int idx = tid; idx < 128 * 128; idx += STR) {
        int m = idx >> 7, w = idx & 127;
        float val;
        if (m < 65) {
            int a = (m * w) & 127;
            float s, c; sincospif(a * (1.0f / 64.0f), &s, &c);
            val = c;
        } else {
            int a = ((m - 64) * w) & 127;
            float s, c; sincospif(a * (1.0f / 64.0f), &s, &c);
            val = -s;
        }
        g_G1[idx] = __float2bfloat16_rn(val);
    }
    for (int idx = tid; idx < 128 * 146; idx += STR) {
        int w = idx / 146, k = idx - (idx / 146) * 146;
        float val = 0.0f;
        if (k < 65) {
            float eps = (k == 0 || k == 64) ? 1.0f : 2.0f;
            int a = (w * k) & 127;
            float s, c; sincospif(a * (1.0f / 64.0f), &s, &c);
            val = eps * c * (1.0f / 128.0f);
        } else if (k >= 72 && k < 137) {
            int kk = k - 72;
            float eps = (kk == 0 || kk == 64) ? 1.0f : 2.0f;
            int a = (w * kk) & 127;
            float s, c; sincospif(a * (1.0f / 64.0f), &s, &c);
            val = -eps * s * (1.0f / 128.0f);
        }
        g_G5[idx] = __float2bfloat16_rn(val);
    }
    // weights: src (L? w2:w1)[ri][n][i][o] -> g_Wb[L][ri][n][o*104+i]
    for (int idx = tid; idx < 2 * 2 * NB * 96 * 96; idx += STR) {
        int o = idx % 96;
        int i = (idx / 96) % 96;
        int n = (idx / (96 * 96)) % NB;
        int ri = (idx / (96 * 96 * NB)) % 2;
        int L = idx / (96 * 96 * NB * 2);
        const float* src = L ? w2 : w1;
        float v = src[(((size_t)ri * NB + n) * 96 + i) * 96 + o];
        g_Wb[L][ri][n][o * 104 + i] = __float2bfloat16_rn(v);
    }
}

// ---------------- fragment helpers -----------------------------------------
__device__ __forceinline__ void mma_bf16(float* d, const unsigned* a, unsigned b0, unsigned b1)
{
    asm volatile(
        "mma.sync.aligned.m16n8k16.row.col.f32.bf16.bf16.f32 "
        "{%0,%1,%2,%3},{%4,%5,%6,%7},{%8,%9},{%0,%1,%2,%3};"
        : "+f"(d[0]), "+f"(d[1]), "+f"(d[2]), "+f"(d[3])
        : "r"(a[0]), "r"(a[1]), "r"(a[2]), "r"(a[3]), "r"(b0), "r"(b1));
}
__device__ __forceinline__ unsigned s2u(const void* p)
{
    unsigned r;
    asm("{ .reg .u64 t; cvta.to.shared.u64 t, %1; cvt.u32.u64 %0, t; }" : "=r"(r) : "l"(p));
    return r;
}
__device__ __forceinline__ void ldsm_x4(unsigned* r, unsigned a)
{
    asm volatile("ldmatrix.sync.aligned.m8n8.x4.shared.b16 {%0,%1,%2,%3},[%4];"
                 : "=r"(r[0]), "=r"(r[1]), "=r"(r[2]), "=r"(r[3]) : "r"(a));
}
__device__ __forceinline__ void ldsm_x2(unsigned* r, unsigned a)
{
    asm volatile("ldmatrix.sync.aligned.m8n8.x2.shared.b16 {%0,%1},[%2];"
                 : "=r"(r[0]), "=r"(r[1]) : "r"(a));
}
__device__ __forceinline__ void ldsm_x2t(unsigned* r, unsigned a)
{
    asm volatile("ldmatrix.sync.aligned.m8n8.x2.trans.shared.b16 {%0,%1},[%2];"
                 : "=r"(r[0]), "=r"(r[1]) : "r"(a));
}
#define AOFF(lane, P) ((((lane) & 15) * (P) + (((lane) >> 4) << 3)) * 2)
#define BOFF(lane, P) (((((lane) & 15) & 7) * (P) + (((((lane) & 15) >> 3) & 1) << 3)) * 2)
#define BTOFF(lane, P) (((lane) & 15) * (P) * 2)

// ---------------------------------------------------------------------------
// K1: W-rfft as GEMM. Per CTA: 2 bh rows (looped), 96 channels.
// ---------------------------------------------------------------------------
#define P1 136
#define PB1 104
#define K1_SG 0                /* 128*136*2 = 34816 */
#define K1_SB 34816            /* 128*104*2 = 26624 */
#define K1_TOT 61440
#define STG_P 98

__global__ void __launch_bounds__(256) k1g(const float* __restrict__ x)
{
    extern __shared__ char sm[];
    __nv_bfloat16* sG  = (__nv_bfloat16*)(sm + K1_SG);
    __nv_bfloat16* sB  = (__nv_bfloat16*)(sm + K1_SB);
    __nv_bfloat16* stg = (__nv_bfloat16*)(sm + K1_SB);

    const int tid = threadIdx.x;
    const int c0 = blockIdx.x * 96;
    const int lane = tid & 31, warp = tid >> 5;
    const int g = lane >> 2, tig = lane & 3;
    const int wm = warp & 3, wn = warp >> 2;

    {
        const unsigned* src = (const unsigned*)g_G1;
        unsigned* dst = (unsigned*)sG;
        for (int p = tid; p < 128 * 64; p += 256) {
            int row = p >> 6, kp = p & 63;
            dst[row * 68 + kp] = src[p];
        }
    }

    const unsigned sG_u = s2u(sG), sB_u = s2u(sB);
    const unsigned abase  = sG_u + (wm * 32) * P1 * 2 + AOFF(lane, P1);
    const unsigned btbase = sB_u + BTOFF(lane, PB1) + (wn * 48) * 2;

    for (int t = 0; t < 2; t++) {
        const int bh = blockIdx.y * 2 + t;
        __syncthreads();

        {   // ingest x natural [w][c], float4 loads
            const float* px = x + (size_t)bh * WW * CH + c0;
            for (int idx = tid; idx < 128 * 24; idx += 256) {
                int w = idx / 24, c = (idx - (idx / 24) * 24) * 4;
                float4 v = *(const float4*)(px + (size_t)w * CH + c);
                *(__nv_bfloat162*)(sB + w * PB1 + c)     = __floats2bfloat162_rn(v.x, v.y);
                *(__nv_bfloat162*)(sB + w * PB1 + c + 2) = __floats2bfloat162_rn(v.z, v.w);
            }
        }
        __syncthreads();

        float acc[2][6][4];
        #pragma unroll
        for (int mt = 0; mt < 2; mt++)
            #pragma unroll
            for (int nt = 0; nt < 6; nt++)
                #pragma unroll
                for (int r = 0; r < 4; r++) acc[mt][nt][r] = 0.0f;

        #pragma unroll
        for (int ks = 0; ks < 8; ks++) {
            const int k0 = ks * 16;
            unsigned a[2][4];
            ldsm_x4(a[0], abase + k0 * 2);
            ldsm_x4(a[1], abase + (16 * P1 + k0) * 2);
            #pragma unroll
            for (int nt = 0; nt < 6; nt++) {
                unsigned bb[2];
                ldsm_x2t(bb, btbase + (k0 * PB1 + nt * 8) * 2);
                mma_bf16(acc[0][nt], a[0], bb[0], bb[1]);
                mma_bf16(acc[1][nt], a[1], bb[0], bb[1]);
            }
        }
        __syncthreads();

        #pragma unroll
        for (int mt = 0; mt < 2; mt++)
            #pragma unroll
            for (int nt = 0; nt < 6; nt++) {
                int row0 = wm * 32 + mt * 16 + g;
                int jj = wn * 48 + nt * 8 + 2 * tig;
                *(__nv_bfloat162*)(stg + row0 * STG_P + jj) =
                    __floats2bfloat162_rn(acc[mt][nt][0], acc[mt][nt][1]);
                *(__nv_bfloat162*)(stg + (row0 + 8) * STG_P + jj) =
                    __floats2bfloat162_rn(acc[mt][nt][2], acc[mt][nt][3]);
            }
        __syncthreads();

        {
            __nv_bfloat162* pa = g_A2 + (size_t)bh * WF * CH + c0;
            const __nv_bfloat16 z = __float2bfloat16_rn(0.0f);
            for (int idx = tid; idx < 65 * 96; idx += 256) {
                int k = idx / 96, c = idx - (idx / 96) * 96;
                __nv_bfloat16 re = stg[k * STG_P + c];
                __nv_bfloat16 im = (k >= 1 && k <= 63) ? stg[(64 + k) * STG_P + c] : z;
                pa[(size_t)k * CH + c] = __halves2bfloat162(re, im);
            }
        }
    }
}

// ---------------------------------------------------------------------------
// KMID: per-(b,wf,n) fused H-DFT -> complex MLP -> inverse H-DFT.
// 512 threads. X/O stacks in NATURAL [k][c] layout (pitch 104) + ldsm.trans.
// ---------------------------------------------------------------------------
#define GP  264
#define PBX 104   /* sX/sOt natural pitch */
#define XP  200   /* sXm (MLP A-side) pitch */
#define WP  104
#define SM_G   0          /* 128*264*2 = 67584 */
#define SM_X   67584      /* max(256*104, 128*200)*2 = 53248 */
#define SM_W   120832     /* 19968 */
#define SM_WI  140800     /* 19968 */
#define SM_B1  160768
#define SM_B2  161536
#define SM_TOT 162304

__global__ void __launch_bounds__(512) kmid(const float* __restrict__ b1,
                                            const float* __restrict__ b2)
{
    extern __shared__ char sm[];
    __nv_bfloat16* sG  = (__nv_bfloat16*)(sm + SM_G);
    __nv_bfloat16* sX  = (__nv_bfloat16*)(sm + SM_X);   // natural [k 256][c 96]
    __nv_bfloat16* sXm = (__nv_bfloat16*)(sm + SM_X);   // [h' 128][192]
    __nv_bfloat16* sOt = (__nv_bfloat16*)(sm + SM_X);   // natural [k 256][c 96]
    __nv_bfloat16* sWr = (__nv_bfloat16*)(sm + SM_W);
    __nv_bfloat16* sWi = (__nv_bfloat16*)(sm + SM_WI);
    __nv_bfloat16* stg = (__nv_bfloat16*)(sm + SM_G);
    float* sB1 = (float*)(sm + SM_B1);
    float* sB2 = (float*)(sm + SM_B2);

    const int tid = threadIdx.x;
    const int n   = blockIdx.x;
    const int b   = blockIdx.y / WF;
    const int wf  = blockIdx.y - b * WF;
    const int lane = tid & 31, warp = tid >> 5;
    const int g = lane >> 2, tig = lane & 3;
    const int wm = warp & 3, wq = warp >> 2;
    const int wn = wq >> 1, wh = wq & 1;

    {
        const __nv_bfloat162* src = (const __nv_bfloat162*)g_G;
        for (int p = tid; p < 128 * 128; p += 512) {
            int hp = p >> 7, kp = p & 127;
            *(__nv_bfloat162*)(sG + hp * GP + 2 * kp) = src[p];
        }
    }
    {   // W1 copy (prebuilt bf16, pitch 104): 16B vector copies
        const uint4* srcR = (const uint4*)&g_Wb[0][0][n][0];
        const uint4* srcI = (const uint4*)&g_Wb[0][1][n][0];
        uint4* dR = (uint4*)sWr;
        uint4* dI = (uint4*)sWi;
        for (int p = tid; p < 96 * 104 / 8; p += 512) { dR[p] = srcR[p]; dI[p] = srcI[p]; }
        if (tid < 192) {
            int half = tid / 96, j = tid - half * 96;
            sB1[tid] = b1[half * (NB * BS) + n * BS + j];
            sB2[tid] = b2[half * (NB * BS) + n * BS + j];
        }
    }
    {   // ingest X natural: rows 0..127 = Xr, 128..255 = Xi (scaled 1/128)
        const __nv_bfloat162* pa = g_A2 + ((size_t)(b * HH) * WF + wf) * CH + n * BS;
        const __nv_bfloat162 c128 = __float2bfloat162_rn(0.0078125f);
        for (int idx = tid; idx < HH * 48; idx += 512) {
            int h = idx / 48, c = (idx - (idx / 48) * 48) * 2;
            uint2 v2 = *(const uint2*)(pa + (size_t)h * WF * CH + c);
            __nv_bfloat162 va = __hmul2(*(__nv_bfloat162*)&v2.x, c128);
            __nv_bfloat162 vb = __hmul2(*(__nv_bfloat162*)&v2.y, c128);
            *(__nv_bfloat162*)(sX + h * PBX + c) =
                __halves2bfloat162(__low2bfloat16(va), __low2bfloat16(vb));
            *(__nv_bfloat162*)(sX + (128 + h) * PBX + c) =
                __halves2bfloat162(__high2bfloat16(va), __high2bfloat16(vb));
        }
    }
    __syncthreads();

    const unsigned sG_u = s2u(sG), sX_u = s2u(sX);
    const unsigned sWr_u = s2u(sWr), sWi_u = s2u(sWi);
    const unsigned abaseG = sG_u + (wm * 32) * GP * 2 + AOFF(lane, GP);
    const unsigned abaseX = sX_u + (wm * 32) * XP * 2 + AOFF(lane, XP);
    const unsigned btbase = sX_u + BTOFF(lane, PBX) + (wh * 48) * 2;
    const unsigned boffW  = (wh * 48) * WP * 2 + BOFF(lane, WP);

    float acc[2][6][4];

    // =============== GEMM1: forward H-DFT ================================
    #pragma unroll
    for (int mt = 0; mt < 2; mt++)
        #pragma unroll
        for (int nt = 0; nt < 6; nt++)
            #pragma unroll
            for (int r = 0; r < 4; r++) acc[mt][nt][r] = 0.0f;

    #pragma unroll
    for (int ks = 0; ks < 16; ks++) {
        const int k0 = ks * 16;
        unsigned a[2][4];
        ldsm_x4(a[0], abaseG + k0 * 2);
        ldsm_x4(a[1], abaseG + (16 * GP + k0) * 2);
        const int kk = wn ? (k0 ^ 128) : k0;
        const unsigned msk = (wn && k0 >= 128) ? 0x80008000u : 0u;
        #pragma unroll
        for (int nt = 0; nt < 6; nt++) {
            unsigned bb[2];
            ldsm_x2t(bb, btbase + (kk * PBX + nt * 8) * 2);
            bb[0] ^= msk; bb[1] ^= msk;
            mma_bf16(acc[0][nt], a[0], bb[0], bb[1]);
            mma_bf16(acc[1][nt], a[1], bb[0], bb[1]);
        }
    }
    __syncthreads();

    #pragma unroll
    for (int mt = 0; mt < 2; mt++)
        #pragma unroll
        for (int nt = 0; nt < 6; nt++) {
            int row0 = wm * 32 + mt * 16 + g;
            int jj = wq * 48 + nt * 8 + 2 * tig;
            *(__nv_bfloat162*)(sXm + row0 * XP + jj) =
                __floats2bfloat162_rn(acc[mt][nt][0], acc[mt][nt][1]);
            *(__nv_bfloat162*)(sXm + (row0 + 8) * XP + jj) =
                __floats2bfloat162_rn(acc[mt][nt][2], acc[mt][nt][3]);
        }
    __syncthreads();

    // =============== MLP layer 1 ==========================================
    #pragma unroll
    for (int mt = 0; mt < 2; mt++)
        #pragma unroll
        for (int nt = 0; nt < 6; nt++)
            #pragma unroll
            for (int r = 0; r < 4; r++) acc[mt][nt][r] = 0.0f;

    #pragma unroll
    for (int ks = 0; ks < 12; ks++) {
        const int khalf = (ks >= 6);
        const int k0 = ks * 16, kkm = k0 - khalf * 96;
        const unsigned sW_u = (wn == 0) ? (khalf ? sWi_u : sWr_u)
                                        : (khalf ? sWr_u : sWi_u);
        const unsigned amsk = ((wn == 0) && khalf) ? 0x80008000u : 0u;
        unsigned a[2][4];
        ldsm_x4(a[0], abaseX + k0 * 2);
        ldsm_x4(a[1], abaseX + (16 * XP + k0) * 2);
        if (amsk) {
            #pragma unroll
            for (int mt = 0; mt < 2; mt++)
                #pragma unroll
                for (int r = 0; r < 4; r++) a[mt][r] ^= amsk;
        }
        #pragma unroll
        for (int nt = 0; nt < 6; nt++) {
            unsigned bb[2];
            ldsm_x2(bb, sW_u + boffW + (nt * 8 * WP + kkm) * 2);
            mma_bf16(acc[0][nt], a[0], bb[0], bb[1]);
            mma_bf16(acc[1][nt], a[1], bb[0], bb[1]);
        }
    }
    __syncthreads();

    #pragma unroll
    for (int mt = 0; mt < 2; mt++)
        #pragma unroll
        for (int nt = 0; nt < 6; nt++) {
            int row0 = wm * 32 + mt * 16 + g;
            int jj = wq * 48 + nt * 8 + 2 * tig;
            float bb0 = sB1[jj], bb1 = sB1[jj + 1];
            *(__nv_bfloat162*)(sXm + row0 * XP + jj) = __floats2bfloat162_rn(
                fmaxf(acc[mt][nt][0] + bb0, 0.0f), fmaxf(acc[mt][nt][1] + bb1, 0.0f));
            *(__nv_bfloat162*)(sXm + (row0 + 8) * XP + jj) = __floats2bfloat162_rn(
                fmaxf(acc[mt][nt][2] + bb0, 0.0f), fmaxf(acc[mt][nt][3] + bb1, 0.0f));
        }
    {   // W2 copy (prebuilt)
        const uint4* srcR = (const uint4*)&g_Wb[1][0][n][0];
        const uint4* srcI = (const uint4*)&g_Wb[1][1][n][0];
        uint4* dR = (uint4*)sWr;
        uint4* dI = (uint4*)sWi;
        for (int p = tid; p < 96 * 104 / 8; p += 512) { dR[p] = srcR[p]; dI[p] = srcI[p]; }
    }
    __syncthreads();

    // =============== MLP layer 2 ==========================================
    #pragma unroll
    for (int mt = 0; mt < 2; mt++)
        #pragma unroll
        for (int nt = 0; nt < 6; nt++)
            #pragma unroll
            for (int r = 0; r < 4; r++) acc[mt][nt][r] = 0.0f;

    #pragma unroll
    for (int ks = 0; ks < 12; ks++) {
        const int khalf = (ks >= 6);
        const int k0 = ks * 16, kkm = k0 - khalf * 96;
        const unsigned sW_u = (wn == 0) ? (khalf ? sWi_u : sWr_u)
                                        : (khalf ? sWr_u : sWi_u);
        const unsigned amsk = ((wn == 0) && khalf) ? 0x80008000u : 0u;
        unsigned a[2][4];
        ldsm_x4(a[0], abaseX + k0 * 2);
        ldsm_x4(a[1], abaseX + (16 * XP + k0) * 2);
        if (amsk) {
            #pragma unroll
            for (int mt = 0; mt < 2; mt++)
                #pragma unroll
                for (int r = 0; r < 4; r++) a[mt][r] ^= amsk;
        }
        #pragma unroll
        for (int nt = 0; nt < 6; nt++) {
            unsigned bb[2];
            ldsm_x2(bb, sW_u + boffW + (nt * 8 * WP + kkm) * 2);
            mma_bf16(acc[0][nt], a[0], bb[0], bb[1]);
            mma_bf16(acc[1][nt], a[1], bb[0], bb[1]);
        }
    }
    __syncthreads();

    // softshrink -> sOt NATURAL [k-stack][c]
    {
        const float lam = 0.01f;
        #pragma unroll
        for (int mt = 0; mt < 2; mt++)
            #pragma unroll
            for (int nt = 0; nt < 6; nt++) {
                int row0 = wm * 32 + mt * 16 + g;
                int c = wh * 48 + nt * 8 + 2 * tig;
                int jj = wn * 96 + c;
                float bb0 = sB2[jj], bb1 = sB2[jj + 1];
                #pragma unroll
                for (int r = 0; r < 4; r++) {
                    float v = acc[mt][nt][r] + ((r & 1) ? bb1 : bb0);
                    v = copysignf(fmaxf(fabsf(v) - lam, 0.0f), v);
                    int cc = c + (r & 1);
                    int kb = wn * 128 + row0 + (r >> 1) * 8;
                    sOt[kb * PBX + cc] = __float2bfloat16_rn(v);
                }
            }
    }
    __syncthreads();

    // =============== GEMM2: inverse H-DFT =================================
    #pragma unroll
    for (int mt = 0; mt < 2; mt++)
        #pragma unroll
        for (int nt = 0; nt < 6; nt++)
            #pragma unroll
            for (int r = 0; r < 4; r++) acc[mt][nt][r] = 0.0f;

    #pragma unroll
    for (int ks = 0; ks < 16; ks++) {
        const int k0 = ks * 16;
        unsigned a[2][4];
        ldsm_x4(a[0], abaseG + k0 * 2);
        ldsm_x4(a[1], abaseG + (16 * GP + k0) * 2);
        const int kk = wn ? (k0 ^ 128) : k0;
        const unsigned msk = (!wn && k0 >= 128) ? 0x80008000u : 0u;
        #pragma unroll
        for (int nt = 0; nt < 6; nt++) {
            unsigned bb[2];
            ldsm_x2t(bb, btbase + (kk * PBX + nt * 8) * 2);
            bb[0] ^= msk; bb[1] ^= msk;
            mma_bf16(acc[0][nt], a[0], bb[0], bb[1]);
            mma_bf16(acc[1][nt], a[1], bb[0], bb[1]);
        }
    }
    __syncthreads();

    #pragma unroll
    for (int mt = 0; mt < 2; mt++)
        #pragma unroll
        for (int nt = 0; nt < 6; nt++) {
            int row0 = wm * 32 + mt * 16 + g;
            int jj = wq * 48 + nt * 8 + 2 * tig;
            *(__nv_bfloat162*)(stg + row0 * XP + jj) =
                __floats2bfloat162_rn(acc[mt][nt][0], acc[mt][nt][1]);
            *(__nv_bfloat162*)(stg + (row0 + 8) * XP + jj) =
                __floats2bfloat162_rn(acc[mt][nt][2], acc[mt][nt][3]);
        }
    __syncthreads();

    {
        __nv_bfloat162* pb = g_B2 + ((size_t)(b * HH) * WF + wf) * CH + n * BS;
        for (int idx = tid; idx < HH * BS; idx += 512) {
            int h = idx / BS, c = idx - (idx / BS) * BS;
            pb[(size_t)h * WF * CH + c] =
                __halves2bfloat162(stg[h * XP + c], stg[h * XP + 96 + c]);
        }
    }
}

// ---------------------------------------------------------------------------
// K5: W-irfft as GEMM + residual. Per CTA: 2 bh rows (looped), 96 channels.
// ---------------------------------------------------------------------------
#define P5 152
#define PB5 104
#define K5_SG 0                /* 128*152*2 = 38912 */
#define K5_SB 38912            /* 144*104*2 = 29952 */
#define K5_TOT 68864

__global__ void __launch_bounds__(256) k5g(const float* __restrict__ x,
                                           float* __restrict__ out)
{
    extern __shared__ char sm[];
    __nv_bfloat16* sG = (__nv_bfloat16*)(sm + K5_SG);
    __nv_bfloat16* sB = (__nv_bfloat16*)(sm + K5_SB);

    const int tid = threadIdx.x;
    const int c0 = blockIdx.x * 96;
    const int lane = tid & 31, warp = tid >> 5;
    const int g = lane >> 2, tig = lane & 3;
    const int wm = warp & 3, wn = warp >> 2;

    {
        const unsigned* src = (const unsigned*)g_G5;
        unsigned* dst = (unsigned*)sG;
        for (int p = tid; p < 128 * 73; p += 256) {
            int row = p / 73, c = p - row * 73;
            dst[row * 76 + c] = src[p];
        }
    }
    {
        unsigned* dz = (unsigned*)sB;
        for (int p = tid; p < 144 * 52; p += 256) dz[p] = 0u;
    }

    const unsigned sG_u = s2u(sG), sB_u = s2u(sB);
    const unsigned abase  = sG_u + (wm * 32) * P5 * 2 + AOFF(lane, P5);
    const unsigned btbase = sB_u + BTOFF(lane, PB5) + (wn * 48) * 2;

    for (int t = 0; t < 2; t++) {
        const int bh = blockIdx.y * 2 + t;
        __syncthreads();

        {   // ingest (uint2: 2 channels per thread)
            const __nv_bfloat162* pb = g_B2 + (size_t)bh * WF * CH + c0;
            for (int idx = tid; idx < 65 * 48; idx += 256) {
                int k = idx / 48, c = (idx - (idx / 48) * 48) * 2;
                uint2 v2 = *(const uint2*)(pb + (size_t)k * CH + c);
                __nv_bfloat162 va = *(__nv_bfloat162*)&v2.x;
                __nv_bfloat162 vb = *(__nv_bfloat162*)&v2.y;
                *(__nv_bfloat162*)(sB + k * PB5 + c) =
                    __halves2bfloat162(__low2bfloat16(va), __low2bfloat16(vb));
                *(__nv_bfloat162*)(sB + (72 + k) * PB5 + c) =
                    __halves2bfloat162(__high2bfloat16(va), __high2bfloat16(vb));
            }
        }
        __syncthreads();

        float acc[2][6][4];
        #pragma unroll
        for (int mt = 0; mt < 2; mt++)
            #pragma unroll
            for (int nt = 0; nt < 6; nt++)
                #pragma unroll
                for (int r = 0; r < 4; r++) acc[mt][nt][r] = 0.0f;

        #pragma unroll
        for (int ks = 0; ks < 9; ks++) {
            const int k0 = ks * 16;
            unsigned a[2][4];
            ldsm_x4(a[0], abase + k0 * 2);
            ldsm_x4(a[1], abase + (16 * P5 + k0) * 2);
            #pragma unroll
            for (int nt = 0; nt < 6; nt++) {
                unsigned bb[2];
                ldsm_x2t(bb, btbase + (k0 * PB5 + nt * 8) * 2);
                mma_bf16(acc[0][nt], a[0], bb[0], bb[1]);
                mma_bf16(acc[1][nt], a[1], bb[0], bb[1]);
            }
        }

        {
            const float* px = x   + (size_t)bh * WW * CH + c0;
            float*       po = out + (size_t)bh * WW * CH + c0;
            #pragma unroll
            for (int mt = 0; mt < 2; mt++)
                #pragma unroll
                for (int nt = 0; nt < 6; nt++) {
                    int row0 = wm * 32 + mt * 16 + g;
                    int jj = wn * 48 + nt * 8 + 2 * tig;
                    float2 xv0 = *(const float2*)(px + (size_t)row0 * CH + jj);
                    float2 xv1 = *(const float2*)(px + (size_t)(row0 + 8) * CH + jj);
                    *(float2*)(po + (size_t)row0 * CH + jj) =
                        make_float2(acc[mt][nt][0] + xv0.x, acc[mt][nt][1] + xv0.y);
                    *(float2*)(po + (size_t)(row0 + 8) * CH + jj) =
                        make_float2(acc[mt][nt][2] + xv1.x, acc[mt][nt][3] + xv1.y);
                }
        }
    }
}

// ---------------------------------------------------------------------------
extern "C" void kernel_launch(void* const* d_in, const int* in_sizes, int n_in,
                              void* d_out, int out_size)
{
    (void)in_sizes; (void)n_in; (void)out_size;
    const float* x  = (const float*)d_in[0];
    const float* w1 = (const float*)d_in[1];
    const float* b1 = (const float*)d_in[2];
    const float* w2 = (const float*)d_in[3];
    const float* b2 = (const float*)d_in[4];
    float* out = (float*)d_out;

    cudaFuncSetAttribute(k1g,  cudaFuncAttributeMaxDynamicSharedMemorySize, K1_TOT);
    cudaFuncSetAttribute(kmid, cudaFuncAttributeMaxDynamicSharedMemorySize, SM_TOT);
    cudaFuncSetAttribute(k5g,  cudaFuncAttributeMaxDynamicSharedMemorySize, K5_TOT);

    k0_build<<<32, 256>>>(w1, w2);
    k1g <<<dim3(CH / 96, BB * HH / 2), 256, K1_TOT>>>(x);
    kmid<<<dim3(NB, BB * WF), 512, SM_TOT>>>(b1, b2);
    k5g <<<dim3(CH / 96, BB * HH / 2), 256, K5_TOT>>>(x, out);
}

// round 12
// speedup vs baseline: 2.0600x; 1.1003x over previous
#include <cuda_runtime.h>
#include <cuda_bf16.h>

// ---------------------------------------------------------------------------
// AFNO2D: rfft2(128x128, ortho) -> blockwise complex MLP (8 blocks x 96ch,
// relu, softshrink 0.01) -> irfft2 -> + x.   All tensor-core GEMMs.
//   K1  W-rfft GEMM (scaled 1/128):  Y = G1 . x  -> g_A2
//   KMID per (b,wf,n): folded H-DFT (K=128) -> MLP -> folded inv H-DFT
//   K5  W-irfft GEMM: out = G5 . [Zr;Zi] + x
// ---------------------------------------------------------------------------

#define BB 4
#define HH 128
#define WW 128
#define CH 768
#define NB 8
#define BS 96
#define WF 65
#define MPTS (BB*HH*WF)

__device__ __nv_bfloat162 g_A2[(size_t)MPTS * CH];
__device__ __nv_bfloat162 g_B2[(size_t)MPTS * CH];
__device__ __align__(16) __nv_bfloat16 g_Gp[128 * 136];  // folded H-DFT matrix
__device__ __nv_bfloat16  g_G1[128 * 128];
__device__ __nv_bfloat16  g_G5[128 * 146];
// [layer][ri][n][o*104+i] bf16, pre-transposed, pitch 104
__device__ __align__(16) __nv_bfloat16 g_Wb[2][2][NB][96 * 104];

// ---------------- K0: build matrices + bf16 weights -------------------------
__global__ void k0_build(const float* __restrict__ w1, const float* __restrict__ w2)
{
    int tid = blockIdx.x * 256 + threadIdx.x;
    const int STR = 32 * 256;
    // folded H-DFT matrix G': col k<=64 -> cos(2pi h'k/128); 65..127 -> sin(2pi h'(k-64)/128)
    for (int idx = tid; idx < 128 * 136; idx += STR) {
        int hp = idx / 136, k = idx - (idx / 136) * 136;
        float val = 0.0f;
        if (k <= 64) {
            int m = (hp * k) & 127;
            float s, c; sincospif(m * (1.0f / 64.0f), &s, &c);
            val = c;
        } else if (k < 128) {
            int m = (hp * (k - 64)) & 127;
            float s, c; sincospif(m * (1.0f / 64.0f), &s, &c);
            val = s;
        }
        g_Gp[idx] = __float2bfloat16_rn(val);
    }
    // W-rfft matrix, scaled by 1/128 (carries the H-pair ortho normalization)
    for (int idx = tid; idx < 128 * 128; idx += STR) {
        int m = idx >> 7, w = idx & 127;
        float val;
        if (m < 65) {
            int a = (m * w) & 127;
            float s, c; sincospif(a * (1.0f / 64.0f), &s, &c);
            val = c;
        } else {
            int a = ((m - 64) * w) & 127;
            float s, c; sincospif(a * (1.0f / 64.0f), &s, &c);
            val = -s;
        }
        g_G1[idx] = __float2bfloat16_rn(val * 0.0078125f);
    }
    for (int idx = tid; idx < 128 * 146; idx += STR) {
        int w = idx / 146, k = idx - (idx / 146) * 146;
        float val = 0.0f;
        if (k < 65) {
            float eps = (k == 0 || k == 64) ? 1.0f : 2.0f;
            int a = (w * k) & 127;
            float s, c; sincospif(a * (1.0f / 64.0f), &s, &c);
            val = eps * c * (1.0f / 128.0f);
        } else if (k >= 72 && k < 137) {
            int kk = k - 72;
            float eps = (kk == 0 || kk == 64) ? 1.0f : 2.0f;
            int a = (w * kk) & 127;
            float s, c; sincospif(a * (1.0f / 64.0f), &s, &c);
            val = -eps * s * (1.0f / 128.0f);
        }
        g_G5[idx] = __float2bfloat16_rn(val);
    }
    for (int idx = tid; idx < 2 * 2 * NB * 96 * 96; idx += STR) {
        int o = idx % 96;
        int i = (idx / 96) % 96;
        int n = (idx / (96 * 96)) % NB;
        int ri = (idx / (96 * 96 * NB)) % 2;
        int L = idx / (96 * 96 * NB * 2);
        const float* src = L ? w2 : w1;
        float v = src[(((size_t)ri * NB + n) * 96 + i) * 96 + o];
        g_Wb[L][ri][n][o * 104 + i] = __float2bfloat16_rn(v);
    }
}

// ---------------- fragment helpers -----------------------------------------
__device__ __forceinline__ void mma_bf16(float* d, const unsigned* a, unsigned b0, unsigned b1)
{
    asm volatile(
        "mma.sync.aligned.m16n8k16.row.col.f32.bf16.bf16.f32 "
        "{%0,%1,%2,%3},{%4,%5,%6,%7},{%8,%9},{%0,%1,%2,%3};"
        : "+f"(d[0]), "+f"(d[1]), "+f"(d[2]), "+f"(d[3])
        : "r"(a[0]), "r"(a[1]), "r"(a[2]), "r"(a[3]), "r"(b0), "r"(b1));
}
__device__ __forceinline__ unsigned s2u(const void* p)
{
    unsigned r;
    asm("{ .reg .u64 t; cvta.to.shared.u64 t, %1; cvt.u32.u64 %0, t; }" : "=r"(r) : "l"(p));
    return r;
}
__device__ __forceinline__ void ldsm_x4(unsigned* r, unsigned a)
{
    asm volatile("ldmatrix.sync.aligned.m8n8.x4.shared.b16 {%0,%1,%2,%3},[%4];"
                 : "=r"(r[0]), "=r"(r[1]), "=r"(r[2]), "=r"(r[3]) : "r"(a));
}
__device__ __forceinline__ void ldsm_x2(unsigned* r, unsigned a)
{
    asm volatile("ldmatrix.sync.aligned.m8n8.x2.shared.b16 {%0,%1},[%2];"
                 : "=r"(r[0]), "=r"(r[1]) : "r"(a));
}
__device__ __forceinline__ void ldsm_x2t(unsigned* r, unsigned a)
{
    asm volatile("ldmatrix.sync.aligned.m8n8.x2.trans.shared.b16 {%0,%1},[%2];"
                 : "=r"(r[0]), "=r"(r[1]) : "r"(a));
}
#define AOFF(lane, P) ((((lane) & 15) * (P) + (((lane) >> 4) << 3)) * 2)
#define BOFF(lane, P) (((((lane) & 15) & 7) * (P) + (((((lane) & 15) >> 3) & 1) << 3)) * 2)
#define BTOFF(lane, P) (((lane) & 15) * (P) * 2)

// ---------------------------------------------------------------------------
// K1: W-rfft as GEMM (unchanged except scaled G1). 2 bh rows per CTA.
// ---------------------------------------------------------------------------
#define P1 136
#define PB1 104
#define K1_SG 0
#define K1_SB 34816
#define K1_TOT 61440
#define STG_P 98

__global__ void __launch_bounds__(256) k1g(const float* __restrict__ x)
{
    extern __shared__ char sm[];
    __nv_bfloat16* sG  = (__nv_bfloat16*)(sm + K1_SG);
    __nv_bfloat16* sB  = (__nv_bfloat16*)(sm + K1_SB);
    __nv_bfloat16* stg = (__nv_bfloat16*)(sm + K1_SB);

    const int tid = threadIdx.x;
    const int c0 = blockIdx.x * 96;
    const int lane = tid & 31, warp = tid >> 5;
    const int g = lane >> 2, tig = lane & 3;
    const int wm = warp & 3, wn = warp >> 2;

    {
        const unsigned* src = (const unsigned*)g_G1;
        unsigned* dst = (unsigned*)sG;
        for (int p = tid; p < 128 * 64; p += 256) {
            int row = p >> 6, kp = p & 63;
            dst[row * 68 + kp] = src[p];
        }
    }

    const unsigned sG_u = s2u(sG), sB_u = s2u(sB);
    const unsigned abase  = sG_u + (wm * 32) * P1 * 2 + AOFF(lane, P1);
    const unsigned btbase = sB_u + BTOFF(lane, PB1) + (wn * 48) * 2;

    for (int t = 0; t < 2; t++) {
        const int bh = blockIdx.y * 2 + t;
        __syncthreads();

        {
            const float* px = x + (size_t)bh * WW * CH + c0;
            for (int idx = tid; idx < 128 * 24; idx += 256) {
                int w = idx / 24, c = (idx - (idx / 24) * 24) * 4;
                float4 v = *(const float4*)(px + (size_t)w * CH + c);
                *(__nv_bfloat162*)(sB + w * PB1 + c)     = __floats2bfloat162_rn(v.x, v.y);
                *(__nv_bfloat162*)(sB + w * PB1 + c + 2) = __floats2bfloat162_rn(v.z, v.w);
            }
        }
        __syncthreads();

        float acc[2][6][4];
        #pragma unroll
        for (int mt = 0; mt < 2; mt++)
            #pragma unroll
            for (int nt = 0; nt < 6; nt++)
                #pragma unroll
                for (int r = 0; r < 4; r++) acc[mt][nt][r] = 0.0f;

        #pragma unroll
        for (int ks = 0; ks < 8; ks++) {
            const int k0 = ks * 16;
            unsigned a[2][4];
            ldsm_x4(a[0], abase + k0 * 2);
            ldsm_x4(a[1], abase + (16 * P1 + k0) * 2);
            #pragma unroll
            for (int nt = 0; nt < 6; nt++) {
                unsigned bb[2];
                ldsm_x2t(bb, btbase + (k0 * PB1 + nt * 8) * 2);
                mma_bf16(acc[0][nt], a[0], bb[0], bb[1]);
                mma_bf16(acc[1][nt], a[1], bb[0], bb[1]);
            }
        }
        __syncthreads();

        #pragma unroll
        for (int mt = 0; mt < 2; mt++)
            #pragma unroll
            for (int nt = 0; nt < 6; nt++) {
                int row0 = wm * 32 + mt * 16 + g;
                int jj = wn * 48 + nt * 8 + 2 * tig;
                *(__nv_bfloat162*)(stg + row0 * STG_P + jj) =
                    __floats2bfloat162_rn(acc[mt][nt][0], acc[mt][nt][1]);
                *(__nv_bfloat162*)(stg + (row0 + 8) * STG_P + jj) =
                    __floats2bfloat162_rn(acc[mt][nt][2], acc[mt][nt][3]);
            }
        __syncthreads();

        {
            __nv_bfloat162* pa = g_A2 + (size_t)bh * WF * CH + c0;
            const __nv_bfloat16 z = __float2bfloat16_rn(0.0f);
            for (int idx = tid; idx < 65 * 96; idx += 256) {
                int k = idx / 96, c = idx - (idx / 96) * 96;
                __nv_bfloat16 re = stg[k * STG_P + c];
                __nv_bfloat16 im = (k >= 1 && k <= 63) ? stg[(64 + k) * STG_P + c] : z;
                pa[(size_t)k * CH + c] = __halves2bfloat162(re, im);
            }
        }
    }
}

// ---------------------------------------------------------------------------
// KMID: per-(b,wf,n) folded H-DFT -> complex MLP -> folded inverse H-DFT.
// 512 threads. DFT GEMMs: K=128 against G' (128x128); B = fold planes,
// natural [k][c] pitch 104, signs baked in at plane build time.
// ---------------------------------------------------------------------------
#define GPP 136
#define PBX 104
#define XP  200
#define WP  104
#define SM_G   0          /* 128*136*2 = 34816 */
#define SM_X   34816      /* 256*104*2 = 53248 (planes / sXm / sOt / stg) */
#define SM_W   88064      /* 19968 */
#define SM_WI  108032     /* 19968 */
#define SM_B1  128000
#define SM_B2  128768
#define SM_TOT 129536

__global__ void __launch_bounds__(512) kmid(const float* __restrict__ b1,
                                            const float* __restrict__ b2)
{
    extern __shared__ char sm[];
    __nv_bfloat16* sG  = (__nv_bfloat16*)(sm + SM_G);
    __nv_bfloat16* sX  = (__nv_bfloat16*)(sm + SM_X);   // fold planes [256][104]
    __nv_bfloat16* sXm = (__nv_bfloat16*)(sm + SM_X);   // MLP A [128][200]
    __nv_bfloat16* sOt = (__nv_bfloat16*)(sm + SM_X);   // O natural [256][104]
    __nv_bfloat16* stg = (__nv_bfloat16*)(sm + SM_X);   // final Z stage [128][200]
    __nv_bfloat16* sWr = (__nv_bfloat16*)(sm + SM_W);
    __nv_bfloat16* sWi = (__nv_bfloat16*)(sm + SM_WI);
    float* sB1 = (float*)(sm + SM_B1);
    float* sB2 = (float*)(sm + SM_B2);

    const int tid = threadIdx.x;
    const int n   = blockIdx.x;
    const int b   = blockIdx.y / WF;
    const int wf  = blockIdx.y - b * WF;
    const int lane = tid & 31, warp = tid >> 5;
    const int g = lane >> 2, tig = lane & 3;
    const int wm = warp & 3, wq = warp >> 2;
    const int wn = wq >> 1, wh = wq & 1;

    {   // G' copy (16B vectors)
        const uint4* src = (const uint4*)g_Gp;
        uint4* dst = (uint4*)sG;
        for (int p = tid; p < 128 * 136 * 2 / 16; p += 512) dst[p] = src[p];
    }
    {   // W1 copy + biases
        const uint4* srcR = (const uint4*)&g_Wb[0][0][n][0];
        const uint4* srcI = (const uint4*)&g_Wb[0][1][n][0];
        uint4* dR = (uint4*)sWr;
        uint4* dI = (uint4*)sWi;
        for (int p = tid; p < 96 * 104 / 8; p += 512) { dR[p] = srcR[p]; dI[p] = srcI[p]; }
        if (tid < 192) {
            int half = tid / 96, j = tid - half * 96;
            sB1[tid] = b1[half * (NB * BS) + n * BS + j];
            sB2[tid] = b2[half * (NB * BS) + n * BS + j];
        }
    }
    {   // ingest + forward fold:
        // plane0 rows 0..64 = Per, 65..127 = Mi ; plane1 rows 0..64 = Pei, 65..127 = -Mr
        const __nv_bfloat162* pa = g_A2 + ((size_t)(b * HH) * WF + wf) * CH + n * BS;
        for (int idx = tid; idx < 65 * 48; idx += 512) {
            int h = idx / 48, c = (idx - (idx / 48) * 48) * 2;
            uint2 ua = *(const uint2*)(pa + (size_t)h * WF * CH + c);
            float2 a0 = __bfloat1622float2(*(__nv_bfloat162*)&ua.x);   // (Xr,Xi) ch c
            float2 a1 = __bfloat1622float2(*(__nv_bfloat162*)&ua.y);   // ch c+1
            if (h == 0 || h == 64) {
                *(__nv_bfloat162*)(sX + h * PBX + c)         = __floats2bfloat162_rn(a0.x, a1.x);
                *(__nv_bfloat162*)(sX + (128 + h) * PBX + c) = __floats2bfloat162_rn(a0.y, a1.y);
            } else {
                uint2 ub = *(const uint2*)(pa + (size_t)(128 - h) * WF * CH + c);
                float2 b0 = __bfloat1622float2(*(__nv_bfloat162*)&ub.x);
                float2 b1v = __bfloat1622float2(*(__nv_bfloat162*)&ub.y);
                *(__nv_bfloat162*)(sX + h * PBX + c) =
                    __floats2bfloat162_rn(a0.x + b0.x, a1.x + b1v.x);          // Per
                *(__nv_bfloat162*)(sX + (64 + h) * PBX + c) =
                    __floats2bfloat162_rn(a0.y - b0.y, a1.y - b1v.y);          // Mi
                *(__nv_bfloat162*)(sX + (128 + h) * PBX + c) =
                    __floats2bfloat162_rn(a0.y + b0.y, a1.y + b1v.y);          // Pei
                *(__nv_bfloat162*)(sX + (192 + h) * PBX + c) =
                    __floats2bfloat162_rn(b0.x - a0.x, b1v.x - a1.x);          // -Mr
            }
        }
    }
    __syncthreads();

    const unsigned sG_u = s2u(sG), sX_u = s2u(sX);
    const unsigned sWr_u = s2u(sWr), sWi_u = s2u(sWi);
    const unsigned abaseG = sG_u + (wm * 32) * GPP * 2 + AOFF(lane, GPP);
    const unsigned abaseX = sX_u + (wm * 32) * XP * 2 + AOFF(lane, XP);
    const unsigned bplane = sX_u + (wn * 128 * PBX + wh * 48) * 2 + BTOFF(lane, PBX);
    const unsigned boffW  = (wh * 48) * WP * 2 + BOFF(lane, WP);

    float acc[2][6][4];

    // =============== GEMM1: folded forward H-DFT (K=128) ==================
    #pragma unroll
    for (int mt = 0; mt < 2; mt++)
        #pragma unroll
        for (int nt = 0; nt < 6; nt++)
            #pragma unroll
            for (int r = 0; r < 4; r++) acc[mt][nt][r] = 0.0f;

    #pragma unroll
    for (int ks = 0; ks < 8; ks++) {
        const int k0 = ks * 16;
        unsigned a[2][4];
        ldsm_x4(a[0], abaseG + k0 * 2);
        ldsm_x4(a[1], abaseG + (16 * GPP + k0) * 2);
        #pragma unroll
        for (int nt = 0; nt < 6; nt++) {
            unsigned bb[2];
            ldsm_x2t(bb, bplane + (k0 * PBX + nt * 8) * 2);
            mma_bf16(acc[0][nt], a[0], bb[0], bb[1]);
            mma_bf16(acc[1][nt], a[1], bb[0], bb[1]);
        }
    }
    __syncthreads();

    #pragma unroll
    for (int mt = 0; mt < 2; mt++)
        #pragma unroll
        for (int nt = 0; nt < 6; nt++) {
            int row0 = wm * 32 + mt * 16 + g;
            int jj = wq * 48 + nt * 8 + 2 * tig;
            *(__nv_bfloat162*)(sXm + row0 * XP + jj) =
                __floats2bfloat162_rn(acc[mt][nt][0], acc[mt][nt][1]);
            *(__nv_bfloat162*)(sXm + (row0 + 8) * XP + jj) =
                __floats2bfloat162_rn(acc[mt][nt][2], acc[mt][nt][3]);
        }
    __syncthreads();

    // =============== MLP layer 1 ==========================================
    #pragma unroll
    for (int mt = 0; mt < 2; mt++)
        #pragma unroll
        for (int nt = 0; nt < 6; nt++)
            #pragma unroll
            for (int r = 0; r < 4; r++) acc[mt][nt][r] = 0.0f;

    #pragma unroll
    for (int ks = 0; ks < 12; ks++) {
        const int khalf = (ks >= 6);
        const int k0 = ks * 16, kkm = k0 - khalf * 96;
        const unsigned sW_u = (wn == 0) ? (khalf ? sWi_u : sWr_u)
                                        : (khalf ? sWr_u : sWi_u);
        const unsigned amsk = ((wn == 0) && khalf) ? 0x80008000u : 0u;
        unsigned a[2][4];
        ldsm_x4(a[0], abaseX + k0 * 2);
        ldsm_x4(a[1], abaseX + (16 * XP + k0) * 2);
        if (amsk) {
            #pragma unroll
            for (int mt = 0; mt < 2; mt++)
                #pragma unroll
                for (int r = 0; r < 4; r++) a[mt][r] ^= amsk;
        }
        #pragma unroll
        for (int nt = 0; nt < 6; nt++) {
            unsigned bb[2];
            ldsm_x2(bb, sW_u + boffW + (nt * 8 * WP + kkm) * 2);
            mma_bf16(acc[0][nt], a[0], bb[0], bb[1]);
            mma_bf16(acc[1][nt], a[1], bb[0], bb[1]);
        }
    }
    __syncthreads();

    #pragma unroll
    for (int mt = 0; mt < 2; mt++)
        #pragma unroll
        for (int nt = 0; nt < 6; nt++) {
            int row0 = wm * 32 + mt * 16 + g;
            int jj = wq * 48 + nt * 8 + 2 * tig;
            float bb0 = sB1[jj], bb1 = sB1[jj + 1];
            *(__nv_bfloat162*)(sXm + row0 * XP + jj) = __floats2bfloat162_rn(
                fmaxf(acc[mt][nt][0] + bb0, 0.0f), fmaxf(acc[mt][nt][1] + bb1, 0.0f));
            *(__nv_bfloat162*)(sXm + (row0 + 8) * XP + jj) = __floats2bfloat162_rn(
                fmaxf(acc[mt][nt][2] + bb0, 0.0f), fmaxf(acc[mt][nt][3] + bb1, 0.0f));
        }
    {   // W2 copy
        const uint4* srcR = (const uint4*)&g_Wb[1][0][n][0];
        const uint4* srcI = (const uint4*)&g_Wb[1][1][n][0];
        uint4* dR = (uint4*)sWr;
        uint4* dI = (uint4*)sWi;
        for (int p = tid; p < 96 * 104 / 8; p += 512) { dR[p] = srcR[p]; dI[p] = srcI[p]; }
    }
    __syncthreads();

    // =============== MLP layer 2 ==========================================
    #pragma unroll
    for (int mt = 0; mt < 2; mt++)
        #pragma unroll
        for (int nt = 0; nt < 6; nt++)
            #pragma unroll
            for (int r = 0; r < 4; r++) acc[mt][nt][r] = 0.0f;

    #pragma unroll
    for (int ks = 0; ks < 12; ks++) {
        const int khalf = (ks >= 6);
        const int k0 = ks * 16, kkm = k0 - khalf * 96;
        const unsigned sW_u = (wn == 0) ? (khalf ? sWi_u : sWr_u)
                                        : (khalf ? sWr_u : sWi_u);
        const unsigned amsk = ((wn == 0) && khalf) ? 0x80008000u : 0u;
        unsigned a[2][4];
        ldsm_x4(a[0], abaseX + k0 * 2);
        ldsm_x4(a[1], abaseX + (16 * XP + k0) * 2);
        if (amsk) {
            #pragma unroll
            for (int mt = 0; mt < 2; mt++)
                #pragma unroll
                for (int r = 0; r < 4; r++) a[mt][r] ^= amsk;
        }
        #pragma unroll
        for (int nt = 0; nt < 6; nt++) {
            unsigned bb[2];
            ldsm_x2(bb, sW_u + boffW + (nt * 8 * WP + kkm) * 2);
            mma_bf16(acc[0][nt], a[0], bb[0], bb[1]);
            mma_bf16(acc[1][nt], a[1], bb[0], bb[1]);
        }
    }
    __syncthreads();

    // softshrink -> sOt natural [k-stack 256][c]
    {
        const float lam = 0.01f;
        #pragma unroll
        for (int mt = 0; mt < 2; mt++)
            #pragma unroll
            for (int nt = 0; nt < 6; nt++) {
                int row0 = wm * 32 + mt * 16 + g;
                int c = wh * 48 + nt * 8 + 2 * tig;
                int jj = wn * 96 + c;
                float bb0 = sB2[jj], bb1 = sB2[jj + 1];
                #pragma unroll
                for (int r = 0; r < 4; r++) {
                    float v = acc[mt][nt][r] + ((r & 1) ? bb1 : bb0);
                    v = copysignf(fmaxf(fabsf(v) - lam, 0.0f), v);
                    int cc = c + (r & 1);
                    int kb = wn * 128 + row0 + (r >> 1) * 8;
                    sOt[kb * PBX + cc] = __float2bfloat16_rn(v);
                }
            }
    }
    __syncthreads();

    // =============== in-place inverse fold (two-phase) ====================
    // plane0 rows: m<=64 POr=Or[m]+Or[128-m]; 64+m (m=1..63) -MOi=Oi[128-m]-Oi[m]
    // plane1 rows: m<=64 POi=Oi[m]+Oi[128-m]; 64+m MOr=Or[m]-Or[128-m]
    {
        unsigned rA[6], rB[6], rC[6], rD[6];
        int ns = 0;
        for (int idx = tid; idx < 63 * 48; idx += 512) {
            int m = idx / 48 + 1, c = (idx - (idx / 48) * 48) * 2;
            rA[ns] = *(unsigned*)(sOt + m * PBX + c);
            rB[ns] = *(unsigned*)(sOt + (128 - m) * PBX + c);
            rC[ns] = *(unsigned*)(sOt + (128 + m) * PBX + c);
            rD[ns] = *(unsigned*)(sOt + (256 - m) * PBX + c);
            ns++;
        }
        __syncthreads();
        ns = 0;
        for (int idx = tid; idx < 63 * 48; idx += 512) {
            int m = idx / 48 + 1, c = (idx - (idx / 48) * 48) * 2;
            float2 fa = __bfloat1622float2(*(__nv_bfloat162*)&rA[ns]);
            float2 fb = __bfloat1622float2(*(__nv_bfloat162*)&rB[ns]);
            float2 fc = __bfloat1622float2(*(__nv_bfloat162*)&rC[ns]);
            float2 fd = __bfloat1622float2(*(__nv_bfloat162*)&rD[ns]);
            *(__nv_bfloat162*)(sOt + m * PBX + c) =
                __floats2bfloat162_rn(fa.x + fb.x, fa.y + fb.y);       // POr
            *(__nv_bfloat162*)(sOt + (64 + m) * PBX + c) =
                __floats2bfloat162_rn(fd.x - fc.x, fd.y - fc.y);       // -MOi
            *(__nv_bfloat162*)(sOt + (128 + m) * PBX + c) =
                __floats2bfloat162_rn(fc.x + fd.x, fc.y + fd.y);       // POi
            *(__nv_bfloat162*)(sOt + (192 + m) * PBX + c) =
                __floats2bfloat162_rn(fa.x - fb.x, fa.y - fb.y);       // MOr
            ns++;
        }
    }
    __syncthreads();

    // =============== GEMM2: folded inverse H-DFT (K=128) ==================
    #pragma unroll
    for (int mt = 0; mt < 2; mt++)
        #pragma unroll
        for (int nt = 0; nt < 6; nt++)
            #pragma unroll
            for (int r = 0; r < 4; r++) acc[mt][nt][r] = 0.0f;

    #pragma unroll
    for (int ks = 0; ks < 8; ks++) {
        const int k0 = ks * 16;
        unsigned a[2][4];
        ldsm_x4(a[0], abaseG + k0 * 2);
        ldsm_x4(a[1], abaseG + (16 * GPP + k0) * 2);
        #pragma unroll
        for (int nt = 0; nt < 6; nt++) {
            unsigned bb[2];
            ldsm_x2t(bb, bplane + (k0 * PBX + nt * 8) * 2);
            mma_bf16(acc[0][nt], a[0], bb[0], bb[1]);
            mma_bf16(acc[1][nt], a[1], bb[0], bb[1]);
        }
    }
    __syncthreads();

    #pragma unroll
    for (int mt = 0; mt < 2; mt++)
        #pragma unroll
        for (int nt = 0; nt < 6; nt++) {
            int row0 = wm * 32 + mt * 16 + g;
            int jj = wq * 48 + nt * 8 + 2 * tig;
            *(__nv_bfloat162*)(stg + row0 * XP + jj) =
                __floats2bfloat162_rn(acc[mt][nt][0], acc[mt][nt][1]);
            *(__nv_bfloat162*)(stg + (row0 + 8) * XP + jj) =
                __floats2bfloat162_rn(acc[mt][nt][2], acc[mt][nt][3]);
        }
    __syncthreads();

    {
        __nv_bfloat162* pb = g_B2 + ((size_t)(b * HH) * WF + wf) * CH + n * BS;
        for (int idx = tid; idx < HH * BS; idx += 512) {
            int h = idx / BS, c = idx - (idx / BS) * BS;
            pb[(size_t)h * WF * CH + c] =
                __halves2bfloat162(stg[h * XP + c], stg[h * XP + 96 + c]);
        }
    }
}

// ---------------------------------------------------------------------------
// K5: W-irfft as GEMM + residual (unchanged). 2 bh rows per CTA.
// ---------------------------------------------------------------------------
#define P5 152
#define PB5 104
#define K5_SG 0
#define K5_SB 38912
#define K5_TOT 68864

__global__ void __launch_bounds__(256) k5g(const float* __restrict__ x,
                                           float* __restrict__ out)
{
    extern __shared__ char sm[];
    __nv_bfloat16* sG = (__nv_bfloat16*)(sm + K5_SG);
    __nv_bfloat16* sB = (__nv_bfloat16*)(sm + K5_SB);

    const int tid = threadIdx.x;
    const int c0 = blockIdx.x * 96;
    const int lane = tid & 31, warp = tid >> 5;
    const int g = lane >> 2, tig = lane & 3;
    const int wm = warp & 3, wn = warp >> 2;

    {
        const unsigned* src = (const unsigned*)g_G5;
        unsigned* dst = (unsigned*)sG;
        for (int p = tid; p < 128 * 73; p += 256) {
            int row = p / 73, c = p - row * 73;
            dst[row * 76 + c] = src[p];
        }
    }
    {
        unsigned* dz = (unsigned*)sB;
        for (int p = tid; p < 144 * 52; p += 256) dz[p] = 0u;
    }

    const unsigned sG_u = s2u(sG), sB_u = s2u(sB);
    const unsigned abase  = sG_u + (wm * 32) * P5 * 2 + AOFF(lane, P5);
    const unsigned btbase = sB_u + BTOFF(lane, PB5) + (wn * 48) * 2;

    for (int t = 0; t < 2; t++) {
        const int bh = blockIdx.y * 2 + t;
        __syncthreads();

        {
            const __nv_bfloat162* pb = g_B2 + (size_t)bh * WF * CH + c0;
            for (int idx = tid; idx < 65 * 48; idx += 256) {
                int k = idx / 48, c = (idx - (idx / 48) * 48) * 2;
                uint2 v2 = *(const uint2*)(pb + (size_t)k * CH + c);
                __nv_bfloat162 va = *(__nv_bfloat162*)&v2.x;
                __nv_bfloat162 vb = *(__nv_bfloat162*)&v2.y;
                *(__nv_bfloat162*)(sB + k * PB5 + c) =
                    __halves2bfloat162(__low2bfloat16(va), __low2bfloat16(vb));
                *(__nv_bfloat162*)(sB + (72 + k) * PB5 + c) =
                    __halves2bfloat162(__high2bfloat16(va), __high2bfloat16(vb));
            }
        }
        __syncthreads();

        float acc[2][6][4];
        #pragma unroll
        for (int mt = 0; mt < 2; mt++)
            #pragma unroll
            for (int nt = 0; nt < 6; nt++)
                #pragma unroll
                for (int r = 0; r < 4; r++) acc[mt][nt][r] = 0.0f;

        #pragma unroll
        for (int ks = 0; ks < 9; ks++) {
            const int k0 = ks * 16;
            unsigned a[2][4];
            ldsm_x4(a[0], abase + k0 * 2);
            ldsm_x4(a[1], abase + (16 * P5 + k0) * 2);
            #pragma unroll
            for (int nt = 0; nt < 6; nt++) {
                unsigned bb[2];
                ldsm_x2t(bb, btbase + (k0 * PB5 + nt * 8) * 2);
                mma_bf16(acc[0][nt], a[0], bb[0], bb[1]);
                mma_bf16(acc[1][nt], a[1], bb[0], bb[1]);
            }
        }

        {
            const float* px = x   + (size_t)bh * WW * CH + c0;
            float*       po = out + (size_t)bh * WW * CH + c0;
            #pragma unroll
            for (int mt = 0; mt < 2; mt++)
                #pragma unroll
                for (int nt = 0; nt < 6; nt++) {
                    int row0 = wm * 32 + mt * 16 + g;
                    int jj = wn * 48 + nt * 8 + 2 * tig;
                    float2 xv0 = *(const float2*)(px + (size_t)row0 * CH + jj);
                    float2 xv1 = *(const float2*)(px + (size_t)(row0 + 8) * CH + jj);
                    *(float2*)(po + (size_t)row0 * CH + jj) =
                        make_float2(acc[mt][nt][0] + xv0.x, acc[mt][nt][1] + xv0.y);
                    *(float2*)(po + (size_t)(row0 + 8) * CH + jj) =
                        make_float2(acc[mt][nt][2] + xv1.x, acc[mt][nt][3] + xv1.y);
                }
        }
    }
}

// ---------------------------------------------------------------------------
extern "C" void kernel_launch(void* const* d_in, const int* in_sizes, int n_in,
                              void* d_out, int out_size)
{
    (void)in_sizes; (void)n_in; (void)out_size;
    const float* x  = (const float*)d_in[0];
    const float* w1 = (const float*)d_in[1];
    const float* b1 = (const float*)d_in[2];
    const float* w2 = (const float*)d_in[3];
    const float* b2 = (const float*)d_in[4];
    float* out = (float*)d_out;

    cudaFuncSetAttribute(k1g,  cudaFuncAttributeMaxDynamicSharedMemorySize, K1_TOT);
    cudaFuncSetAttribute(kmid, cudaFuncAttributeMaxDynamicSharedMemorySize, SM_TOT);
    cudaFuncSetAttribute(k5g,  cudaFuncAttributeMaxDynamicSharedMemorySize, K5_TOT);

    k0_build<<<32, 256>>>(w1, w2);
    k1g <<<dim3(CH / 96, BB * HH / 2), 256, K1_TOT>>>(x);
    kmid<<<dim3(NB, BB * WF), 512, SM_TOT>>>(b1, b2);
    k5g <<<dim3(CH / 96, BB * HH / 2), 256, K5_TOT>>>(x, out);
}

// round 13
// speedup vs baseline: 2.3012x; 1.1171x over previous
#include <cuda_runtime.h>
#include <cuda_bf16.h>

// ---------------------------------------------------------------------------
// AFNO2D: rfft2(128x128, ortho) -> blockwise complex MLP (8 blocks x 96ch,
// relu, softshrink 0.01) -> irfft2 -> + x.   All tensor-core GEMMs.
//   K1  W-rfft GEMM (scaled 1/128):  Y = G1 . x  -> g_A2
//   KMID per (b,wf,n): folded H-DFT (K=128) -> MLP -> folded inv H-DFT
//        G' and W1/W2 share one smem region (time-multiplexed) -> 2 CTA/SM
//   K5  W-irfft GEMM: out = G5 . [Zr;Zi] + x
// ---------------------------------------------------------------------------

#define BB 4
#define HH 128
#define WW 128
#define CH 768
#define NB 8
#define BS 96
#define WF 65
#define MPTS (BB*HH*WF)

__device__ __nv_bfloat162 g_A2[(size_t)MPTS * CH];
__device__ __nv_bfloat162 g_B2[(size_t)MPTS * CH];
__device__ __align__(16) __nv_bfloat16 g_Gp[128 * 136];  // folded H-DFT matrix
__device__ __nv_bfloat16  g_G1[128 * 128];
__device__ __nv_bfloat16  g_G5[128 * 146];
// [layer][ri][n][o*104+i] bf16, pre-transposed, pitch 104
__device__ __align__(16) __nv_bfloat16 g_Wb[2][2][NB][96 * 104];

// ---------------- K0: build matrices + bf16 weights -------------------------
__global__ void k0_build(const float* __restrict__ w1, const float* __restrict__ w2)
{
    int tid = blockIdx.x * 256 + threadIdx.x;
    const int STR = 32 * 256;
    for (int idx = tid; idx < 128 * 136; idx += STR) {
        int hp = idx / 136, k = idx - (idx / 136) * 136;
        float val = 0.0f;
        if (k <= 64) {
            int m = (hp * k) & 127;
            float s, c; sincospif(m * (1.0f / 64.0f), &s, &c);
            val = c;
        } else if (k < 128) {
            int m = (hp * (k - 64)) & 127;
            float s, c; sincospif(m * (1.0f / 64.0f), &s, &c);
            val = s;
        }
        g_Gp[idx] = __float2bfloat16_rn(val);
    }
    for (int idx = tid; idx < 128 * 128; idx += STR) {
        int m = idx >> 7, w = idx & 127;
        float val;
        if (m < 65) {
            int a = (m * w) & 127;
            float s, c; sincospif(a * (1.0f / 64.0f), &s, &c);
            val = c;
        } else {
            int a = ((m - 64) * w) & 127;
            float s, c; sincospif(a * (1.0f / 64.0f), &s, &c);
            val = -s;
        }
        g_G1[idx] = __float2bfloat16_rn(val * 0.0078125f);
    }
    for (int idx = tid; idx < 128 * 146; idx += STR) {
        int w = idx / 146, k = idx - (idx / 146) * 146;
        float val = 0.0f;
        if (k < 65) {
            float eps = (k == 0 || k == 64) ? 1.0f : 2.0f;
            int a = (w * k) & 127;
            float s, c; sincospif(a * (1.0f / 64.0f), &s, &c);
            val = eps * c * (1.0f / 128.0f);
        } else if (k >= 72 && k < 137) {
            int kk = k - 72;
            float eps = (kk == 0 || kk == 64) ? 1.0f : 2.0f;
            int a = (w * kk) & 127;
            float s, c; sincospif(a * (1.0f / 64.0f), &s, &c);
            val = -eps * s * (1.0f / 128.0f);
        }
        g_G5[idx] = __float2bfloat16_rn(val);
    }
    for (int idx = tid; idx < 2 * 2 * NB * 96 * 96; idx += STR) {
        int o = idx % 96;
        int i = (idx / 96) % 96;
        int n = (idx / (96 * 96)) % NB;
        int ri = (idx / (96 * 96 * NB)) % 2;
        int L = idx / (96 * 96 * NB * 2);
        const float* src = L ? w2 : w1;
        float v = src[(((size_t)ri * NB + n) * 96 + i) * 96 + o];
        g_Wb[L][ri][n][o * 104 + i] = __float2bfloat16_rn(v);
    }
}

// ---------------- fragment helpers -----------------------------------------
__device__ __forceinline__ void mma_bf16(float* d, const unsigned* a, unsigned b0, unsigned b1)
{
    asm volatile(
        "mma.sync.aligned.m16n8k16.row.col.f32.bf16.bf16.f32 "
        "{%0,%1,%2,%3},{%4,%5,%6,%7},{%8,%9},{%0,%1,%2,%3};"
        : "+f"(d[0]), "+f"(d[1]), "+f"(d[2]), "+f"(d[3])
        : "r"(a[0]), "r"(a[1]), "r"(a[2]), "r"(a[3]), "r"(b0), "r"(b1));
}
__device__ __forceinline__ unsigned s2u(const void* p)
{
    unsigned r;
    asm("{ .reg .u64 t; cvta.to.shared.u64 t, %1; cvt.u32.u64 %0, t; }" : "=r"(r) : "l"(p));
    return r;
}
__device__ __forceinline__ void ldsm_x4(unsigned* r, unsigned a)
{
    asm volatile("ldmatrix.sync.aligned.m8n8.x4.shared.b16 {%0,%1,%2,%3},[%4];"
                 : "=r"(r[0]), "=r"(r[1]), "=r"(r[2]), "=r"(r[3]) : "r"(a));
}
__device__ __forceinline__ void ldsm_x2(unsigned* r, unsigned a)
{
    asm volatile("ldmatrix.sync.aligned.m8n8.x2.shared.b16 {%0,%1},[%2];"
                 : "=r"(r[0]), "=r"(r[1]) : "r"(a));
}
__device__ __forceinline__ void ldsm_x2t(unsigned* r, unsigned a)
{
    asm volatile("ldmatrix.sync.aligned.m8n8.x2.trans.shared.b16 {%0,%1},[%2];"
                 : "=r"(r[0]), "=r"(r[1]) : "r"(a));
}
#define AOFF(lane, P) ((((lane) & 15) * (P) + (((lane) >> 4) << 3)) * 2)
#define BOFF(lane, P) (((((lane) & 15) & 7) * (P) + (((((lane) & 15) >> 3) & 1) << 3)) * 2)
#define BTOFF(lane, P) (((lane) & 15) * (P) * 2)

// ---------------------------------------------------------------------------
// K1: W-rfft as GEMM. 2 bh rows per CTA.
// ---------------------------------------------------------------------------
#define P1 136
#define PB1 104
#define K1_SG 0
#define K1_SB 34816
#define K1_TOT 61440
#define STG_P 98

__global__ void __launch_bounds__(256) k1g(const float* __restrict__ x)
{
    extern __shared__ char sm[];
    __nv_bfloat16* sG  = (__nv_bfloat16*)(sm + K1_SG);
    __nv_bfloat16* sB  = (__nv_bfloat16*)(sm + K1_SB);
    __nv_bfloat16* stg = (__nv_bfloat16*)(sm + K1_SB);

    const int tid = threadIdx.x;
    const int c0 = blockIdx.x * 96;
    const int lane = tid & 31, warp = tid >> 5;
    const int g = lane >> 2, tig = lane & 3;
    const int wm = warp & 3, wn = warp >> 2;

    {
        const unsigned* src = (const unsigned*)g_G1;
        unsigned* dst = (unsigned*)sG;
        for (int p = tid; p < 128 * 64; p += 256) {
            int row = p >> 6, kp = p & 63;
            dst[row * 68 + kp] = src[p];
        }
    }

    const unsigned sG_u = s2u(sG), sB_u = s2u(sB);
    const unsigned abase  = sG_u + (wm * 32) * P1 * 2 + AOFF(lane, P1);
    const unsigned btbase = sB_u + BTOFF(lane, PB1) + (wn * 48) * 2;

    for (int t = 0; t < 2; t++) {
        const int bh = blockIdx.y * 2 + t;
        __syncthreads();

        {
            const float* px = x + (size_t)bh * WW * CH + c0;
            for (int idx = tid; idx < 128 * 24; idx += 256) {
                int w = idx / 24, c = (idx - (idx / 24) * 24) * 4;
                float4 v = *(const float4*)(px + (size_t)w * CH + c);
                *(__nv_bfloat162*)(sB + w * PB1 + c)     = __floats2bfloat162_rn(v.x, v.y);
                *(__nv_bfloat162*)(sB + w * PB1 + c + 2) = __floats2bfloat162_rn(v.z, v.w);
            }
        }
        __syncthreads();

        float acc[2][6][4];
        #pragma unroll
        for (int mt = 0; mt < 2; mt++)
            #pragma unroll
            for (int nt = 0; nt < 6; nt++)
                #pragma unroll
                for (int r = 0; r < 4; r++) acc[mt][nt][r] = 0.0f;

        #pragma unroll
        for (int ks = 0; ks < 8; ks++) {
            const int k0 = ks * 16;
            unsigned a[2][4];
            ldsm_x4(a[0], abase + k0 * 2);
            ldsm_x4(a[1], abase + (16 * P1 + k0) * 2);
            #pragma unroll
            for (int nt = 0; nt < 6; nt++) {
                unsigned bb[2];
                ldsm_x2t(bb, btbase + (k0 * PB1 + nt * 8) * 2);
                mma_bf16(acc[0][nt], a[0], bb[0], bb[1]);
                mma_bf16(acc[1][nt], a[1], bb[0], bb[1]);
            }
        }
        __syncthreads();

        #pragma unroll
        for (int mt = 0; mt < 2; mt++)
            #pragma unroll
            for (int nt = 0; nt < 6; nt++) {
                int row0 = wm * 32 + mt * 16 + g;
                int jj = wn * 48 + nt * 8 + 2 * tig;
                *(__nv_bfloat162*)(stg + row0 * STG_P + jj) =
                    __floats2bfloat162_rn(acc[mt][nt][0], acc[mt][nt][1]);
                *(__nv_bfloat162*)(stg + (row0 + 8) * STG_P + jj) =
                    __floats2bfloat162_rn(acc[mt][nt][2], acc[mt][nt][3]);
            }
        __syncthreads();

        {
            __nv_bfloat162* pa = g_A2 + (size_t)bh * WF * CH + c0;
            const __nv_bfloat16 z = __float2bfloat16_rn(0.0f);
            for (int idx = tid; idx < 65 * 96; idx += 256) {
                int k = idx / 96, c = idx - (idx / 96) * 96;
                __nv_bfloat16 re = stg[k * STG_P + c];
                __nv_bfloat16 im = (k >= 1 && k <= 63) ? stg[(64 + k) * STG_P + c] : z;
                pa[(size_t)k * CH + c] = __halves2bfloat162(re, im);
            }
        }
    }
}

// ---------------------------------------------------------------------------
// KMID: folded H-DFT -> MLP -> folded inverse H-DFT. 512 thr, 2 CTA/SM.
// G' and W1/W2 time-share one smem region: G'->GEMM1, W1->MLP1, W2->MLP2,
// G' reload->GEMM2.
// ---------------------------------------------------------------------------
#define GPP 136
#define PBX 104
#define XP  200
#define WP  104
#define SM_W   0          /* sWr 19968 + sWi 19968 = 39936 ; sG aliases (34816) */
#define SM_WI  19968
#define SM_X   39936      /* 256*104*2 = 53248 (planes / sXm / sOt / stg) */
#define SM_B1  93184
#define SM_B2  93952
#define SM_TOT 94720

__global__ void __launch_bounds__(512, 2) kmid(const float* __restrict__ b1,
                                               const float* __restrict__ b2)
{
    extern __shared__ char sm[];
    __nv_bfloat16* sG  = (__nv_bfloat16*)(sm + SM_W);   // aliases W region
    __nv_bfloat16* sWr = (__nv_bfloat16*)(sm + SM_W);
    __nv_bfloat16* sWi = (__nv_bfloat16*)(sm + SM_WI);
    __nv_bfloat16* sX  = (__nv_bfloat16*)(sm + SM_X);   // fold planes [256][104]
    __nv_bfloat16* sXm = (__nv_bfloat16*)(sm + SM_X);   // MLP A [128][200]
    __nv_bfloat16* sOt = (__nv_bfloat16*)(sm + SM_X);   // O natural [256][104]
    __nv_bfloat16* stg = (__nv_bfloat16*)(sm + SM_X);   // final Z stage [128][200]
    float* sB1 = (float*)(sm + SM_B1);
    float* sB2 = (float*)(sm + SM_B2);

    const int tid = threadIdx.x;
    const int n   = blockIdx.x;
    const int b   = blockIdx.y / WF;
    const int wf  = blockIdx.y - b * WF;
    const int lane = tid & 31, warp = tid >> 5;
    const int g = lane >> 2, tig = lane & 3;
    const int wm = warp & 3, wq = warp >> 2;
    const int wn = wq >> 1, wh = wq & 1;

    {   // G' copy (16B vectors)
        const uint4* src = (const uint4*)g_Gp;
        uint4* dst = (uint4*)sG;
        for (int p = tid; p < 128 * 136 * 2 / 16; p += 512) dst[p] = src[p];
        if (tid < 192) {
            int half = tid / 96, j = tid - half * 96;
            sB1[tid] = b1[half * (NB * BS) + n * BS + j];
            sB2[tid] = b2[half * (NB * BS) + n * BS + j];
        }
    }
    {   // ingest + forward fold
        const __nv_bfloat162* pa = g_A2 + ((size_t)(b * HH) * WF + wf) * CH + n * BS;
        for (int idx = tid; idx < 65 * 48; idx += 512) {
            int h = idx / 48, c = (idx - (idx / 48) * 48) * 2;
            uint2 ua = *(const uint2*)(pa + (size_t)h * WF * CH + c);
            float2 a0 = __bfloat1622float2(*(__nv_bfloat162*)&ua.x);
            float2 a1 = __bfloat1622float2(*(__nv_bfloat162*)&ua.y);
            if (h == 0 || h == 64) {
                *(__nv_bfloat162*)(sX + h * PBX + c)         = __floats2bfloat162_rn(a0.x, a1.x);
                *(__nv_bfloat162*)(sX + (128 + h) * PBX + c) = __floats2bfloat162_rn(a0.y, a1.y);
            } else {
                uint2 ub = *(const uint2*)(pa + (size_t)(128 - h) * WF * CH + c);
                float2 b0 = __bfloat1622float2(*(__nv_bfloat162*)&ub.x);
                float2 b1v = __bfloat1622float2(*(__nv_bfloat162*)&ub.y);
                *(__nv_bfloat162*)(sX + h * PBX + c) =
                    __floats2bfloat162_rn(a0.x + b0.x, a1.x + b1v.x);          // Per
                *(__nv_bfloat162*)(sX + (64 + h) * PBX + c) =
                    __floats2bfloat162_rn(a0.y - b0.y, a1.y - b1v.y);          // Mi
                *(__nv_bfloat162*)(sX + (128 + h) * PBX + c) =
                    __floats2bfloat162_rn(a0.y + b0.y, a1.y + b1v.y);          // Pei
                *(__nv_bfloat162*)(sX + (192 + h) * PBX + c) =
                    __floats2bfloat162_rn(b0.x - a0.x, b1v.x - a1.x);          // -Mr
            }
        }
    }
    __syncthreads();

    const unsigned sG_u = s2u(sG), sX_u = s2u(sX);
    const unsigned sWr_u = s2u(sWr), sWi_u = s2u(sWi);
    const unsigned abaseG = sG_u + (wm * 32) * GPP * 2 + AOFF(lane, GPP);
    const unsigned abaseX = sX_u + (wm * 32) * XP * 2 + AOFF(lane, XP);
    const unsigned bplane = sX_u + (wn * 128 * PBX + wh * 48) * 2 + BTOFF(lane, PBX);
    const unsigned boffW  = (wh * 48) * WP * 2 + BOFF(lane, WP);

    float acc[2][6][4];

    // =============== GEMM1: folded forward H-DFT (K=128) ==================
    #pragma unroll
    for (int mt = 0; mt < 2; mt++)
        #pragma unroll
        for (int nt = 0; nt < 6; nt++)
            #pragma unroll
            for (int r = 0; r < 4; r++) acc[mt][nt][r] = 0.0f;

    #pragma unroll
    for (int ks = 0; ks < 8; ks++) {
        const int k0 = ks * 16;
        unsigned a[2][4];
        ldsm_x4(a[0], abaseG + k0 * 2);
        ldsm_x4(a[1], abaseG + (16 * GPP + k0) * 2);
        #pragma unroll
        for (int nt = 0; nt < 6; nt++) {
            unsigned bb[2];
            ldsm_x2t(bb, bplane + (k0 * PBX + nt * 8) * 2);
            mma_bf16(acc[0][nt], a[0], bb[0], bb[1]);
            mma_bf16(acc[1][nt], a[1], bb[0], bb[1]);
        }
    }
    __syncthreads();   // G' + plane reads done

    // epilogue -> sXm ; W1 copy over G'
    #pragma unroll
    for (int mt = 0; mt < 2; mt++)
        #pragma unroll
        for (int nt = 0; nt < 6; nt++) {
            int row0 = wm * 32 + mt * 16 + g;
            int jj = wq * 48 + nt * 8 + 2 * tig;
            *(__nv_bfloat162*)(sXm + row0 * XP + jj) =
                __floats2bfloat162_rn(acc[mt][nt][0], acc[mt][nt][1]);
            *(__nv_bfloat162*)(sXm + (row0 + 8) * XP + jj) =
                __floats2bfloat162_rn(acc[mt][nt][2], acc[mt][nt][3]);
        }
    {
        const uint4* srcR = (const uint4*)&g_Wb[0][0][n][0];
        const uint4* srcI = (const uint4*)&g_Wb[0][1][n][0];
        uint4* dR = (uint4*)sWr;
        uint4* dI = (uint4*)sWi;
        for (int p = tid; p < 96 * 104 / 8; p += 512) { dR[p] = srcR[p]; dI[p] = srcI[p]; }
    }
    __syncthreads();

    // =============== MLP layer 1 ==========================================
    #pragma unroll
    for (int mt = 0; mt < 2; mt++)
        #pragma unroll
        for (int nt = 0; nt < 6; nt++)
            #pragma unroll
            for (int r = 0; r < 4; r++) acc[mt][nt][r] = 0.0f;

    #pragma unroll
    for (int ks = 0; ks < 12; ks++) {
        const int khalf = (ks >= 6);
        const int k0 = ks * 16, kkm = k0 - khalf * 96;
        const unsigned sW_u = (wn == 0) ? (khalf ? sWi_u : sWr_u)
                                        : (khalf ? sWr_u : sWi_u);
        const unsigned amsk = ((wn == 0) && khalf) ? 0x80008000u : 0u;
        unsigned a[2][4];
        ldsm_x4(a[0], abaseX + k0 * 2);
        ldsm_x4(a[1], abaseX + (16 * XP + k0) * 2);
        if (amsk) {
            #pragma unroll
            for (int mt = 0; mt < 2; mt++)
                #pragma unroll
                for (int r = 0; r < 4; r++) a[mt][r] ^= amsk;
        }
        #pragma unroll
        for (int nt = 0; nt < 6; nt++) {
            unsigned bb[2];
            ldsm_x2(bb, sW_u + boffW + (nt * 8 * WP + kkm) * 2);
            mma_bf16(acc[0][nt], a[0], bb[0], bb[1]);
            mma_bf16(acc[1][nt], a[1], bb[0], bb[1]);
        }
    }
    __syncthreads();

    #pragma unroll
    for (int mt = 0; mt < 2; mt++)
        #pragma unroll
        for (int nt = 0; nt < 6; nt++) {
            int row0 = wm * 32 + mt * 16 + g;
            int jj = wq * 48 + nt * 8 + 2 * tig;
            float bb0 = sB1[jj], bb1 = sB1[jj + 1];
            *(__nv_bfloat162*)(sXm + row0 * XP + jj) = __floats2bfloat162_rn(
                fmaxf(acc[mt][nt][0] + bb0, 0.0f), fmaxf(acc[mt][nt][1] + bb1, 0.0f));
            *(__nv_bfloat162*)(sXm + (row0 + 8) * XP + jj) = __floats2bfloat162_rn(
                fmaxf(acc[mt][nt][2] + bb0, 0.0f), fmaxf(acc[mt][nt][3] + bb1, 0.0f));
        }
    {   // W2 copy
        const uint4* srcR = (const uint4*)&g_Wb[1][0][n][0];
        const uint4* srcI = (const uint4*)&g_Wb[1][1][n][0];
        uint4* dR = (uint4*)sWr;
        uint4* dI = (uint4*)sWi;
        for (int p = tid; p < 96 * 104 / 8; p += 512) { dR[p] = srcR[p]; dI[p] = srcI[p]; }
    }
    __syncthreads();

    // =============== MLP layer 2 ==========================================
    #pragma unroll
    for (int mt = 0; mt < 2; mt++)
        #pragma unroll
        for (int nt = 0; nt < 6; nt++)
            #pragma unroll
            for (int r = 0; r < 4; r++) acc[mt][nt][r] = 0.0f;

    #pragma unroll
    for (int ks = 0; ks < 12; ks++) {
        const int khalf = (ks >= 6);
        const int k0 = ks * 16, kkm = k0 - khalf * 96;
        const unsigned sW_u = (wn == 0) ? (khalf ? sWi_u : sWr_u)
                                        : (khalf ? sWr_u : sWi_u);
        const unsigned amsk = ((wn == 0) && khalf) ? 0x80008000u : 0u;
        unsigned a[2][4];
        ldsm_x4(a[0], abaseX + k0 * 2);
        ldsm_x4(a[1], abaseX + (16 * XP + k0) * 2);
        if (amsk) {
            #pragma unroll
            for (int mt = 0; mt < 2; mt++)
                #pragma unroll
                for (int r = 0; r < 4; r++) a[mt][r] ^= amsk;
        }
        #pragma unroll
        for (int nt = 0; nt < 6; nt++) {
            unsigned bb[2];
            ldsm_x2(bb, sW_u + boffW + (nt * 8 * WP + kkm) * 2);
            mma_bf16(acc[0][nt], a[0], bb[0], bb[1]);
            mma_bf16(acc[1][nt], a[1], bb[0], bb[1]);
        }
    }
    __syncthreads();

    // softshrink -> sOt natural [k-stack 256][c] ; G' reload over W
    {
        const float lam = 0.01f;
        #pragma unroll
        for (int mt = 0; mt < 2; mt++)
            #pragma unroll
            for (int nt = 0; nt < 6; nt++) {
                int row0 = wm * 32 + mt * 16 + g;
                int c = wh * 48 + nt * 8 + 2 * tig;
                int jj = wn * 96 + c;
                float bb0 = sB2[jj], bb1 = sB2[jj + 1];
                #pragma unroll
                for (int r = 0; r < 4; r++) {
                    float v = acc[mt][nt][r] + ((r & 1) ? bb1 : bb0);
                    v = copysignf(fmaxf(fabsf(v) - lam, 0.0f), v);
                    int cc = c + (r & 1);
                    int kb = wn * 128 + row0 + (r >> 1) * 8;
                    sOt[kb * PBX + cc] = __float2bfloat16_rn(v);
                }
            }
    }
    {
        const uint4* src = (const uint4*)g_Gp;
        uint4* dst = (uint4*)sG;
        for (int p = tid; p < 128 * 136 * 2 / 16; p += 512) dst[p] = src[p];
    }
    __syncthreads();

    // =============== in-place inverse fold (two-phase) ====================
    {
        unsigned rA[6], rB[6], rC[6], rD[6];
        int ns = 0;
        for (int idx = tid; idx < 63 * 48; idx += 512) {
            int m = idx / 48 + 1, c = (idx - (idx / 48) * 48) * 2;
            rA[ns] = *(unsigned*)(sOt + m * PBX + c);
            rB[ns] = *(unsigned*)(sOt + (128 - m) * PBX + c);
            rC[ns] = *(unsigned*)(sOt + (128 + m) * PBX + c);
            rD[ns] = *(unsigned*)(sOt + (256 - m) * PBX + c);
            ns++;
        }
        __syncthreads();
        ns = 0;
        for (int idx = tid; idx < 63 * 48; idx += 512) {
            int m = idx / 48 + 1, c = (idx - (idx / 48) * 48) * 2;
            float2 fa = __bfloat1622float2(*(__nv_bfloat162*)&rA[ns]);
            float2 fb = __bfloat1622float2(*(__nv_bfloat162*)&rB[ns]);
            float2 fc = __bfloat1622float2(*(__nv_bfloat162*)&rC[ns]);
            float2 fd = __bfloat1622float2(*(__nv_bfloat162*)&rD[ns]);
            *(__nv_bfloat162*)(sOt + m * PBX + c) =
                __floats2bfloat162_rn(fa.x + fb.x, fa.y + fb.y);       // POr
            *(__nv_bfloat162*)(sOt + (64 + m) * PBX + c) =
                __floats2bfloat162_rn(fd.x - fc.x, fd.y - fc.y);       // -MOi
            *(__nv_bfloat162*)(sOt + (128 + m) * PBX + c) =
                __floats2bfloat162_rn(fc.x + fd.x, fc.y + fd.y);       // POi
            *(__nv_bfloat162*)(sOt + (192 + m) * PBX + c) =
                __floats2bfloat162_rn(fa.x - fb.x, fa.y - fb.y);       // MOr
            ns++;
        }
    }
    __syncthreads();

    // =============== GEMM2: folded inverse H-DFT (K=128) ==================
    #pragma unroll
    for (int mt = 0; mt < 2; mt++)
        #pragma unroll
        for (int nt = 0; nt < 6; nt++)
            #pragma unroll
            for (int r = 0; r < 4; r++) acc[mt][nt][r] = 0.0f;

    #pragma unroll
    for (int ks = 0; ks < 8; ks++) {
        const int k0 = ks * 16;
        unsigned a[2][4];
        ldsm_x4(a[0], abaseG + k0 * 2);
        ldsm_x4(a[1], abaseG + (16 * GPP + k0) * 2);
        #pragma unroll
        for (int nt = 0; nt < 6; nt++) {
            unsigned bb[2];
            ldsm_x2t(bb, bplane + (k0 * PBX + nt * 8) * 2);
            mma_bf16(acc[0][nt], a[0], bb[0], bb[1]);
            mma_bf16(acc[1][nt], a[1], bb[0], bb[1]);
        }
    }
    __syncthreads();

    #pragma unroll
    for (int mt = 0; mt < 2; mt++)
        #pragma unroll
        for (int nt = 0; nt < 6; nt++) {
            int row0 = wm * 32 + mt * 16 + g;
            int jj = wq * 48 + nt * 8 + 2 * tig;
            *(__nv_bfloat162*)(stg + row0 * XP + jj) =
                __floats2bfloat162_rn(acc[mt][nt][0], acc[mt][nt][1]);
            *(__nv_bfloat162*)(stg + (row0 + 8) * XP + jj) =
                __floats2bfloat162_rn(acc[mt][nt][2], acc[mt][nt][3]);
        }
    __syncthreads();

    {
        __nv_bfloat162* pb = g_B2 + ((size_t)(b * HH) * WF + wf) * CH + n * BS;
        for (int idx = tid; idx < HH * BS; idx += 512) {
            int h = idx / BS, c = idx - (idx / BS) * BS;
            pb[(size_t)h * WF * CH + c] =
                __halves2bfloat162(stg[h * XP + c], stg[h * XP + 96 + c]);
        }
    }
}

// ---------------------------------------------------------------------------
// K5: W-irfft as GEMM + residual. 2 bh rows per CTA.
// ---------------------------------------------------------------------------
#define P5 152
#define PB5 104
#define K5_SG 0
#define K5_SB 38912
#define K5_TOT 68864

__global__ void __launch_bounds__(256) k5g(const float* __restrict__ x,
                                           float* __restrict__ out)
{
    extern __shared__ char sm[];
    __nv_bfloat16* sG = (__nv_bfloat16*)(sm + K5_SG);
    __nv_bfloat16* sB = (__nv_bfloat16*)(sm + K5_SB);

    const int tid = threadIdx.x;
    const int c0 = blockIdx.x * 96;
    const int lane = tid & 31, warp = tid >> 5;
    const int g = lane >> 2, tig = lane & 3;
    const int wm = warp & 3, wn = warp >> 2;

    {
        const unsigned* src = (const unsigned*)g_G5;
        unsigned* dst = (unsigned*)sG;
        for (int p = tid; p < 128 * 73; p += 256) {
            int row = p / 73, c = p - row * 73;
            dst[row * 76 + c] = src[p];
        }
    }
    {
        unsigned* dz = (unsigned*)sB;
        for (int p = tid; p < 144 * 52; p += 256) dz[p] = 0u;
    }

    const unsigned sG_u = s2u(sG), sB_u = s2u(sB);
    const unsigned abase  = sG_u + (wm * 32) * P5 * 2 + AOFF(lane, P5);
    const unsigned btbase = sB_u + BTOFF(lane, PB5) + (wn * 48) * 2;

    for (int t = 0; t < 2; t++) {
        const int bh = blockIdx.y * 2 + t;
        __syncthreads();

        {
            const __nv_bfloat162* pb = g_B2 + (size_t)bh * WF * CH + c0;
            for (int idx = tid; idx < 65 * 48; idx += 256) {
                int k = idx / 48, c = (idx - (idx / 48) * 48) * 2;
                uint2 v2 = *(const uint2*)(pb + (size_t)k * CH + c);
                __nv_bfloat162 va = *(__nv_bfloat162*)&v2.x;
                __nv_bfloat162 vb = *(__nv_bfloat162*)&v2.y;
                *(__nv_bfloat162*)(sB + k * PB5 + c) =
                    __halves2bfloat162(__low2bfloat16(va), __low2bfloat16(vb));
                *(__nv_bfloat162*)(sB + (72 + k) * PB5 + c) =
                    __halves2bfloat162(__high2bfloat16(va), __high2bfloat16(vb));
            }
        }
        __syncthreads();

        float acc[2][6][4];
        #pragma unroll
        for (int mt = 0; mt < 2; mt++)
            #pragma unroll
            for (int nt = 0; nt < 6; nt++)
                #pragma unroll
                for (int r = 0; r < 4; r++) acc[mt][nt][r] = 0.0f;

        #pragma unroll
        for (int ks = 0; ks < 9; ks++) {
            const int k0 = ks * 16;
            unsigned a[2][4];
            ldsm_x4(a[0], abase + k0 * 2);
            ldsm_x4(a[1], abase + (16 * P5 + k0) * 2);
            #pragma unroll
            for (int nt = 0; nt < 6; nt++) {
                unsigned bb[2];
                ldsm_x2t(bb, btbase + (k0 * PB5 + nt * 8) * 2);
                mma_bf16(acc[0][nt], a[0], bb[0], bb[1]);
                mma_bf16(acc[1][nt], a[1], bb[0], bb[1]);
            }
        }

        {
            const float* px = x   + (size_t)bh * WW * CH + c0;
            float*       po = out + (size_t)bh * WW * CH + c0;
            #pragma unroll
            for (int mt = 0; mt < 2; mt++)
                #pragma unroll
                for (int nt = 0; nt < 6; nt++) {
                    int row0 = wm * 32 + mt * 16 + g;
                    int jj = wn * 48 + nt * 8 + 2 * tig;
                    float2 xv0 = *(const float2*)(px + (size_t)row0 * CH + jj);
                    float2 xv1 = *(const float2*)(px + (size_t)(row0 + 8) * CH + jj);
                    *(float2*)(po + (size_t)row0 * CH + jj) =
                        make_float2(acc[mt][nt][0] + xv0.x, acc[mt][nt][1] + xv0.y);
                    *(float2*)(po + (size_t)(row0 + 8) * CH + jj) =
                        make_float2(acc[mt][nt][2] + xv1.x, acc[mt][nt][3] + xv1.y);
                }
        }
    }
}

// ---------------------------------------------------------------------------
extern "C" void kernel_launch(void* const* d_in, const int* in_sizes, int n_in,
                              void* d_out, int out_size)
{
    (void)in_sizes; (void)n_in; (void)out_size;
    const float* x  = (const float*)d_in[0];
    const float* w1 = (const float*)d_in[1];
    const float* b1 = (const float*)d_in[2];
    const float* w2 = (const float*)d_in[3];
    const float* b2 = (const float*)d_in[4];
    float* out = (float*)d_out;

    cudaFuncSetAttribute(k1g,  cudaFuncAttributeMaxDynamicSharedMemorySize, K1_TOT);
    cudaFuncSetAttribute(kmid, cudaFuncAttributeMaxDynamicSharedMemorySize, SM_TOT);
    cudaFuncSetAttribute(k5g,  cudaFuncAttributeMaxDynamicSharedMemorySize, K5_TOT);

    k0_build<<<32, 256>>>(w1, w2);
    k1g <<<dim3(CH / 96, BB * HH / 2), 256, K1_TOT>>>(x);
    kmid<<<dim3(NB, BB * WF), 512, SM_TOT>>>(b1, b2);
    k5g <<<dim3(CH / 96, BB * HH / 2), 256, K5_TOT>>>(x, out);
}